// round 10
// baseline (speedup 1.0000x reference)
#include <cuda_runtime.h>
#include <cuda_bf16.h>
#include <cuda_fp16.h>
#include <cstdint>
#include <math.h>

#define NB   8
#define HSP  37
#define WSP  37
#define NPIX 1369
#define BN   10952
#define CC   1024
#define HEADS 8
#define HD   128
#define PTS  8
#define MBLK 86
#define MPAIRS 43           // MBLK / 2
#define MPAD (MBLK * 128)   // 11008
#define NCH  16             // K chunks of 64
#define TILE_BYTES 16384    // 128 rows x 128B
#define LO_SCALE 1024.0f
#define LO_INV   0.0009765625f

#if defined(__CUDA_ARCH__) && (defined(__CUDA_ARCH_FEAT_SM103_ALL) || defined(__CUDA_ARCH_FEAT_SM100_ALL) || defined(__CUDA_ARCH_SPECIFIC__))
#define HAS_TCGEN05 1
#else
#define HAS_TCGEN05 0
#endif

#define SMEM_SWIZZLE_128B(byte_offset) ((byte_offset) ^ (((byte_offset) >> 3) & 0x70))

// ============================ Scratch ============================
__device__ float g_q[BN * CC];
__device__ float g_k[BN * CC];          // fallback path only
__device__ __half g_kh[BN * CC];        // tc path: k in fp16 for the gather
__device__ float g_off[BN * HEADS * PTS * 2];
__device__ float g_attn[BN * CC];

// Blocked+swizzled fp16 operands (16KB tiles, tile (r,c) at ((r*NCH)+c)*16KB)
__device__ __half g_qh[MPAD * CC];
__device__ __half g_ql[MPAD * CC];
__device__ __half g_rh[MPAD * CC];
__device__ __half g_rl[MPAD * CC];
__device__ __half g_ah[MPAD * CC];
__device__ __half g_al[MPAD * CC];
__device__ __half g_Wq[CC * CC];
__device__ __half g_Wk[CC * CC];
__device__ __half g_Wo[CC * CC];
__device__ __half g_Wf_h[128 * CC];
__device__ __half g_Wf_l[128 * CC];

// ============================ tcgen05 helpers (guarded) ============================
#if HAS_TCGEN05
__device__ __forceinline__ uint32_t smem_to_u32(const void* p) {
    uint32_t a;
    asm("{ .reg .u64 t; cvta.to.shared.u64 t, %1; cvt.u32.u64 %0, t; }" : "=r"(a) : "l"(p));
    return a;
}
#define TCGEN05_ALLOC(smem_result_addr, nCols) \
    asm volatile("tcgen05.alloc.cta_group::1.sync.aligned.shared::cta.b32 [%0], %1;" \
        :: "r"((uint32_t)(smem_result_addr)), "r"((uint32_t)(nCols)) : "memory")
#define TCGEN05_DEALLOC(tmem_addr, nCols) \
    asm volatile("tcgen05.dealloc.cta_group::1.sync.aligned.b32 %0, %1;" :: "r"(tmem_addr), "r"(nCols))
#define TCGEN05_RELINQUISH_ALLOC_PERMIT() \
    asm volatile("tcgen05.relinquish_alloc_permit.cta_group::1.sync.aligned;")
#define TCGEN05_ALLOC_CG2(smem_result_addr, nCols) \
    asm volatile("tcgen05.alloc.cta_group::2.sync.aligned.shared::cta.b32 [%0], %1;" \
        :: "r"((uint32_t)(smem_result_addr)), "r"((uint32_t)(nCols)) : "memory")
#define TCGEN05_DEALLOC_CG2(tmem_addr, nCols) \
    asm volatile("tcgen05.dealloc.cta_group::2.sync.aligned.b32 %0, %1;" :: "r"(tmem_addr), "r"(nCols))
#define TCGEN05_RELINQUISH_ALLOC_PERMIT_CG2() \
    asm volatile("tcgen05.relinquish_alloc_permit.cta_group::2.sync.aligned;")
#define TCGEN05_COMMIT_MC(mbar_smem_addr, mask) \
    asm volatile("tcgen05.commit.cta_group::1.mbarrier::arrive::one.shared::cluster.multicast::cluster.b64 [%0], %1;" \
        :: "r"((uint32_t)(mbar_smem_addr)), "h"((uint16_t)(mask)) : "memory")
#define TCGEN05_COMMIT_MC_CG2(mbar_smem_addr, mask) \
    asm volatile("tcgen05.commit.cta_group::2.mbarrier::arrive::one.shared::cluster.multicast::cluster.b64 [%0], %1;" \
        :: "r"((uint32_t)(mbar_smem_addr)), "h"((uint16_t)(mask)) : "memory")
#define TCGEN05_WAIT_LD() asm volatile("tcgen05.wait::ld.sync.aligned;" ::: "memory")
#define TCGEN05_FENCE_AFTER() asm volatile("tcgen05.fence::after_thread_sync;" ::: "memory")
#define TCGEN05_FENCE_BEFORE() asm volatile("tcgen05.fence::before_thread_sync;" ::: "memory")
#define MBARRIER_INIT(mbar_smem_addr, count) \
    asm volatile("mbarrier.init.shared.b64 [%0], %1;" \
        :: "r"((uint32_t)(mbar_smem_addr)), "r"((uint32_t)(count)) : "memory")
#define MBARRIER_EXPECT_TX(mbar_smem_addr, tx_bytes) \
    asm volatile("mbarrier.arrive.expect_tx.shared.b64 _, [%0], %1;" \
        :: "r"((uint32_t)(mbar_smem_addr)), "r"((uint32_t)(tx_bytes)) : "memory")
#define MBARRIER_ARRIVE_CLUSTER(local_mbar_addr, target_rank) \
    asm volatile("{\n\t.reg .b32 remAddr32;\n\t" \
        "mapa.shared::cluster.u32 remAddr32, %0, %1;\n\t" \
        "mbarrier.arrive.release.cluster.shared::cluster.b64 _, [remAddr32];\n\t}" \
        :: "r"((uint32_t)(local_mbar_addr)), "r"((uint32_t)(target_rank)) : "memory")
#define MBARRIER_WAIT_PARITY(mbar_smem_addr, phase_parity) do { \
    uint32_t _mbar = (uint32_t)(mbar_smem_addr); \
    uint32_t _parity = (uint32_t)(phase_parity); \
    uint32_t _done; \
    asm volatile("{\n\t.reg .pred p;\n\t" \
        "mbarrier.try_wait.parity.acquire.cta.shared::cta.b64 p, [%1], %2;\n\t" \
        "selp.b32 %0, 1, 0, p;\n\t}" : "=r"(_done) : "r"(_mbar), "r"(_parity) : "memory"); \
    if (!_done) { \
        asm volatile("{\n\t.reg .pred P1;\n\t" \
            "WAIT_LOOP_%=:\n\t" \
            "mbarrier.try_wait.parity.acquire.cta.shared::cta.b64 P1, [%0], %1, 0x989680;\n\t" \
            "@P1 bra.uni WAIT_DONE_%=;\n\t" \
            "bra.uni WAIT_LOOP_%=;\n\t" \
            "WAIT_DONE_%=:\n\t}" :: "r"(_mbar), "r"(_parity) : "memory"); \
    } \
} while(0)
#define MBARRIER_WAIT_PARITY_CLUSTER(mbar_smem_addr, phase_parity) do { \
    uint32_t _mbar = (uint32_t)(mbar_smem_addr); \
    uint32_t _parity = (uint32_t)(phase_parity); \
    uint32_t _done; \
    asm volatile("{\n\t.reg .pred p;\n\t" \
        "mbarrier.try_wait.parity.acquire.cluster.shared::cta.b64 p, [%1], %2;\n\t" \
        "selp.b32 %0, 1, 0, p;\n\t}" : "=r"(_done) : "r"(_mbar), "r"(_parity) : "memory"); \
    if (!_done) { \
        asm volatile("{\n\t.reg .pred P1;\n\t" \
            "WAIT_LOOP_%=:\n\t" \
            "mbarrier.try_wait.parity.acquire.cluster.shared::cta.b64 P1, [%0], %1, 0x989680;\n\t" \
            "@P1 bra.uni WAIT_DONE_%=;\n\t" \
            "bra.uni WAIT_LOOP_%=;\n\t" \
            "WAIT_DONE_%=:\n\t}" :: "r"(_mbar), "r"(_parity) : "memory"); \
    } \
} while(0)
#define CLUSTER_SYNC() do { \
    asm volatile("barrier.cluster.arrive.aligned;" ::: "memory"); \
    asm volatile("barrier.cluster.wait.aligned;" ::: "memory"); \
} while(0)
#define TCGEN05_LD_32X32B_X32(r, tmem_addr) \
    asm volatile("tcgen05.ld.sync.aligned.32x32b.x32.b32 " \
        "{%0, %1, %2, %3, %4, %5, %6, %7, %8, %9, %10, %11, %12, %13, %14, %15, " \
        " %16, %17, %18, %19, %20, %21, %22, %23, %24, %25, %26, %27, %28, %29, %30, %31}, [%32];" \
        : "=r"((r)[0]),  "=r"((r)[1]),  "=r"((r)[2]),  "=r"((r)[3]), \
          "=r"((r)[4]),  "=r"((r)[5]),  "=r"((r)[6]),  "=r"((r)[7]), \
          "=r"((r)[8]),  "=r"((r)[9]),  "=r"((r)[10]), "=r"((r)[11]), \
          "=r"((r)[12]), "=r"((r)[13]), "=r"((r)[14]), "=r"((r)[15]), \
          "=r"((r)[16]), "=r"((r)[17]), "=r"((r)[18]), "=r"((r)[19]), \
          "=r"((r)[20]), "=r"((r)[21]), "=r"((r)[22]), "=r"((r)[23]), \
          "=r"((r)[24]), "=r"((r)[25]), "=r"((r)[26]), "=r"((r)[27]), \
          "=r"((r)[28]), "=r"((r)[29]), "=r"((r)[30]), "=r"((r)[31]) \
        : "r"(tmem_addr))

static constexpr uint64_t SMEM_DESC_BASE_SW128 =
    (uint64_t(2)  << 61) | (uint64_t(1) << 46) | (uint64_t(64) << 32) | (uint64_t(1) << 16);
#define MAKE_SMEM_DESC(base_addr) (SMEM_DESC_BASE_SW128 | ((uint64_t)((base_addr) >> 4) & 0x3FFF))

__device__ __forceinline__ void mma_f16_ss(uint32_t d, uint64_t ad, uint64_t bd,
                                           uint32_t idesc, bool en) {
    uint32_t e = en ? 1u : 0u;
    asm volatile(
        "{\n\t.reg .pred p;\n\tsetp.ne.u32 p, %5, 0;\n\t"
        "tcgen05.mma.cta_group::1.kind::f16 [%0], %1, %2, %3, {%4, %4, %4, %4}, p;\n\t}"
        :: "r"(d), "l"(ad), "l"(bd), "r"(idesc), "r"(0u), "r"(e) : "memory");
}
__device__ __forceinline__ void mma_f16_ss_cg2(uint32_t d, uint64_t ad, uint64_t bd,
                                               uint32_t idesc, bool en) {
    uint32_t e = en ? 1u : 0u;
    asm volatile(
        "{\n\t.reg .pred p;\n\tsetp.ne.u32 p, %5, 0;\n\t"
        "tcgen05.mma.cta_group::2.kind::f16 [%0], %1, %2, %3, "
        "{%4, %4, %4, %4, %4, %4, %4, %4}, p;\n\t}"
        :: "r"(d), "l"(ad), "l"(bd), "r"(idesc), "r"(0u), "r"(e) : "memory");
}
__device__ __forceinline__ void bulk_g2s(uint32_t dst, const void* src, uint32_t bytes, uint32_t mbar) {
    asm volatile("cp.async.bulk.shared::cluster.global.mbarrier::complete_tx::bytes [%0], [%1], %2, [%3];"
        :: "r"(dst), "l"(src), "r"(bytes), "r"(mbar) : "memory");
}
__device__ __forceinline__ void bulk_g2s_mc(uint32_t dst, const void* src, uint32_t bytes,
                                            uint32_t mbar, uint16_t mask) {
    asm volatile("cp.async.bulk.shared::cluster.global.mbarrier::complete_tx::bytes.multicast::cluster [%0], [%1], %2, [%3], %4;"
        :: "r"(dst), "l"(src), "r"(bytes), "r"(mbar), "h"(mask) : "memory");
}
__device__ __forceinline__ uint32_t cluster_rank() {
    uint32_t r;
    asm("mov.u32 %0, %%cluster_ctarank;" : "=r"(r));
    return r;
}
#endif  // HAS_TCGEN05

// ============================ Pack kernels ============================
__global__ void split_act2_kernel(const float* __restrict__ src0,
                                  __half* __restrict__ hi0, __half* __restrict__ lo0,
                                  const float* __restrict__ src1,
                                  __half* __restrict__ hi1, __half* __restrict__ lo1, int M)
{
    const float* src = blockIdx.z ? src1 : src0;
    __half* hi = blockIdx.z ? hi1 : hi0;
    __half* lo = blockIdx.z ? lo1 : lo0;
    const int c  = blockIdx.x;
    const int mb = blockIdx.y;
    const int t  = threadIdx.x;
    const int j  = t & 7;
    char* hbase = (char*)hi + ((size_t)(mb * NCH + c)) * TILE_BYTES;
    char* lbase = (char*)lo + ((size_t)(mb * NCH + c)) * TILE_BYTES;

    #pragma unroll
    for (int g = 0; g < 8; g++) {
        int ml = g * 16 + (t >> 3);
        int m = mb * 128 + ml;
        float x[8];
        if (m < M) {
            float4 a = *(const float4*)(src + (size_t)m * CC + c * 64 + j * 8);
            float4 b = *(const float4*)(src + (size_t)m * CC + c * 64 + j * 8 + 4);
            x[0]=a.x; x[1]=a.y; x[2]=a.z; x[3]=a.w; x[4]=b.x; x[5]=b.y; x[6]=b.z; x[7]=b.w;
        } else {
            #pragma unroll
            for (int i = 0; i < 8; i++) x[i] = 0.0f;
        }
        __half h[8], l[8];
        #pragma unroll
        for (int i = 0; i < 8; i++) {
            h[i] = __float2half(x[i]);
            l[i] = __float2half((x[i] - __half2float(h[i])) * LO_SCALE);
        }
        uint32_t off = SMEM_SWIZZLE_128B((uint32_t)(ml * 128 + j * 16));
        *(uint4*)(hbase + off) = *(uint4*)h;
        *(uint4*)(lbase + off) = *(uint4*)l;
    }
}

__global__ void __launch_bounds__(512)
pack_weights_all(const float* __restrict__ Wq, const float* __restrict__ Wkv,
                 const float* __restrict__ Woff, const float* __restrict__ Wout,
                 __half* __restrict__ wq, __half* __restrict__ wk,
                 __half* __restrict__ wfh, __half* __restrict__ wfl,
                 __half* __restrict__ wo)
{
    __shared__ float ts[64][129];
    const int c = blockIdx.x;
    const int y = blockIdx.y;
    const int t = threadIdx.x;

    const float* W; int ldw, nb; __half *hi, *lo;
    if (y < 8)       { W = Wq;   ldw = CC;     nb = y;      hi = wq;  lo = nullptr; }
    else if (y < 16) { W = Wkv;  ldw = 2 * CC; nb = y - 8;  hi = wk;  lo = nullptr; }
    else if (y < 17) { W = Woff; ldw = 128;    nb = 0;      hi = wfh; lo = wfl; }
    else             { W = Wout; ldw = CC;     nb = y - 17; hi = wo;  lo = nullptr; }

    const int k0 = c * 64;
    const int n0 = nb * 128;
    const int lrow = t >> 7;
    const int lcol = t & 127;
    #pragma unroll
    for (int i = 0; i < 16; i++) {
        int row = i * 4 + lrow;
        ts[row][lcol] = W[(size_t)(k0 + row) * ldw + n0 + lcol];
    }
    __syncthreads();

    char* hbase = (char*)hi + ((size_t)(nb * NCH + c)) * TILE_BYTES;
    char* lbase = lo ? (char*)lo + ((size_t)(nb * NCH + c)) * TILE_BYTES : nullptr;
    #pragma unroll
    for (int it = 0; it < 2; it++) {
        int idx = t + it * 512;
        int nl = idx >> 3;
        int j  = idx & 7;
        __half h[8], l[8];
        #pragma unroll
        for (int jj = 0; jj < 8; jj++) {
            float x = ts[j * 8 + jj][nl];
            h[jj] = __float2half(x);
            l[jj] = __float2half((x - __half2float(h[jj])) * LO_SCALE);
        }
        uint32_t off = SMEM_SWIZZLE_128B((uint32_t)(nl * 128 + j * 16));
        *(uint4*)(hbase + off) = *(uint4*)h;
        if (lbase) *(uint4*)(lbase + off) = *(uint4*)l;
    }
}

// ====== cg2 GEMM: M=256 per cluster pair (paired along cluster x), N=256 ======
// Cluster (2,1,1): grid (2, 4*MPAIRS). blockIdx.y = ntile*MPAIRS + pair.
// m0 = (pair*2 + rank)*128, n0 = ntile*256. Each rank loads its A rows + its
// N/2 B-half (tile row ntile*2+rank). rank0 issues cg2 MMAs reading both SMEMs.
template <typename TOut>
__global__ void __launch_bounds__(128, 1) __cluster_dims__(2, 1, 1)
gemm_cg2(const char* __restrict__ Ah, const char* __restrict__ Al,
         const char* __restrict__ B,
         const float* __restrict__ bias, TOut* __restrict__ C, int M, int Ncols)
{
#if HAS_TCGEN05
    constexpr int NT = 256;
    constexpr uint32_t SB = 3 * TILE_BYTES;
    constexpr uint32_t HDR = 1024;
    constexpr uint32_t IDESC = 0x10400010u;  // M=256 (16<<24), N=256 (32<<17), f32 acc, f16xf16

    extern __shared__ char smem[];
    uint32_t sb = smem_to_u32(smem);
    const int tid = threadIdx.x;
    const int wid = tid >> 5;
    const int lane = tid & 31;
    const uint32_t rank = cluster_rank();
    const int pair  = blockIdx.y % MPAIRS;
    const int ntile = blockIdx.y / MPAIRS;
    const int mrow = pair * 2 + (int)rank;    // this CTA's 128-row block index
    const int m0 = mrow * 128;
    const int n0 = ntile * NT;

    if (wid == 0) TCGEN05_ALLOC_CG2(sb + 0, 512);
    if (tid == 0) {
        #pragma unroll
        for (int s = 0; s < 4; s++) {
            MBARRIER_INIT(sb + 16 + 8u * s, rank == 0 ? 2u : 1u);  // full
            MBARRIER_INIT(sb + 48 + 8u * s, 1u);                   // empty
        }
    }
    __syncthreads();
    CLUSTER_SYNC();
    uint32_t tmem;
    asm volatile("ld.shared.b32 %0, [%1];" : "=r"(tmem) : "r"(sb));

    if (tid == 0) {
        auto copies = [&](int c) {
            int s = c & 3;
            uint32_t fb = sb + 16 + 8u * s;
            uint32_t st = sb + HDR + (uint32_t)s * SB;
            MBARRIER_EXPECT_TX(fb, SB);
            size_t aoff = ((size_t)mrow * NCH + c) * TILE_BYTES;
            bulk_g2s(st, Ah + aoff, TILE_BYTES, fb);
            bulk_g2s(st + TILE_BYTES, Al + aoff, TILE_BYTES, fb);
            size_t boff = ((size_t)(ntile * 2 + rank) * NCH + c) * TILE_BYTES;
            bulk_g2s(st + 2 * TILE_BYTES, B + boff, TILE_BYTES, fb);
        };
        copies(0); copies(1); copies(2); copies(3);

        if (rank == 0) {
            for (int c = 0; c < NCH; c++) {
                int s = c & 3;
                uint32_t ph = (uint32_t)((c >> 2) & 1);
                MBARRIER_WAIT_PARITY_CLUSTER(sb + 16 + 8u * s, ph);
                uint32_t st = sb + HDR + (uint32_t)s * SB;
                uint64_t ahd = MAKE_SMEM_DESC(st);
                uint64_t ald = MAKE_SMEM_DESC(st + TILE_BYTES);
                uint64_t bd  = MAKE_SMEM_DESC(st + 2 * TILE_BYTES);
                #pragma unroll
                for (int ks = 0; ks < 4; ks++)
                    mma_f16_ss_cg2(tmem, ahd + ks * 2, bd + ks * 2, IDESC, !(c == 0 && ks == 0));
                #pragma unroll
                for (int ks = 0; ks < 4; ks++)
                    mma_f16_ss_cg2(tmem + NT, ald + ks * 2, bd + ks * 2, IDESC, !(c == 0 && ks == 0));
                TCGEN05_COMMIT_MC_CG2(sb + 48 + 8u * s, 3);
                if (c + 4 < NCH) {
                    MBARRIER_WAIT_PARITY(sb + 48 + 8u * s, ph);
                    copies(c + 4);
                }
            }
        } else {
            for (int c = 0; c < NCH; c++) {
                int s = c & 3;
                uint32_t ph = (uint32_t)((c >> 2) & 1);
                MBARRIER_WAIT_PARITY(sb + 16 + 8u * s, ph);      // own TMA done
                MBARRIER_ARRIVE_CLUSTER(sb + 16 + 8u * s, 0);    // signal leader
                if (c + 4 < NCH) {
                    MBARRIER_WAIT_PARITY(sb + 48 + 8u * s, ph);
                    copies(c + 4);
                }
            }
        }
        for (int c = NCH - 4; c < NCH; c++)
            MBARRIER_WAIT_PARITY(sb + 48 + 8u * (c & 3), (uint32_t)((c >> 2) & 1));
    }
    __syncthreads();
    TCGEN05_FENCE_AFTER();

    // Epilogue: combine acc0 + acc1*2^-10, per-warp transpose, coalesced STG.
    float* buf = (float*)(smem + HDR) + wid * (32 * 33);
    #pragma unroll
    for (int base = 0; base < NT; base += 32) {
        uint32_t r0[32], r1[32];
        TCGEN05_LD_32X32B_X32(r0, tmem + base);
        TCGEN05_LD_32X32B_X32(r1, tmem + NT + base);
        TCGEN05_WAIT_LD();
        #pragma unroll
        for (int q = 0; q < 32; q++)
            buf[lane * 33 + q] = __uint_as_float(r0[q]) + __uint_as_float(r1[q]) * LO_INV;
        __syncwarp();
        float bv = bias[n0 + base + lane];
        #pragma unroll 4
        for (int rr = 0; rr < 32; rr++) {
            int gm = m0 + wid * 32 + rr;
            if (gm < M)
                C[(size_t)gm * Ncols + n0 + base + lane] = (TOut)(buf[rr * 33 + lane] + bv);
        }
        __syncwarp();
    }
    TCGEN05_FENCE_BEFORE();
    __syncthreads();
    if (wid == 0) {
        TCGEN05_RELINQUISH_ALLOC_PERMIT_CG2();
        TCGEN05_DEALLOC_CG2(tmem, 512);
    }
    CLUSTER_SYNC();
#endif
}

// ====== cg1 GEMM kept for the off-GEMM (NT=128, B hi/lo split) ======
template <int NT, int BPARTS, typename TOut>
__global__ void __launch_bounds__(128, 1) __cluster_dims__(1, 2, 1)
gemm_tc(const char* __restrict__ Ah, const char* __restrict__ Al,
        const char* __restrict__ Bh, const char* __restrict__ Bl,
        const float* __restrict__ bias, TOut* __restrict__ C, int M, int Ncols)
{
#if HAS_TCGEN05
    constexpr int NBB = NT / 128;
    constexpr int NBT = BPARTS * NBB;
    constexpr uint32_t SB = (2 + NBT) * TILE_BYTES;
    constexpr uint32_t HDR = 1024;
    constexpr uint32_t IDESC = 0x8000010u | ((NT / 8) << 17);

    extern __shared__ char smem[];
    uint32_t sb = smem_to_u32(smem);
    const int tid = threadIdx.x;
    const int wid = tid >> 5;
    const int lane = tid & 31;
    const int m0 = blockIdx.y * 128;
    const int n0 = blockIdx.x * NT;
    const uint32_t rank = cluster_rank();

    if (wid == 0) TCGEN05_ALLOC(sb + 0, 512);
    if (tid == 0) {
        MBARRIER_INIT(sb + 16, 1);
        MBARRIER_INIT(sb + 24, 1);
        MBARRIER_INIT(sb + 32, 1);
        MBARRIER_INIT(sb + 48, 2);
        MBARRIER_INIT(sb + 56, 2);
        MBARRIER_INIT(sb + 64, 2);
    }
    __syncthreads();
    CLUSTER_SYNC();
    uint32_t tmem;
    asm volatile("ld.shared.b32 %0, [%1];" : "=r"(tmem) : "r"(sb));

    if (tid == 0) {
        auto issue = [&](int c) {
            int s = c % 3;
            uint32_t fb = sb + 16 + 8u * s;
            uint32_t st = sb + HDR + (uint32_t)s * SB;
            MBARRIER_EXPECT_TX(fb, SB);
            size_t aoff = ((size_t)blockIdx.y * NCH + c) * TILE_BYTES;
            bulk_g2s(st, Ah + aoff, TILE_BYTES, fb);
            bulk_g2s(st + TILE_BYTES, Al + aoff, TILE_BYTES, fb);
            #pragma unroll
            for (int i = 0; i < NBT; i++) {
                const char* src;
                if (BPARTS == 1)
                    src = Bh + ((size_t)(blockIdx.x * NBB + i) * NCH + c) * TILE_BYTES;
                else
                    src = (i == 0 ? Bh : Bl) + ((size_t)(blockIdx.x * NBB) * NCH + c) * TILE_BYTES;
                if ((uint32_t)(i & 1) == rank)
                    bulk_g2s_mc(st + (2 + i) * TILE_BYTES, src, TILE_BYTES, fb, 3);
            }
        };
        issue(0); issue(1); issue(2);
        for (int c = 0; c < NCH; c++) {
            int s = c % 3;
            uint32_t fullb  = sb + 16 + 8u * s;
            uint32_t emptyb = sb + 48 + 8u * s;
            MBARRIER_WAIT_PARITY(fullb, (uint32_t)((c / 3) & 1));
            uint32_t st = sb + HDR + (uint32_t)s * SB;
            uint64_t ahd = MAKE_SMEM_DESC(st);
            uint64_t ald = MAKE_SMEM_DESC(st + TILE_BYTES);
            uint64_t bhd = MAKE_SMEM_DESC(st + 2 * TILE_BYTES);
            #pragma unroll
            for (int ks = 0; ks < 4; ks++)
                mma_f16_ss(tmem, ahd + ks * 2, bhd + ks * 2, IDESC, !(c == 0 && ks == 0));
            #pragma unroll
            for (int ks = 0; ks < 4; ks++)
                mma_f16_ss(tmem + NT, ald + ks * 2, bhd + ks * 2, IDESC, !(c == 0 && ks == 0));
            if (BPARTS == 2) {
                uint64_t bld = MAKE_SMEM_DESC(st + 3 * TILE_BYTES);
                #pragma unroll
                for (int ks = 0; ks < 4; ks++)
                    mma_f16_ss(tmem + NT, ahd + ks * 2, bld + ks * 2, IDESC, true);
            }
            TCGEN05_COMMIT_MC(emptyb, 3);
            if (c + 3 < NCH) {
                MBARRIER_WAIT_PARITY(emptyb, (uint32_t)((c / 3) & 1));
                issue(c + 3);
            }
        }
        for (int c = NCH - 3; c < NCH; c++)
            MBARRIER_WAIT_PARITY(sb + 48 + 8u * (c % 3), (uint32_t)((c / 3) & 1));
    }
    __syncthreads();
    TCGEN05_FENCE_AFTER();

    float* buf = (float*)(smem + HDR) + wid * (32 * 33);
    #pragma unroll
    for (int base = 0; base < NT; base += 32) {
        uint32_t r0[32], r1[32];
        TCGEN05_LD_32X32B_X32(r0, tmem + base);
        TCGEN05_LD_32X32B_X32(r1, tmem + NT + base);
        TCGEN05_WAIT_LD();
        #pragma unroll
        for (int q = 0; q < 32; q++)
            buf[lane * 33 + q] = __uint_as_float(r0[q]) + __uint_as_float(r1[q]) * LO_INV;
        __syncwarp();
        float bv = bias[n0 + base + lane];
        #pragma unroll 4
        for (int rr = 0; rr < 32; rr++) {
            int gm = m0 + wid * 32 + rr;
            if (gm < M)
                C[(size_t)gm * Ncols + n0 + base + lane] = (TOut)(buf[rr * 33 + lane] + bv);
        }
        __syncwarp();
    }
    TCGEN05_FENCE_BEFORE();
    __syncthreads();
    if (wid == 0) {
        TCGEN05_RELINQUISH_ALLOC_PERMIT();
        TCGEN05_DEALLOC(tmem, 512);
    }
#endif
}

// ============================ Fallback SGEMM ============================
__global__ void sgemm_bias_kernel(const float* __restrict__ A,
                                  const float* __restrict__ Wt,
                                  const float* __restrict__ bias,
                                  float* __restrict__ C,
                                  int M, int Ncols, int K, int ldw)
{
    __shared__ float As[16][64];
    __shared__ float Bs[16][64];
    const int tid = threadIdx.x;
    const int tx = tid & 15;
    const int ty = tid >> 4;
    const int n0 = blockIdx.x * 64;
    const int m0 = blockIdx.y * 64;
    float acc[4][4] = {};
    for (int k0 = 0; k0 < K; k0 += 16) {
        #pragma unroll
        for (int i = 0; i < 4; i++) {
            int idx = tid + i * 256;
            int m  = idx >> 4, kk = idx & 15, gm = m0 + m;
            As[kk][m] = (gm < M) ? A[(size_t)gm * K + (k0 + kk)] : 0.0f;
        }
        #pragma unroll
        for (int i = 0; i < 4; i++) {
            int idx = tid + i * 256;
            int kk = idx >> 6, n = idx & 63, gn = n0 + n;
            Bs[kk][n] = (gn < Ncols) ? Wt[(size_t)(k0 + kk) * ldw + gn] : 0.0f;
        }
        __syncthreads();
        #pragma unroll
        for (int kk = 0; kk < 16; kk++) {
            float4 a = *(const float4*)&As[kk][ty * 4];
            float4 w = *(const float4*)&Bs[kk][tx * 4];
            acc[0][0] += a.x*w.x; acc[0][1] += a.x*w.y; acc[0][2] += a.x*w.z; acc[0][3] += a.x*w.w;
            acc[1][0] += a.y*w.x; acc[1][1] += a.y*w.y; acc[1][2] += a.y*w.z; acc[1][3] += a.y*w.w;
            acc[2][0] += a.z*w.x; acc[2][1] += a.z*w.y; acc[2][2] += a.z*w.z; acc[2][3] += a.z*w.w;
            acc[3][0] += a.w*w.x; acc[3][1] += a.w*w.y; acc[3][2] += a.w*w.z; acc[3][3] += a.w*w.w;
        }
        __syncthreads();
    }
    #pragma unroll
    for (int r = 0; r < 4; r++) {
        int gm = m0 + ty * 4 + r;
        if (gm >= M) continue;
        #pragma unroll
        for (int c = 0; c < 4; c++) {
            int gn = n0 + tx * 4 + c;
            if (gn < Ncols) C[(size_t)gm * Ncols + gn] = acc[r][c] + bias[gn];
        }
    }
}

// ============================ Attention (warp per (bn,h)), fp16 k gathers ============
__global__ void attn_warp_kernel()
{
    const int bn = blockIdx.x;
    const int h  = threadIdx.x >> 5;
    const int lane = threadIdx.x & 31;

    const int b = bn / NPIX;
    const int n = bn % NPIX;
    const int row = n / WSP;
    const int col = n % WSP;
    const float step = 2.0f / 36.0f;
    const float ybase = -1.0f + row * step;
    const float xbase = -1.0f + col * step;

    float4 q4 = *(const float4*)(g_q + (size_t)bn * CC + h * HD + lane * 4);
    const __half* kbase = g_kh + (size_t)b * NPIX * CC + h * HD + lane * 4;

    float offv = 0.0f;
    if (lane < 16) offv = g_off[(size_t)bn * (HEADS * PTS * 2) + h * (PTS * 2) + lane];

    float4 sv[PTS];
    float sc[PTS];
    #pragma unroll
    for (int p = 0; p < PTS; p++) {
        float o0 = __shfl_sync(0xffffffffu, offv, 2 * p);
        float o1 = __shfl_sync(0xffffffffu, offv, 2 * p + 1);
        float xn = ybase + o0;
        float yn = xbase + o1;
        float ix = fminf(fmaxf((xn + 1.0f) * 0.5f * (WSP - 1), 0.0f), (float)(WSP - 1));
        float iy = fminf(fmaxf((yn + 1.0f) * 0.5f * (HSP - 1), 0.0f), (float)(HSP - 1));
        float x0f = floorf(ix), y0f = floorf(iy);
        float wx = ix - x0f, wy = iy - y0f;
        int x0 = (int)x0f, y0 = (int)y0f;
        int x1 = min(x0 + 1, WSP - 1);
        int y1 = min(y0 + 1, HSP - 1);

        uint2 u00 = *(const uint2*)(kbase + (size_t)(y0 * WSP + x0) * CC);
        uint2 u01 = *(const uint2*)(kbase + (size_t)(y0 * WSP + x1) * CC);
        uint2 u10 = *(const uint2*)(kbase + (size_t)(y1 * WSP + x0) * CC);
        uint2 u11 = *(const uint2*)(kbase + (size_t)(y1 * WSP + x1) * CC);
        float2 a00 = __half22float2(*(__half2*)&u00.x), b00 = __half22float2(*(__half2*)&u00.y);
        float2 a01 = __half22float2(*(__half2*)&u01.x), b01 = __half22float2(*(__half2*)&u01.y);
        float2 a10 = __half22float2(*(__half2*)&u10.x), b10 = __half22float2(*(__half2*)&u10.y);
        float2 a11 = __half22float2(*(__half2*)&u11.x), b11 = __half22float2(*(__half2*)&u11.y);

        float w00 = (1.0f - wy) * (1.0f - wx), w01 = (1.0f - wy) * wx;
        float w10 = wy * (1.0f - wx), w11 = wy * wx;
        float4 s;
        s.x = w00*a00.x + w01*a01.x + w10*a10.x + w11*a11.x;
        s.y = w00*a00.y + w01*a01.y + w10*a10.y + w11*a11.y;
        s.z = w00*b00.x + w01*b01.x + w10*b10.x + w11*b11.x;
        s.w = w00*b00.y + w01*b01.y + w10*b10.y + w11*b11.y;
        sv[p] = s;

        float d = q4.x*s.x + q4.y*s.y + q4.z*s.z + q4.w*s.w;
        #pragma unroll
        for (int o = 16; o; o >>= 1) d += __shfl_xor_sync(0xffffffffu, d, o);
        sc[p] = d * 0.088388347648318447f;
    }

    float m = sc[0];
    #pragma unroll
    for (int p = 1; p < PTS; p++) m = fmaxf(m, sc[p]);
    float e[PTS], denom = 0.0f;
    #pragma unroll
    for (int p = 0; p < PTS; p++) { e[p] = expf(sc[p] - m); denom += e[p]; }
    float inv = 1.0f / denom;

    float4 o = make_float4(0, 0, 0, 0);
    #pragma unroll
    for (int p = 0; p < PTS; p++) {
        float w = e[p] * inv;
        o.x += w * sv[p].x; o.y += w * sv[p].y; o.z += w * sv[p].z; o.w += w * sv[p].w;
    }

    int k = h * HD + lane * 4;
    int mb = bn >> 7, ml = bn & 127;
    int c = k >> 6, kl = k & 63;
    size_t tbase = ((size_t)(mb * NCH + c)) * TILE_BYTES;
    uint32_t off = SMEM_SWIZZLE_128B((uint32_t)(ml * 128 + kl * 2));

    __half h4[4], l4[4];
    float ov[4] = {o.x, o.y, o.z, o.w};
    #pragma unroll
    for (int i = 0; i < 4; i++) {
        h4[i] = __float2half(ov[i]);
        l4[i] = __float2half((ov[i] - __half2float(h4[i])) * LO_SCALE);
    }
    *(uint2*)((char*)g_ah + tbase + off) = *(uint2*)h4;
    *(uint2*)((char*)g_al + tbase + off) = *(uint2*)l4;
}

// Fallback attention (fp32 k, fp32 output to g_attn)
__global__ void attn_kernel(float* __restrict__ out)
{
    const int bn = blockIdx.x;
    const int h  = blockIdx.y;
    const int t  = threadIdx.x;
    const int lane = t & 31;
    const int wid  = t >> 5;
    const int b = bn / NPIX;
    const int n = bn % NPIX;
    const int row = n / WSP;
    const int col = n % WSP;
    const float step = 2.0f / 36.0f;
    const float ybase = -1.0f + row * step;
    const float xbase = -1.0f + col * step;
    const float qv = g_q[(size_t)bn * CC + h * HD + t];
    const float* kbase = g_k + (size_t)b * NPIX * CC + h * HD + t;
    const float* offp  = g_off + (size_t)bn * (HEADS * PTS * 2) + h * (PTS * 2);
    float sv[PTS];
    __shared__ float red[PTS][4];
    __shared__ float sc[PTS];
    #pragma unroll
    for (int p = 0; p < PTS; p++) {
        float o0 = offp[p * 2 + 0], o1 = offp[p * 2 + 1];
        float xn = ybase + o0, yn = xbase + o1;
        float ix = fminf(fmaxf((xn + 1.0f) * 0.5f * (WSP - 1), 0.0f), (float)(WSP - 1));
        float iy = fminf(fmaxf((yn + 1.0f) * 0.5f * (HSP - 1), 0.0f), (float)(HSP - 1));
        float x0f = floorf(ix), y0f = floorf(iy);
        float wx = ix - x0f, wy = iy - y0f;
        int x0 = (int)x0f, y0 = (int)y0f;
        int x1 = min(x0 + 1, WSP - 1), y1 = min(y0 + 1, HSP - 1);
        float v00 = kbase[(size_t)(y0 * WSP + x0) * CC];
        float v01 = kbase[(size_t)(y0 * WSP + x1) * CC];
        float v10 = kbase[(size_t)(y1 * WSP + x0) * CC];
        float v11 = kbase[(size_t)(y1 * WSP + x1) * CC];
        float s = (1.0f - wy) * ((1.0f - wx) * v00 + wx * v01)
                +          wy * ((1.0f - wx) * v10 + wx * v11);
        sv[p] = s;
        float d = qv * s;
        #pragma unroll
        for (int o = 16; o; o >>= 1) d += __shfl_down_sync(0xffffffffu, d, o);
        if (lane == 0) red[p][wid] = d;
    }
    __syncthreads();
    if (t < PTS) sc[t] = (red[t][0] + red[t][1] + red[t][2] + red[t][3]) * 0.088388347648318447f;
    __syncthreads();
    float m = sc[0];
    #pragma unroll
    for (int p = 1; p < PTS; p++) m = fmaxf(m, sc[p]);
    float e[PTS], denom = 0.0f;
    #pragma unroll
    for (int p = 0; p < PTS; p++) { e[p] = expf(sc[p] - m); denom += e[p]; }
    float inv = 1.0f / denom;
    float o = 0.0f;
    #pragma unroll
    for (int p = 0; p < PTS; p++) o += e[p] * inv * sv[p];
    out[(size_t)bn * CC + h * HD + t] = o;
}

// ============================ Launch ============================
extern "C" void kernel_launch(void* const* d_in, const int* in_sizes, int n_in,
                              void* d_out, int out_size)
{
    const float* query = (const float*)d_in[0];
    const float* ref   = (const float*)d_in[1];
    const float* Wq    = (const float*)d_in[2];
    const float* bq    = (const float*)d_in[3];
    const float* Wkv   = (const float*)d_in[4];
    const float* bkv   = (const float*)d_in[5];
    const float* Woff  = (const float*)d_in[6];
    const float* boff  = (const float*)d_in[7];
    const float* Wout  = (const float*)d_in[8];
    const float* bout  = (const float*)d_in[9];
    float* out = (float*)d_out;

    float *q_ptr, *k_ptr, *off_ptr, *attn_ptr;
    __half* kh_ptr;
    cudaGetSymbolAddress((void**)&q_ptr,    g_q);
    cudaGetSymbolAddress((void**)&k_ptr,    g_k);
    cudaGetSymbolAddress((void**)&kh_ptr,   g_kh);
    cudaGetSymbolAddress((void**)&off_ptr,  g_off);
    cudaGetSymbolAddress((void**)&attn_ptr, g_attn);

    cudaFuncAttributes fa;
    cudaFuncGetAttributes(&fa, gemm_cg2<float>);
    bool use_tc = (fa.numRegs > 32);

    if (use_tc) {
        char *qh, *ql, *rh, *rl, *ah, *al;
        char *wq, *wk, *wo, *wfh, *wfl;
        cudaGetSymbolAddress((void**)&qh, g_qh);   cudaGetSymbolAddress((void**)&ql, g_ql);
        cudaGetSymbolAddress((void**)&rh, g_rh);   cudaGetSymbolAddress((void**)&rl, g_rl);
        cudaGetSymbolAddress((void**)&ah, g_ah);   cudaGetSymbolAddress((void**)&al, g_al);
        cudaGetSymbolAddress((void**)&wq, g_Wq);
        cudaGetSymbolAddress((void**)&wk, g_Wk);
        cudaGetSymbolAddress((void**)&wo, g_Wo);
        cudaGetSymbolAddress((void**)&wfh, g_Wf_h); cudaGetSymbolAddress((void**)&wfl, g_Wf_l);

        static bool attr_set = false;
        if (!attr_set) {
            cudaFuncSetAttribute(gemm_cg2<float>,         cudaFuncAttributeMaxDynamicSharedMemorySize, 197632);
            cudaFuncSetAttribute(gemm_cg2<__half>,        cudaFuncAttributeMaxDynamicSharedMemorySize, 197632);
            cudaFuncSetAttribute(gemm_tc<128, 2, float>,  cudaFuncAttributeMaxDynamicSharedMemorySize, 197632);
            attr_set = true;
        }

        split_act2_kernel<<<dim3(NCH, MBLK, 2), 128>>>(
            query, (__half*)qh, (__half*)ql,
            ref,   (__half*)rh, (__half*)rl, BN);
        pack_weights_all<<<dim3(NCH, 25), 512>>>(
            Wq, Wkv, Woff, Wout,
            (__half*)wq, (__half*)wk, (__half*)wfh, (__half*)wfl, (__half*)wo);

        dim3 gcg2(2, 4 * MPAIRS);   // (2, 172), cluster (2,1,1)
        gemm_cg2<float ><<<gcg2, 128, 197632>>>(qh, ql, wq, bq,   q_ptr,  BN, CC);
        gemm_cg2<__half><<<gcg2, 128, 197632>>>(rh, rl, wk, bkv,  kh_ptr, BN, CC);
        gemm_tc<128, 2, float><<<dim3(1, MBLK), 128, 197632>>>(qh, ql, wfh, wfl, boff, off_ptr, BN, 128);

        attn_warp_kernel<<<BN, 256>>>();

        gemm_cg2<float><<<gcg2, 128, 197632>>>(ah, al, wo, bout, out, BN, CC);
    } else {
        dim3 blk(256);
        dim3 gBig((CC + 63) / 64, (BN + 63) / 64);
        dim3 gOff((128 + 63) / 64, (BN + 63) / 64);
        sgemm_bias_kernel<<<gBig, blk>>>(query, Wq, bq, q_ptr, BN, CC, CC, CC);
        sgemm_bias_kernel<<<gBig, blk>>>(ref, Wkv, bkv, k_ptr, BN, CC, CC, 2 * CC);
        sgemm_bias_kernel<<<gOff, blk>>>(query, Woff, boff, off_ptr, BN, HEADS * PTS * 2, CC, HEADS * PTS * 2);
        attn_kernel<<<dim3(BN, HEADS), 128>>>(attn_ptr);
        sgemm_bias_kernel<<<gBig, blk>>>(attn_ptr, Wout, bout, out, BN, CC, CC, CC);
    }
}

// round 11
// speedup vs baseline: 1.3101x; 1.3101x over previous
#include <cuda_runtime.h>
#include <cuda_bf16.h>
#include <cuda_fp16.h>
#include <cstdint>
#include <math.h>

#define NB   8
#define HSP  37
#define WSP  37
#define NPIX 1369
#define BN   10952
#define CC   1024
#define HEADS 8
#define HD   128
#define PTS  8
#define MBLK 86
#define MPAD (MBLK * 128)   // 11008
#define NCH  16             // K chunks of 64
#define TILE_BYTES 16384    // 128 rows x 128B
#define LO_SCALE 1024.0f
#define LO_INV   0.0009765625f

#if defined(__CUDA_ARCH__) && (defined(__CUDA_ARCH_FEAT_SM103_ALL) || defined(__CUDA_ARCH_FEAT_SM100_ALL) || defined(__CUDA_ARCH_SPECIFIC__))
#define HAS_TCGEN05 1
#else
#define HAS_TCGEN05 0
#endif

#define SMEM_SWIZZLE_128B(byte_offset) ((byte_offset) ^ (((byte_offset) >> 3) & 0x70))

// ============================ Scratch ============================
__device__ float g_q[BN * CC];
__device__ float g_k[BN * CC];          // fallback path only
__device__ __half g_kh[BN * CC];        // tc path: k in fp16 for the gather
__device__ float g_off[BN * HEADS * PTS * 2];
__device__ float g_attn[BN * CC];

// Blocked+swizzled fp16 operands (16KB tiles, tile (r,c) at ((r*NCH)+c)*16KB)
__device__ __half g_qh[MPAD * CC];
__device__ __half g_ql[MPAD * CC];
__device__ __half g_rh[MPAD * CC];
__device__ __half g_rl[MPAD * CC];
__device__ __half g_ah[MPAD * CC];
__device__ __half g_al[MPAD * CC];
__device__ __half g_Wq[CC * CC];
__device__ __half g_Wk[CC * CC];
__device__ __half g_Wo[CC * CC];
__device__ __half g_Wf_h[128 * CC];
__device__ __half g_Wf_l[128 * CC];

// ============================ tcgen05 helpers (guarded) ============================
#if HAS_TCGEN05
__device__ __forceinline__ uint32_t smem_to_u32(const void* p) {
    uint32_t a;
    asm("{ .reg .u64 t; cvta.to.shared.u64 t, %1; cvt.u32.u64 %0, t; }" : "=r"(a) : "l"(p));
    return a;
}
#define TCGEN05_ALLOC(smem_result_addr, nCols) \
    asm volatile("tcgen05.alloc.cta_group::1.sync.aligned.shared::cta.b32 [%0], %1;" \
        :: "r"((uint32_t)(smem_result_addr)), "r"((uint32_t)(nCols)) : "memory")
#define TCGEN05_DEALLOC(tmem_addr, nCols) \
    asm volatile("tcgen05.dealloc.cta_group::1.sync.aligned.b32 %0, %1;" :: "r"(tmem_addr), "r"(nCols))
#define TCGEN05_RELINQUISH_ALLOC_PERMIT() \
    asm volatile("tcgen05.relinquish_alloc_permit.cta_group::1.sync.aligned;")
#define TCGEN05_COMMIT_MC(mbar_smem_addr, mask) \
    asm volatile("tcgen05.commit.cta_group::1.mbarrier::arrive::one.shared::cluster.multicast::cluster.b64 [%0], %1;" \
        :: "r"((uint32_t)(mbar_smem_addr)), "h"((uint16_t)(mask)) : "memory")
#define TCGEN05_WAIT_LD() asm volatile("tcgen05.wait::ld.sync.aligned;" ::: "memory")
#define TCGEN05_FENCE_AFTER() asm volatile("tcgen05.fence::after_thread_sync;" ::: "memory")
#define TCGEN05_FENCE_BEFORE() asm volatile("tcgen05.fence::before_thread_sync;" ::: "memory")
#define MBARRIER_INIT(mbar_smem_addr, count) \
    asm volatile("mbarrier.init.shared.b64 [%0], %1;" \
        :: "r"((uint32_t)(mbar_smem_addr)), "r"((uint32_t)(count)) : "memory")
#define MBARRIER_EXPECT_TX(mbar_smem_addr, tx_bytes) \
    asm volatile("mbarrier.arrive.expect_tx.shared.b64 _, [%0], %1;" \
        :: "r"((uint32_t)(mbar_smem_addr)), "r"((uint32_t)(tx_bytes)) : "memory")
#define MBARRIER_WAIT_PARITY(mbar_smem_addr, phase_parity) do { \
    uint32_t _mbar = (uint32_t)(mbar_smem_addr); \
    uint32_t _parity = (uint32_t)(phase_parity); \
    uint32_t _done; \
    asm volatile("{\n\t.reg .pred p;\n\t" \
        "mbarrier.try_wait.parity.acquire.cta.shared::cta.b64 p, [%1], %2;\n\t" \
        "selp.b32 %0, 1, 0, p;\n\t}" : "=r"(_done) : "r"(_mbar), "r"(_parity) : "memory"); \
    if (!_done) { \
        asm volatile("{\n\t.reg .pred P1;\n\t" \
            "WAIT_LOOP_%=:\n\t" \
            "mbarrier.try_wait.parity.acquire.cta.shared::cta.b64 P1, [%0], %1, 0x989680;\n\t" \
            "@P1 bra.uni WAIT_DONE_%=;\n\t" \
            "bra.uni WAIT_LOOP_%=;\n\t" \
            "WAIT_DONE_%=:\n\t}" :: "r"(_mbar), "r"(_parity) : "memory"); \
    } \
} while(0)
#define CLUSTER_SYNC() do { \
    asm volatile("barrier.cluster.arrive.aligned;" ::: "memory"); \
    asm volatile("barrier.cluster.wait.aligned;" ::: "memory"); \
} while(0)
#define TCGEN05_LD_32X32B_X32(r, tmem_addr) \
    asm volatile("tcgen05.ld.sync.aligned.32x32b.x32.b32 " \
        "{%0, %1, %2, %3, %4, %5, %6, %7, %8, %9, %10, %11, %12, %13, %14, %15, " \
        " %16, %17, %18, %19, %20, %21, %22, %23, %24, %25, %26, %27, %28, %29, %30, %31}, [%32];" \
        : "=r"((r)[0]),  "=r"((r)[1]),  "=r"((r)[2]),  "=r"((r)[3]), \
          "=r"((r)[4]),  "=r"((r)[5]),  "=r"((r)[6]),  "=r"((r)[7]), \
          "=r"((r)[8]),  "=r"((r)[9]),  "=r"((r)[10]), "=r"((r)[11]), \
          "=r"((r)[12]), "=r"((r)[13]), "=r"((r)[14]), "=r"((r)[15]), \
          "=r"((r)[16]), "=r"((r)[17]), "=r"((r)[18]), "=r"((r)[19]), \
          "=r"((r)[20]), "=r"((r)[21]), "=r"((r)[22]), "=r"((r)[23]), \
          "=r"((r)[24]), "=r"((r)[25]), "=r"((r)[26]), "=r"((r)[27]), \
          "=r"((r)[28]), "=r"((r)[29]), "=r"((r)[30]), "=r"((r)[31]) \
        : "r"(tmem_addr))

static constexpr uint64_t SMEM_DESC_BASE_SW128 =
    (uint64_t(2)  << 61) | (uint64_t(1) << 46) | (uint64_t(64) << 32) | (uint64_t(1) << 16);
#define MAKE_SMEM_DESC(base_addr) (SMEM_DESC_BASE_SW128 | ((uint64_t)((base_addr) >> 4) & 0x3FFF))

__device__ __forceinline__ void mma_f16_ss(uint32_t d, uint64_t ad, uint64_t bd,
                                           uint32_t idesc, bool en) {
    uint32_t e = en ? 1u : 0u;
    asm volatile(
        "{\n\t.reg .pred p;\n\tsetp.ne.u32 p, %5, 0;\n\t"
        "tcgen05.mma.cta_group::1.kind::f16 [%0], %1, %2, %3, {%4, %4, %4, %4}, p;\n\t}"
        :: "r"(d), "l"(ad), "l"(bd), "r"(idesc), "r"(0u), "r"(e) : "memory");
}
__device__ __forceinline__ void bulk_g2s(uint32_t dst, const void* src, uint32_t bytes, uint32_t mbar) {
    asm volatile("cp.async.bulk.shared::cluster.global.mbarrier::complete_tx::bytes [%0], [%1], %2, [%3];"
        :: "r"(dst), "l"(src), "r"(bytes), "r"(mbar) : "memory");
}
__device__ __forceinline__ void bulk_g2s_mc(uint32_t dst, const void* src, uint32_t bytes,
                                            uint32_t mbar, uint16_t mask) {
    asm volatile("cp.async.bulk.shared::cluster.global.mbarrier::complete_tx::bytes.multicast::cluster [%0], [%1], %2, [%3], %4;"
        :: "r"(dst), "l"(src), "r"(bytes), "r"(mbar), "h"(mask) : "memory");
}
__device__ __forceinline__ uint32_t cluster_rank() {
    uint32_t r;
    asm("mov.u32 %0, %%cluster_ctarank;" : "=r"(r));
    return r;
}
#endif  // HAS_TCGEN05

// ============================ Pack kernels ============================
__global__ void split_act2_kernel(const float* __restrict__ src0,
                                  __half* __restrict__ hi0, __half* __restrict__ lo0,
                                  const float* __restrict__ src1,
                                  __half* __restrict__ hi1, __half* __restrict__ lo1, int M)
{
    const float* src = blockIdx.z ? src1 : src0;
    __half* hi = blockIdx.z ? hi1 : hi0;
    __half* lo = blockIdx.z ? lo1 : lo0;
    const int c  = blockIdx.x;
    const int mb = blockIdx.y;
    const int t  = threadIdx.x;
    const int j  = t & 7;
    char* hbase = (char*)hi + ((size_t)(mb * NCH + c)) * TILE_BYTES;
    char* lbase = (char*)lo + ((size_t)(mb * NCH + c)) * TILE_BYTES;

    #pragma unroll
    for (int g = 0; g < 8; g++) {
        int ml = g * 16 + (t >> 3);
        int m = mb * 128 + ml;
        float x[8];
        if (m < M) {
            float4 a = *(const float4*)(src + (size_t)m * CC + c * 64 + j * 8);
            float4 b = *(const float4*)(src + (size_t)m * CC + c * 64 + j * 8 + 4);
            x[0]=a.x; x[1]=a.y; x[2]=a.z; x[3]=a.w; x[4]=b.x; x[5]=b.y; x[6]=b.z; x[7]=b.w;
        } else {
            #pragma unroll
            for (int i = 0; i < 8; i++) x[i] = 0.0f;
        }
        __half h[8], l[8];
        #pragma unroll
        for (int i = 0; i < 8; i++) {
            h[i] = __float2half(x[i]);
            l[i] = __float2half((x[i] - __half2float(h[i])) * LO_SCALE);
        }
        uint32_t off = SMEM_SWIZZLE_128B((uint32_t)(ml * 128 + j * 16));
        *(uint4*)(hbase + off) = *(uint4*)h;
        *(uint4*)(lbase + off) = *(uint4*)l;
    }
}

__global__ void __launch_bounds__(512)
pack_weights_all(const float* __restrict__ Wq, const float* __restrict__ Wkv,
                 const float* __restrict__ Woff, const float* __restrict__ Wout,
                 __half* __restrict__ wq, __half* __restrict__ wk,
                 __half* __restrict__ wfh, __half* __restrict__ wfl,
                 __half* __restrict__ wo)
{
    __shared__ float ts[64][129];
    const int c = blockIdx.x;
    const int y = blockIdx.y;
    const int t = threadIdx.x;

    const float* W; int ldw, nb; __half *hi, *lo;
    if (y < 8)       { W = Wq;   ldw = CC;     nb = y;      hi = wq;  lo = nullptr; }
    else if (y < 16) { W = Wkv;  ldw = 2 * CC; nb = y - 8;  hi = wk;  lo = nullptr; }
    else if (y < 17) { W = Woff; ldw = 128;    nb = 0;      hi = wfh; lo = wfl; }
    else             { W = Wout; ldw = CC;     nb = y - 17; hi = wo;  lo = nullptr; }

    const int k0 = c * 64;
    const int n0 = nb * 128;
    const int lrow = t >> 7;
    const int lcol = t & 127;
    #pragma unroll
    for (int i = 0; i < 16; i++) {
        int row = i * 4 + lrow;
        ts[row][lcol] = W[(size_t)(k0 + row) * ldw + n0 + lcol];
    }
    __syncthreads();

    char* hbase = (char*)hi + ((size_t)(nb * NCH + c)) * TILE_BYTES;
    char* lbase = lo ? (char*)lo + ((size_t)(nb * NCH + c)) * TILE_BYTES : nullptr;
    #pragma unroll
    for (int it = 0; it < 2; it++) {
        int idx = t + it * 512;
        int nl = idx >> 3;
        int j  = idx & 7;
        __half h[8], l[8];
        #pragma unroll
        for (int jj = 0; jj < 8; jj++) {
            float x = ts[j * 8 + jj][nl];
            h[jj] = __float2half(x);
            l[jj] = __float2half((x - __half2float(h[jj])) * LO_SCALE);
        }
        uint32_t off = SMEM_SWIZZLE_128B((uint32_t)(nl * 128 + j * 16));
        *(uint4*)(hbase + off) = *(uint4*)h;
        if (lbase) *(uint4*)(lbase + off) = *(uint4*)l;
    }
}

// ===== cg1 GEMM, WARP-SPECIALIZED pipeline: thread0 = MMA consumer, thread32 = =====
// ===== copy producer. A hi/lo split -> two accumulators; optional B hi/lo.     =====
// Producer waits on the 3-chunk-older commit, so MMA issue never blocks on its
// own completion (round-7's serialization bug).
template <int NT, int BPARTS, typename TOut>
__global__ void __launch_bounds__(128, 1) __cluster_dims__(1, 2, 1)
gemm_tc(const char* __restrict__ Ah, const char* __restrict__ Al,
        const char* __restrict__ Bh, const char* __restrict__ Bl,
        const float* __restrict__ bias, TOut* __restrict__ C, int M, int Ncols)
{
#if HAS_TCGEN05
    constexpr int NBB = NT / 128;
    constexpr int NBT = BPARTS * NBB;
    constexpr uint32_t SB = (2 + NBT) * TILE_BYTES;
    constexpr uint32_t HDR = 1024;
    constexpr uint32_t IDESC = 0x8000010u | ((NT / 8) << 17);

    extern __shared__ char smem[];
    uint32_t sb = smem_to_u32(smem);
    const int tid = threadIdx.x;
    const int wid = tid >> 5;
    const int lane = tid & 31;
    const int m0 = blockIdx.y * 128;
    const int n0 = blockIdx.x * NT;
    const uint32_t rank = cluster_rank();

    if (wid == 0) TCGEN05_ALLOC(sb + 0, 512);
    if (tid == 0) {
        MBARRIER_INIT(sb + 16, 1);   // full0
        MBARRIER_INIT(sb + 24, 1);   // full1
        MBARRIER_INIT(sb + 32, 1);   // full2
        MBARRIER_INIT(sb + 48, 2);   // empty0 (both ranks' commits)
        MBARRIER_INIT(sb + 56, 2);   // empty1
        MBARRIER_INIT(sb + 64, 2);   // empty2
    }
    __syncthreads();
    CLUSTER_SYNC();
    uint32_t tmem;
    asm volatile("ld.shared.b32 %0, [%1];" : "=r"(tmem) : "r"(sb));

    if (tid == 0) {
        // ---- MMA consumer: never waits on empty in the loop ----
        for (int c = 0; c < NCH; c++) {
            int s = c % 3;
            MBARRIER_WAIT_PARITY(sb + 16 + 8u * s, (uint32_t)((c / 3) & 1));
            uint32_t st = sb + HDR + (uint32_t)s * SB;
            uint64_t ahd = MAKE_SMEM_DESC(st);
            uint64_t ald = MAKE_SMEM_DESC(st + TILE_BYTES);
            uint64_t bhd = MAKE_SMEM_DESC(st + 2 * TILE_BYTES);
            #pragma unroll
            for (int ks = 0; ks < 4; ks++)
                mma_f16_ss(tmem, ahd + ks * 2, bhd + ks * 2, IDESC, !(c == 0 && ks == 0));
            #pragma unroll
            for (int ks = 0; ks < 4; ks++)
                mma_f16_ss(tmem + NT, ald + ks * 2, bhd + ks * 2, IDESC, !(c == 0 && ks == 0));
            if (BPARTS == 2) {
                uint64_t bld = MAKE_SMEM_DESC(st + 3 * TILE_BYTES);
                #pragma unroll
                for (int ks = 0; ks < 4; ks++)
                    mma_f16_ss(tmem + NT, ahd + ks * 2, bld + ks * 2, IDESC, true);
            }
            TCGEN05_COMMIT_MC(sb + 48 + 8u * s, 3);
        }
        // drain: wait for the final commit on each stage before the epilogue
        for (int c = NCH - 3; c < NCH; c++)
            MBARRIER_WAIT_PARITY(sb + 48 + 8u * (c % 3), (uint32_t)((c / 3) & 1));
    } else if (tid == 32) {
        // ---- copy producer ----
        auto issue = [&](int c) {
            int s = c % 3;
            uint32_t fb = sb + 16 + 8u * s;
            uint32_t st = sb + HDR + (uint32_t)s * SB;
            MBARRIER_EXPECT_TX(fb, SB);
            size_t aoff = ((size_t)blockIdx.y * NCH + c) * TILE_BYTES;
            bulk_g2s(st, Ah + aoff, TILE_BYTES, fb);
            bulk_g2s(st + TILE_BYTES, Al + aoff, TILE_BYTES, fb);
            #pragma unroll
            for (int i = 0; i < NBT; i++) {
                const char* src;
                if (BPARTS == 1)
                    src = Bh + ((size_t)(blockIdx.x * NBB + i) * NCH + c) * TILE_BYTES;
                else
                    src = (i == 0 ? Bh : Bl) + ((size_t)(blockIdx.x * NBB) * NCH + c) * TILE_BYTES;
                if ((uint32_t)(i & 1) == rank)
                    bulk_g2s_mc(st + (2 + i) * TILE_BYTES, src, TILE_BYTES, fb, 3);
            }
        };
        issue(0); issue(1); issue(2);
        for (int c = 3; c < NCH; c++) {
            int s = c % 3;
            // wait for chunk c-3's commit (phase (c/3 - 1)) before refilling stage s
            MBARRIER_WAIT_PARITY(sb + 48 + 8u * s, (uint32_t)((c / 3 - 1) & 1));
            issue(c);
        }
    }
    __syncthreads();
    TCGEN05_FENCE_AFTER();

    // Epilogue: combine acc0 + acc1*2^-10, per-warp transpose, coalesced STG.
    float* buf = (float*)(smem + HDR) + wid * (32 * 33);
    #pragma unroll
    for (int base = 0; base < NT; base += 32) {
        uint32_t r0[32], r1[32];
        TCGEN05_LD_32X32B_X32(r0, tmem + base);
        TCGEN05_LD_32X32B_X32(r1, tmem + NT + base);
        TCGEN05_WAIT_LD();
        #pragma unroll
        for (int q = 0; q < 32; q++)
            buf[lane * 33 + q] = __uint_as_float(r0[q]) + __uint_as_float(r1[q]) * LO_INV;
        __syncwarp();
        float bv = bias[n0 + base + lane];
        #pragma unroll 4
        for (int rr = 0; rr < 32; rr++) {
            int gm = m0 + wid * 32 + rr;
            if (gm < M)
                C[(size_t)gm * Ncols + n0 + base + lane] = (TOut)(buf[rr * 33 + lane] + bv);
        }
        __syncwarp();
    }
    TCGEN05_FENCE_BEFORE();
    __syncthreads();
    if (wid == 0) {
        TCGEN05_RELINQUISH_ALLOC_PERMIT();
        TCGEN05_DEALLOC(tmem, 512);
    }
#endif
}

// ============================ Fallback SGEMM ============================
__global__ void sgemm_bias_kernel(const float* __restrict__ A,
                                  const float* __restrict__ Wt,
                                  const float* __restrict__ bias,
                                  float* __restrict__ C,
                                  int M, int Ncols, int K, int ldw)
{
    __shared__ float As[16][64];
    __shared__ float Bs[16][64];
    const int tid = threadIdx.x;
    const int tx = tid & 15;
    const int ty = tid >> 4;
    const int n0 = blockIdx.x * 64;
    const int m0 = blockIdx.y * 64;
    float acc[4][4] = {};
    for (int k0 = 0; k0 < K; k0 += 16) {
        #pragma unroll
        for (int i = 0; i < 4; i++) {
            int idx = tid + i * 256;
            int m  = idx >> 4, kk = idx & 15, gm = m0 + m;
            As[kk][m] = (gm < M) ? A[(size_t)gm * K + (k0 + kk)] : 0.0f;
        }
        #pragma unroll
        for (int i = 0; i < 4; i++) {
            int idx = tid + i * 256;
            int kk = idx >> 6, n = idx & 63, gn = n0 + n;
            Bs[kk][n] = (gn < Ncols) ? Wt[(size_t)(k0 + kk) * ldw + gn] : 0.0f;
        }
        __syncthreads();
        #pragma unroll
        for (int kk = 0; kk < 16; kk++) {
            float4 a = *(const float4*)&As[kk][ty * 4];
            float4 w = *(const float4*)&Bs[kk][tx * 4];
            acc[0][0] += a.x*w.x; acc[0][1] += a.x*w.y; acc[0][2] += a.x*w.z; acc[0][3] += a.x*w.w;
            acc[1][0] += a.y*w.x; acc[1][1] += a.y*w.y; acc[1][2] += a.y*w.z; acc[1][3] += a.y*w.w;
            acc[2][0] += a.z*w.x; acc[2][1] += a.z*w.y; acc[2][2] += a.z*w.z; acc[2][3] += a.z*w.w;
            acc[3][0] += a.w*w.x; acc[3][1] += a.w*w.y; acc[3][2] += a.w*w.z; acc[3][3] += a.w*w.w;
        }
        __syncthreads();
    }
    #pragma unroll
    for (int r = 0; r < 4; r++) {
        int gm = m0 + ty * 4 + r;
        if (gm >= M) continue;
        #pragma unroll
        for (int c = 0; c < 4; c++) {
            int gn = n0 + tx * 4 + c;
            if (gn < Ncols) C[(size_t)gm * Ncols + gn] = acc[r][c] + bias[gn];
        }
    }
}

// ============================ Attention (warp per (bn,h)), fp16 k gathers ============
__global__ void attn_warp_kernel()
{
    const int bn = blockIdx.x;
    const int h  = threadIdx.x >> 5;
    const int lane = threadIdx.x & 31;

    const int b = bn / NPIX;
    const int n = bn % NPIX;
    const int row = n / WSP;
    const int col = n % WSP;
    const float step = 2.0f / 36.0f;
    const float ybase = -1.0f + row * step;
    const float xbase = -1.0f + col * step;

    float4 q4 = *(const float4*)(g_q + (size_t)bn * CC + h * HD + lane * 4);
    const __half* kbase = g_kh + (size_t)b * NPIX * CC + h * HD + lane * 4;

    float offv = 0.0f;
    if (lane < 16) offv = g_off[(size_t)bn * (HEADS * PTS * 2) + h * (PTS * 2) + lane];

    float4 sv[PTS];
    float sc[PTS];
    #pragma unroll
    for (int p = 0; p < PTS; p++) {
        float o0 = __shfl_sync(0xffffffffu, offv, 2 * p);
        float o1 = __shfl_sync(0xffffffffu, offv, 2 * p + 1);
        float xn = ybase + o0;
        float yn = xbase + o1;
        float ix = fminf(fmaxf((xn + 1.0f) * 0.5f * (WSP - 1), 0.0f), (float)(WSP - 1));
        float iy = fminf(fmaxf((yn + 1.0f) * 0.5f * (HSP - 1), 0.0f), (float)(HSP - 1));
        float x0f = floorf(ix), y0f = floorf(iy);
        float wx = ix - x0f, wy = iy - y0f;
        int x0 = (int)x0f, y0 = (int)y0f;
        int x1 = min(x0 + 1, WSP - 1);
        int y1 = min(y0 + 1, HSP - 1);

        uint2 u00 = *(const uint2*)(kbase + (size_t)(y0 * WSP + x0) * CC);
        uint2 u01 = *(const uint2*)(kbase + (size_t)(y0 * WSP + x1) * CC);
        uint2 u10 = *(const uint2*)(kbase + (size_t)(y1 * WSP + x0) * CC);
        uint2 u11 = *(const uint2*)(kbase + (size_t)(y1 * WSP + x1) * CC);
        float2 a00 = __half22float2(*(__half2*)&u00.x), b00 = __half22float2(*(__half2*)&u00.y);
        float2 a01 = __half22float2(*(__half2*)&u01.x), b01 = __half22float2(*(__half2*)&u01.y);
        float2 a10 = __half22float2(*(__half2*)&u10.x), b10 = __half22float2(*(__half2*)&u10.y);
        float2 a11 = __half22float2(*(__half2*)&u11.x), b11 = __half22float2(*(__half2*)&u11.y);

        float w00 = (1.0f - wy) * (1.0f - wx), w01 = (1.0f - wy) * wx;
        float w10 = wy * (1.0f - wx), w11 = wy * wx;
        float4 s;
        s.x = w00*a00.x + w01*a01.x + w10*a10.x + w11*a11.x;
        s.y = w00*a00.y + w01*a01.y + w10*a10.y + w11*a11.y;
        s.z = w00*b00.x + w01*b01.x + w10*b10.x + w11*b11.x;
        s.w = w00*b00.y + w01*b01.y + w10*b10.y + w11*b11.y;
        sv[p] = s;

        float d = q4.x*s.x + q4.y*s.y + q4.z*s.z + q4.w*s.w;
        #pragma unroll
        for (int o = 16; o; o >>= 1) d += __shfl_xor_sync(0xffffffffu, d, o);
        sc[p] = d * 0.088388347648318447f;
    }

    float m = sc[0];
    #pragma unroll
    for (int p = 1; p < PTS; p++) m = fmaxf(m, sc[p]);
    float e[PTS], denom = 0.0f;
    #pragma unroll
    for (int p = 0; p < PTS; p++) { e[p] = expf(sc[p] - m); denom += e[p]; }
    float inv = 1.0f / denom;

    float4 o = make_float4(0, 0, 0, 0);
    #pragma unroll
    for (int p = 0; p < PTS; p++) {
        float w = e[p] * inv;
        o.x += w * sv[p].x; o.y += w * sv[p].y; o.z += w * sv[p].z; o.w += w * sv[p].w;
    }

    int k = h * HD + lane * 4;
    int mb = bn >> 7, ml = bn & 127;
    int c = k >> 6, kl = k & 63;
    size_t tbase = ((size_t)(mb * NCH + c)) * TILE_BYTES;
    uint32_t off = SMEM_SWIZZLE_128B((uint32_t)(ml * 128 + kl * 2));

    __half h4[4], l4[4];
    float ov[4] = {o.x, o.y, o.z, o.w};
    #pragma unroll
    for (int i = 0; i < 4; i++) {
        h4[i] = __float2half(ov[i]);
        l4[i] = __float2half((ov[i] - __half2float(h4[i])) * LO_SCALE);
    }
    *(uint2*)((char*)g_ah + tbase + off) = *(uint2*)h4;
    *(uint2*)((char*)g_al + tbase + off) = *(uint2*)l4;
}

// Fallback attention (fp32 k, fp32 output to g_attn)
__global__ void attn_kernel(float* __restrict__ out)
{
    const int bn = blockIdx.x;
    const int h  = blockIdx.y;
    const int t  = threadIdx.x;
    const int lane = t & 31;
    const int wid  = t >> 5;
    const int b = bn / NPIX;
    const int n = bn % NPIX;
    const int row = n / WSP;
    const int col = n % WSP;
    const float step = 2.0f / 36.0f;
    const float ybase = -1.0f + row * step;
    const float xbase = -1.0f + col * step;
    const float qv = g_q[(size_t)bn * CC + h * HD + t];
    const float* kbase = g_k + (size_t)b * NPIX * CC + h * HD + t;
    const float* offp  = g_off + (size_t)bn * (HEADS * PTS * 2) + h * (PTS * 2);
    float sv[PTS];
    __shared__ float red[PTS][4];
    __shared__ float sc[PTS];
    #pragma unroll
    for (int p = 0; p < PTS; p++) {
        float o0 = offp[p * 2 + 0], o1 = offp[p * 2 + 1];
        float xn = ybase + o0, yn = xbase + o1;
        float ix = fminf(fmaxf((xn + 1.0f) * 0.5f * (WSP - 1), 0.0f), (float)(WSP - 1));
        float iy = fminf(fmaxf((yn + 1.0f) * 0.5f * (HSP - 1), 0.0f), (float)(HSP - 1));
        float x0f = floorf(ix), y0f = floorf(iy);
        float wx = ix - x0f, wy = iy - y0f;
        int x0 = (int)x0f, y0 = (int)y0f;
        int x1 = min(x0 + 1, WSP - 1), y1 = min(y0 + 1, HSP - 1);
        float v00 = kbase[(size_t)(y0 * WSP + x0) * CC];
        float v01 = kbase[(size_t)(y0 * WSP + x1) * CC];
        float v10 = kbase[(size_t)(y1 * WSP + x0) * CC];
        float v11 = kbase[(size_t)(y1 * WSP + x1) * CC];
        float s = (1.0f - wy) * ((1.0f - wx) * v00 + wx * v01)
                +          wy * ((1.0f - wx) * v10 + wx * v11);
        sv[p] = s;
        float d = qv * s;
        #pragma unroll
        for (int o = 16; o; o >>= 1) d += __shfl_down_sync(0xffffffffu, d, o);
        if (lane == 0) red[p][wid] = d;
    }
    __syncthreads();
    if (t < PTS) sc[t] = (red[t][0] + red[t][1] + red[t][2] + red[t][3]) * 0.088388347648318447f;
    __syncthreads();
    float m = sc[0];
    #pragma unroll
    for (int p = 1; p < PTS; p++) m = fmaxf(m, sc[p]);
    float e[PTS], denom = 0.0f;
    #pragma unroll
    for (int p = 0; p < PTS; p++) { e[p] = expf(sc[p] - m); denom += e[p]; }
    float inv = 1.0f / denom;
    float o = 0.0f;
    #pragma unroll
    for (int p = 0; p < PTS; p++) o += e[p] * inv * sv[p];
    out[(size_t)bn * CC + h * HD + t] = o;
}

// ============================ Launch ============================
extern "C" void kernel_launch(void* const* d_in, const int* in_sizes, int n_in,
                              void* d_out, int out_size)
{
    const float* query = (const float*)d_in[0];
    const float* ref   = (const float*)d_in[1];
    const float* Wq    = (const float*)d_in[2];
    const float* bq    = (const float*)d_in[3];
    const float* Wkv   = (const float*)d_in[4];
    const float* bkv   = (const float*)d_in[5];
    const float* Woff  = (const float*)d_in[6];
    const float* boff  = (const float*)d_in[7];
    const float* Wout  = (const float*)d_in[8];
    const float* bout  = (const float*)d_in[9];
    float* out = (float*)d_out;

    float *q_ptr, *k_ptr, *off_ptr, *attn_ptr;
    __half* kh_ptr;
    cudaGetSymbolAddress((void**)&q_ptr,    g_q);
    cudaGetSymbolAddress((void**)&k_ptr,    g_k);
    cudaGetSymbolAddress((void**)&kh_ptr,   g_kh);
    cudaGetSymbolAddress((void**)&off_ptr,  g_off);
    cudaGetSymbolAddress((void**)&attn_ptr, g_attn);

    cudaFuncAttributes fa;
    cudaFuncGetAttributes(&fa, gemm_tc<256, 1, float>);
    bool use_tc = (fa.numRegs > 32);

    if (use_tc) {
        char *qh, *ql, *rh, *rl, *ah, *al;
        char *wq, *wk, *wo, *wfh, *wfl;
        cudaGetSymbolAddress((void**)&qh, g_qh);   cudaGetSymbolAddress((void**)&ql, g_ql);
        cudaGetSymbolAddress((void**)&rh, g_rh);   cudaGetSymbolAddress((void**)&rl, g_rl);
        cudaGetSymbolAddress((void**)&ah, g_ah);   cudaGetSymbolAddress((void**)&al, g_al);
        cudaGetSymbolAddress((void**)&wq, g_Wq);
        cudaGetSymbolAddress((void**)&wk, g_Wk);
        cudaGetSymbolAddress((void**)&wo, g_Wo);
        cudaGetSymbolAddress((void**)&wfh, g_Wf_h); cudaGetSymbolAddress((void**)&wfl, g_Wf_l);

        static bool attr_set = false;
        if (!attr_set) {
            cudaFuncSetAttribute(gemm_tc<256, 1, float>,  cudaFuncAttributeMaxDynamicSharedMemorySize, 197632);
            cudaFuncSetAttribute(gemm_tc<256, 1, __half>, cudaFuncAttributeMaxDynamicSharedMemorySize, 197632);
            cudaFuncSetAttribute(gemm_tc<128, 2, float>,  cudaFuncAttributeMaxDynamicSharedMemorySize, 197632);
            attr_set = true;
        }

        split_act2_kernel<<<dim3(NCH, MBLK, 2), 128>>>(
            query, (__half*)qh, (__half*)ql,
            ref,   (__half*)rh, (__half*)rl, BN);
        pack_weights_all<<<dim3(NCH, 25), 512>>>(
            Wq, Wkv, Woff, Wout,
            (__half*)wq, (__half*)wk, (__half*)wfh, (__half*)wfl, (__half*)wo);

        gemm_tc<256, 1, float ><<<dim3(4, MBLK), 128, 197632>>>(qh, ql, wq, nullptr, bq,   q_ptr,   BN, CC);
        gemm_tc<256, 1, __half><<<dim3(4, MBLK), 128, 197632>>>(rh, rl, wk, nullptr, bkv,  kh_ptr,  BN, CC);
        gemm_tc<128, 2, float ><<<dim3(1, MBLK), 128, 197632>>>(qh, ql, wfh, wfl,    boff, off_ptr, BN, 128);

        attn_warp_kernel<<<BN, 256>>>();

        gemm_tc<256, 1, float><<<dim3(4, MBLK), 128, 197632>>>(ah, al, wo, nullptr, bout, out, BN, CC);
    } else {
        dim3 blk(256);
        dim3 gBig((CC + 63) / 64, (BN + 63) / 64);
        dim3 gOff((128 + 63) / 64, (BN + 63) / 64);
        sgemm_bias_kernel<<<gBig, blk>>>(query, Wq, bq, q_ptr, BN, CC, CC, CC);
        sgemm_bias_kernel<<<gBig, blk>>>(ref, Wkv, bkv, k_ptr, BN, CC, CC, 2 * CC);
        sgemm_bias_kernel<<<gOff, blk>>>(query, Woff, boff, off_ptr, BN, HEADS * PTS * 2, CC, HEADS * PTS * 2);
        attn_kernel<<<dim3(BN, HEADS), 128>>>(attn_ptr);
        sgemm_bias_kernel<<<gBig, blk>>>(attn_ptr, Wout, bout, out, BN, CC, CC, CC);
    }
}

// round 12
// speedup vs baseline: 1.3137x; 1.0027x over previous
#include <cuda_runtime.h>
#include <cuda_bf16.h>
#include <cuda_fp16.h>
#include <cstdint>
#include <math.h>

#define NB   8
#define HSP  37
#define WSP  37
#define NPIX 1369
#define BN   10952
#define CC   1024
#define HEADS 8
#define HD   128
#define PTS  8
#define MBLK 86
#define MPAD (MBLK * 128)   // 11008
#define NCH  16             // K chunks of 64
#define TILE_BYTES 16384    // 128 rows x 128B
#define LO_SCALE 1024.0f
#define LO_INV   0.0009765625f

#if defined(__CUDA_ARCH__) && (defined(__CUDA_ARCH_FEAT_SM103_ALL) || defined(__CUDA_ARCH_FEAT_SM100_ALL) || defined(__CUDA_ARCH_SPECIFIC__))
#define HAS_TCGEN05 1
#else
#define HAS_TCGEN05 0
#endif

#define SMEM_SWIZZLE_128B(byte_offset) ((byte_offset) ^ (((byte_offset) >> 3) & 0x70))

// ============================ Scratch ============================
__device__ float g_q[BN * CC];
__device__ float g_k[BN * CC];          // fallback path only
__device__ __half g_kh[BN * CC];        // tc path: k in fp16 for the gather
__device__ float g_off[BN * HEADS * PTS * 2];
__device__ float g_attn[BN * CC];

// Blocked+swizzled fp16 operands (16KB tiles, tile (r,c) at ((r*NCH)+c)*16KB)
__device__ __half g_qh[MPAD * CC];
__device__ __half g_ql[MPAD * CC];
__device__ __half g_rh[MPAD * CC];
__device__ __half g_rl[MPAD * CC];
__device__ __half g_ah[MPAD * CC];
__device__ __half g_al[MPAD * CC];
__device__ __half g_Wq[CC * CC];
__device__ __half g_Wk[CC * CC];
__device__ __half g_Wo[CC * CC];
__device__ __half g_Wf_h[128 * CC];
__device__ __half g_Wf_l[128 * CC];

// ============================ tcgen05 helpers (guarded) ============================
#if HAS_TCGEN05
__device__ __forceinline__ uint32_t smem_to_u32(const void* p) {
    uint32_t a;
    asm("{ .reg .u64 t; cvta.to.shared.u64 t, %1; cvt.u32.u64 %0, t; }" : "=r"(a) : "l"(p));
    return a;
}
#define TCGEN05_ALLOC(smem_result_addr, nCols) \
    asm volatile("tcgen05.alloc.cta_group::1.sync.aligned.shared::cta.b32 [%0], %1;" \
        :: "r"((uint32_t)(smem_result_addr)), "r"((uint32_t)(nCols)) : "memory")
#define TCGEN05_DEALLOC(tmem_addr, nCols) \
    asm volatile("tcgen05.dealloc.cta_group::1.sync.aligned.b32 %0, %1;" :: "r"(tmem_addr), "r"(nCols))
#define TCGEN05_RELINQUISH_ALLOC_PERMIT() \
    asm volatile("tcgen05.relinquish_alloc_permit.cta_group::1.sync.aligned;")
#define TCGEN05_COMMIT_MC(mbar_smem_addr, mask) \
    asm volatile("tcgen05.commit.cta_group::1.mbarrier::arrive::one.shared::cluster.multicast::cluster.b64 [%0], %1;" \
        :: "r"((uint32_t)(mbar_smem_addr)), "h"((uint16_t)(mask)) : "memory")
#define TCGEN05_WAIT_LD() asm volatile("tcgen05.wait::ld.sync.aligned;" ::: "memory")
#define TCGEN05_FENCE_AFTER() asm volatile("tcgen05.fence::after_thread_sync;" ::: "memory")
#define TCGEN05_FENCE_BEFORE() asm volatile("tcgen05.fence::before_thread_sync;" ::: "memory")
#define MBARRIER_INIT(mbar_smem_addr, count) \
    asm volatile("mbarrier.init.shared.b64 [%0], %1;" \
        :: "r"((uint32_t)(mbar_smem_addr)), "r"((uint32_t)(count)) : "memory")
#define MBARRIER_EXPECT_TX(mbar_smem_addr, tx_bytes) \
    asm volatile("mbarrier.arrive.expect_tx.shared.b64 _, [%0], %1;" \
        :: "r"((uint32_t)(mbar_smem_addr)), "r"((uint32_t)(tx_bytes)) : "memory")
#define MBARRIER_WAIT_PARITY(mbar_smem_addr, phase_parity) do { \
    uint32_t _mbar = (uint32_t)(mbar_smem_addr); \
    uint32_t _parity = (uint32_t)(phase_parity); \
    uint32_t _done; \
    asm volatile("{\n\t.reg .pred p;\n\t" \
        "mbarrier.try_wait.parity.acquire.cta.shared::cta.b64 p, [%1], %2;\n\t" \
        "selp.b32 %0, 1, 0, p;\n\t}" : "=r"(_done) : "r"(_mbar), "r"(_parity) : "memory"); \
    if (!_done) { \
        asm volatile("{\n\t.reg .pred P1;\n\t" \
            "WAIT_LOOP_%=:\n\t" \
            "mbarrier.try_wait.parity.acquire.cta.shared::cta.b64 P1, [%0], %1, 0x989680;\n\t" \
            "@P1 bra.uni WAIT_DONE_%=;\n\t" \
            "bra.uni WAIT_LOOP_%=;\n\t" \
            "WAIT_DONE_%=:\n\t}" :: "r"(_mbar), "r"(_parity) : "memory"); \
    } \
} while(0)
#define CLUSTER_SYNC() do { \
    asm volatile("barrier.cluster.arrive.aligned;" ::: "memory"); \
    asm volatile("barrier.cluster.wait.aligned;" ::: "memory"); \
} while(0)
#define TCGEN05_LD_32X32B_X32(r, tmem_addr) \
    asm volatile("tcgen05.ld.sync.aligned.32x32b.x32.b32 " \
        "{%0, %1, %2, %3, %4, %5, %6, %7, %8, %9, %10, %11, %12, %13, %14, %15, " \
        " %16, %17, %18, %19, %20, %21, %22, %23, %24, %25, %26, %27, %28, %29, %30, %31}, [%32];" \
        : "=r"((r)[0]),  "=r"((r)[1]),  "=r"((r)[2]),  "=r"((r)[3]), \
          "=r"((r)[4]),  "=r"((r)[5]),  "=r"((r)[6]),  "=r"((r)[7]), \
          "=r"((r)[8]),  "=r"((r)[9]),  "=r"((r)[10]), "=r"((r)[11]), \
          "=r"((r)[12]), "=r"((r)[13]), "=r"((r)[14]), "=r"((r)[15]), \
          "=r"((r)[16]), "=r"((r)[17]), "=r"((r)[18]), "=r"((r)[19]), \
          "=r"((r)[20]), "=r"((r)[21]), "=r"((r)[22]), "=r"((r)[23]), \
          "=r"((r)[24]), "=r"((r)[25]), "=r"((r)[26]), "=r"((r)[27]), \
          "=r"((r)[28]), "=r"((r)[29]), "=r"((r)[30]), "=r"((r)[31]) \
        : "r"(tmem_addr))

static constexpr uint64_t SMEM_DESC_BASE_SW128 =
    (uint64_t(2)  << 61) | (uint64_t(1) << 46) | (uint64_t(64) << 32) | (uint64_t(1) << 16);
#define MAKE_SMEM_DESC(base_addr) (SMEM_DESC_BASE_SW128 | ((uint64_t)((base_addr) >> 4) & 0x3FFF))

__device__ __forceinline__ void mma_f16_ss(uint32_t d, uint64_t ad, uint64_t bd,
                                           uint32_t idesc, bool en) {
    uint32_t e = en ? 1u : 0u;
    asm volatile(
        "{\n\t.reg .pred p;\n\tsetp.ne.u32 p, %5, 0;\n\t"
        "tcgen05.mma.cta_group::1.kind::f16 [%0], %1, %2, %3, {%4, %4, %4, %4}, p;\n\t}"
        :: "r"(d), "l"(ad), "l"(bd), "r"(idesc), "r"(0u), "r"(e) : "memory");
}
__device__ __forceinline__ void bulk_g2s(uint32_t dst, const void* src, uint32_t bytes, uint32_t mbar) {
    asm volatile("cp.async.bulk.shared::cluster.global.mbarrier::complete_tx::bytes [%0], [%1], %2, [%3];"
        :: "r"(dst), "l"(src), "r"(bytes), "r"(mbar) : "memory");
}
__device__ __forceinline__ void bulk_g2s_mc(uint32_t dst, const void* src, uint32_t bytes,
                                            uint32_t mbar, uint16_t mask) {
    asm volatile("cp.async.bulk.shared::cluster.global.mbarrier::complete_tx::bytes.multicast::cluster [%0], [%1], %2, [%3], %4;"
        :: "r"(dst), "l"(src), "r"(bytes), "r"(mbar), "h"(mask) : "memory");
}
__device__ __forceinline__ uint32_t cluster_rank() {
    uint32_t r;
    asm("mov.u32 %0, %%cluster_ctarank;" : "=r"(r));
    return r;
}
#endif  // HAS_TCGEN05

// ============================ Pack kernels ============================
__global__ void split_act2_kernel(const float* __restrict__ src0,
                                  __half* __restrict__ hi0, __half* __restrict__ lo0,
                                  const float* __restrict__ src1,
                                  __half* __restrict__ hi1, __half* __restrict__ lo1, int M)
{
    const float* src = blockIdx.z ? src1 : src0;
    __half* hi = blockIdx.z ? hi1 : hi0;
    __half* lo = blockIdx.z ? lo1 : lo0;
    const int c  = blockIdx.x;
    const int mb = blockIdx.y;
    const int t  = threadIdx.x;
    const int j  = t & 7;
    char* hbase = (char*)hi + ((size_t)(mb * NCH + c)) * TILE_BYTES;
    char* lbase = (char*)lo + ((size_t)(mb * NCH + c)) * TILE_BYTES;

    #pragma unroll
    for (int g = 0; g < 8; g++) {
        int ml = g * 16 + (t >> 3);
        int m = mb * 128 + ml;
        float x[8];
        if (m < M) {
            float4 a = *(const float4*)(src + (size_t)m * CC + c * 64 + j * 8);
            float4 b = *(const float4*)(src + (size_t)m * CC + c * 64 + j * 8 + 4);
            x[0]=a.x; x[1]=a.y; x[2]=a.z; x[3]=a.w; x[4]=b.x; x[5]=b.y; x[6]=b.z; x[7]=b.w;
        } else {
            #pragma unroll
            for (int i = 0; i < 8; i++) x[i] = 0.0f;
        }
        __half h[8], l[8];
        #pragma unroll
        for (int i = 0; i < 8; i++) {
            h[i] = __float2half(x[i]);
            l[i] = __float2half((x[i] - __half2float(h[i])) * LO_SCALE);
        }
        uint32_t off = SMEM_SWIZZLE_128B((uint32_t)(ml * 128 + j * 16));
        *(uint4*)(hbase + off) = *(uint4*)h;
        *(uint4*)(lbase + off) = *(uint4*)l;
    }
}

__global__ void __launch_bounds__(512)
pack_weights_all(const float* __restrict__ Wq, const float* __restrict__ Wkv,
                 const float* __restrict__ Woff, const float* __restrict__ Wout,
                 __half* __restrict__ wq, __half* __restrict__ wk,
                 __half* __restrict__ wfh, __half* __restrict__ wfl,
                 __half* __restrict__ wo)
{
    __shared__ float ts[64][129];
    const int c = blockIdx.x;
    const int y = blockIdx.y;
    const int t = threadIdx.x;

    const float* W; int ldw, nb; __half *hi, *lo;
    if (y < 8)       { W = Wq;   ldw = CC;     nb = y;      hi = wq;  lo = nullptr; }
    else if (y < 16) { W = Wkv;  ldw = 2 * CC; nb = y - 8;  hi = wk;  lo = nullptr; }
    else if (y < 17) { W = Woff; ldw = 128;    nb = 0;      hi = wfh; lo = wfl; }
    else             { W = Wout; ldw = CC;     nb = y - 17; hi = wo;  lo = nullptr; }

    const int k0 = c * 64;
    const int n0 = nb * 128;
    const int lrow = t >> 7;
    const int lcol = t & 127;
    #pragma unroll
    for (int i = 0; i < 16; i++) {
        int row = i * 4 + lrow;
        ts[row][lcol] = W[(size_t)(k0 + row) * ldw + n0 + lcol];
    }
    __syncthreads();

    char* hbase = (char*)hi + ((size_t)(nb * NCH + c)) * TILE_BYTES;
    char* lbase = lo ? (char*)lo + ((size_t)(nb * NCH + c)) * TILE_BYTES : nullptr;
    #pragma unroll
    for (int it = 0; it < 2; it++) {
        int idx = t + it * 512;
        int nl = idx >> 3;
        int j  = idx & 7;
        __half h[8], l[8];
        #pragma unroll
        for (int jj = 0; jj < 8; jj++) {
            float x = ts[j * 8 + jj][nl];
            h[jj] = __float2half(x);
            l[jj] = __float2half((x - __half2float(h[jj])) * LO_SCALE);
        }
        uint32_t off = SMEM_SWIZZLE_128B((uint32_t)(nl * 128 + j * 16));
        *(uint4*)(hbase + off) = *(uint4*)h;
        if (lbase) *(uint4*)(lbase + off) = *(uint4*)l;
    }
}

// ===== cg1 GEMM, WARP-SPECIALIZED pipeline: thread0 = MMA consumer, thread32 = =====
// ===== copy producer. A hi/lo split -> two accumulators; optional B hi/lo.     =====
// Producer waits on the 3-chunk-older commit, so MMA issue never blocks on its
// own completion (round-7's serialization bug).
template <int NT, int BPARTS, typename TOut>
__global__ void __launch_bounds__(128, 1) __cluster_dims__(1, 2, 1)
gemm_tc(const char* __restrict__ Ah, const char* __restrict__ Al,
        const char* __restrict__ Bh, const char* __restrict__ Bl,
        const float* __restrict__ bias, TOut* __restrict__ C, int M, int Ncols)
{
#if HAS_TCGEN05
    constexpr int NBB = NT / 128;
    constexpr int NBT = BPARTS * NBB;
    constexpr uint32_t SB = (2 + NBT) * TILE_BYTES;
    constexpr uint32_t HDR = 1024;
    constexpr uint32_t IDESC = 0x8000010u | ((NT / 8) << 17);

    extern __shared__ char smem[];
    uint32_t sb = smem_to_u32(smem);
    const int tid = threadIdx.x;
    const int wid = tid >> 5;
    const int lane = tid & 31;
    const int m0 = blockIdx.y * 128;
    const int n0 = blockIdx.x * NT;
    const uint32_t rank = cluster_rank();

    if (wid == 0) TCGEN05_ALLOC(sb + 0, 512);
    if (tid == 0) {
        MBARRIER_INIT(sb + 16, 1);   // full0
        MBARRIER_INIT(sb + 24, 1);   // full1
        MBARRIER_INIT(sb + 32, 1);   // full2
        MBARRIER_INIT(sb + 48, 2);   // empty0 (both ranks' commits)
        MBARRIER_INIT(sb + 56, 2);   // empty1
        MBARRIER_INIT(sb + 64, 2);   // empty2
    }
    __syncthreads();
    CLUSTER_SYNC();
    uint32_t tmem;
    asm volatile("ld.shared.b32 %0, [%1];" : "=r"(tmem) : "r"(sb));

    if (tid == 0) {
        // ---- MMA consumer: never waits on empty in the loop ----
        for (int c = 0; c < NCH; c++) {
            int s = c % 3;
            MBARRIER_WAIT_PARITY(sb + 16 + 8u * s, (uint32_t)((c / 3) & 1));
            uint32_t st = sb + HDR + (uint32_t)s * SB;
            uint64_t ahd = MAKE_SMEM_DESC(st);
            uint64_t ald = MAKE_SMEM_DESC(st + TILE_BYTES);
            uint64_t bhd = MAKE_SMEM_DESC(st + 2 * TILE_BYTES);
            #pragma unroll
            for (int ks = 0; ks < 4; ks++)
                mma_f16_ss(tmem, ahd + ks * 2, bhd + ks * 2, IDESC, !(c == 0 && ks == 0));
            #pragma unroll
            for (int ks = 0; ks < 4; ks++)
                mma_f16_ss(tmem + NT, ald + ks * 2, bhd + ks * 2, IDESC, !(c == 0 && ks == 0));
            if (BPARTS == 2) {
                uint64_t bld = MAKE_SMEM_DESC(st + 3 * TILE_BYTES);
                #pragma unroll
                for (int ks = 0; ks < 4; ks++)
                    mma_f16_ss(tmem + NT, ahd + ks * 2, bld + ks * 2, IDESC, true);
            }
            TCGEN05_COMMIT_MC(sb + 48 + 8u * s, 3);
        }
        // drain: wait for the final commit on each stage before the epilogue
        for (int c = NCH - 3; c < NCH; c++)
            MBARRIER_WAIT_PARITY(sb + 48 + 8u * (c % 3), (uint32_t)((c / 3) & 1));
    } else if (tid == 32) {
        // ---- copy producer ----
        auto issue = [&](int c) {
            int s = c % 3;
            uint32_t fb = sb + 16 + 8u * s;
            uint32_t st = sb + HDR + (uint32_t)s * SB;
            MBARRIER_EXPECT_TX(fb, SB);
            size_t aoff = ((size_t)blockIdx.y * NCH + c) * TILE_BYTES;
            bulk_g2s(st, Ah + aoff, TILE_BYTES, fb);
            bulk_g2s(st + TILE_BYTES, Al + aoff, TILE_BYTES, fb);
            #pragma unroll
            for (int i = 0; i < NBT; i++) {
                const char* src;
                if (BPARTS == 1)
                    src = Bh + ((size_t)(blockIdx.x * NBB + i) * NCH + c) * TILE_BYTES;
                else
                    src = (i == 0 ? Bh : Bl) + ((size_t)(blockIdx.x * NBB) * NCH + c) * TILE_BYTES;
                if ((uint32_t)(i & 1) == rank)
                    bulk_g2s_mc(st + (2 + i) * TILE_BYTES, src, TILE_BYTES, fb, 3);
            }
        };
        issue(0); issue(1); issue(2);
        for (int c = 3; c < NCH; c++) {
            int s = c % 3;
            // wait for chunk c-3's commit (phase (c/3 - 1)) before refilling stage s
            MBARRIER_WAIT_PARITY(sb + 48 + 8u * s, (uint32_t)((c / 3 - 1) & 1));
            issue(c);
        }
    }
    __syncthreads();
    TCGEN05_FENCE_AFTER();

    // Epilogue: combine acc0 + acc1*2^-10, per-warp transpose, coalesced STG.
    float* buf = (float*)(smem + HDR) + wid * (32 * 33);
    #pragma unroll
    for (int base = 0; base < NT; base += 32) {
        uint32_t r0[32], r1[32];
        TCGEN05_LD_32X32B_X32(r0, tmem + base);
        TCGEN05_LD_32X32B_X32(r1, tmem + NT + base);
        TCGEN05_WAIT_LD();
        #pragma unroll
        for (int q = 0; q < 32; q++)
            buf[lane * 33 + q] = __uint_as_float(r0[q]) + __uint_as_float(r1[q]) * LO_INV;
        __syncwarp();
        float bv = bias[n0 + base + lane];
        #pragma unroll 4
        for (int rr = 0; rr < 32; rr++) {
            int gm = m0 + wid * 32 + rr;
            if (gm < M)
                C[(size_t)gm * Ncols + n0 + base + lane] = (TOut)(buf[rr * 33 + lane] + bv);
        }
        __syncwarp();
    }
    TCGEN05_FENCE_BEFORE();
    __syncthreads();
    if (wid == 0) {
        TCGEN05_RELINQUISH_ALLOC_PERMIT();
        TCGEN05_DEALLOC(tmem, 512);
    }
#endif
}

// ============================ Fallback SGEMM ============================
__global__ void sgemm_bias_kernel(const float* __restrict__ A,
                                  const float* __restrict__ Wt,
                                  const float* __restrict__ bias,
                                  float* __restrict__ C,
                                  int M, int Ncols, int K, int ldw)
{
    __shared__ float As[16][64];
    __shared__ float Bs[16][64];
    const int tid = threadIdx.x;
    const int tx = tid & 15;
    const int ty = tid >> 4;
    const int n0 = blockIdx.x * 64;
    const int m0 = blockIdx.y * 64;
    float acc[4][4] = {};
    for (int k0 = 0; k0 < K; k0 += 16) {
        #pragma unroll
        for (int i = 0; i < 4; i++) {
            int idx = tid + i * 256;
            int m  = idx >> 4, kk = idx & 15, gm = m0 + m;
            As[kk][m] = (gm < M) ? A[(size_t)gm * K + (k0 + kk)] : 0.0f;
        }
        #pragma unroll
        for (int i = 0; i < 4; i++) {
            int idx = tid + i * 256;
            int kk = idx >> 6, n = idx & 63, gn = n0 + n;
            Bs[kk][n] = (gn < Ncols) ? Wt[(size_t)(k0 + kk) * ldw + gn] : 0.0f;
        }
        __syncthreads();
        #pragma unroll
        for (int kk = 0; kk < 16; kk++) {
            float4 a = *(const float4*)&As[kk][ty * 4];
            float4 w = *(const float4*)&Bs[kk][tx * 4];
            acc[0][0] += a.x*w.x; acc[0][1] += a.x*w.y; acc[0][2] += a.x*w.z; acc[0][3] += a.x*w.w;
            acc[1][0] += a.y*w.x; acc[1][1] += a.y*w.y; acc[1][2] += a.y*w.z; acc[1][3] += a.y*w.w;
            acc[2][0] += a.z*w.x; acc[2][1] += a.z*w.y; acc[2][2] += a.z*w.z; acc[2][3] += a.z*w.w;
            acc[3][0] += a.w*w.x; acc[3][1] += a.w*w.y; acc[3][2] += a.w*w.z; acc[3][3] += a.w*w.w;
        }
        __syncthreads();
    }
    #pragma unroll
    for (int r = 0; r < 4; r++) {
        int gm = m0 + ty * 4 + r;
        if (gm >= M) continue;
        #pragma unroll
        for (int c = 0; c < 4; c++) {
            int gn = n0 + tx * 4 + c;
            if (gn < Ncols) C[(size_t)gm * Ncols + gn] = acc[r][c] + bias[gn];
        }
    }
}

// ============================ Attention (warp per (bn,h)), fp16 k gathers ============
__global__ void attn_warp_kernel()
{
    const int bn = blockIdx.x;
    const int h  = threadIdx.x >> 5;
    const int lane = threadIdx.x & 31;

    const int b = bn / NPIX;
    const int n = bn % NPIX;
    const int row = n / WSP;
    const int col = n % WSP;
    const float step = 2.0f / 36.0f;
    const float ybase = -1.0f + row * step;
    const float xbase = -1.0f + col * step;

    float4 q4 = *(const float4*)(g_q + (size_t)bn * CC + h * HD + lane * 4);
    const __half* kbase = g_kh + (size_t)b * NPIX * CC + h * HD + lane * 4;

    float offv = 0.0f;
    if (lane < 16) offv = g_off[(size_t)bn * (HEADS * PTS * 2) + h * (PTS * 2) + lane];

    float4 sv[PTS];
    float sc[PTS];
    #pragma unroll
    for (int p = 0; p < PTS; p++) {
        float o0 = __shfl_sync(0xffffffffu, offv, 2 * p);
        float o1 = __shfl_sync(0xffffffffu, offv, 2 * p + 1);
        float xn = ybase + o0;
        float yn = xbase + o1;
        float ix = fminf(fmaxf((xn + 1.0f) * 0.5f * (WSP - 1), 0.0f), (float)(WSP - 1));
        float iy = fminf(fmaxf((yn + 1.0f) * 0.5f * (HSP - 1), 0.0f), (float)(HSP - 1));
        float x0f = floorf(ix), y0f = floorf(iy);
        float wx = ix - x0f, wy = iy - y0f;
        int x0 = (int)x0f, y0 = (int)y0f;
        int x1 = min(x0 + 1, WSP - 1);
        int y1 = min(y0 + 1, HSP - 1);

        uint2 u00 = *(const uint2*)(kbase + (size_t)(y0 * WSP + x0) * CC);
        uint2 u01 = *(const uint2*)(kbase + (size_t)(y0 * WSP + x1) * CC);
        uint2 u10 = *(const uint2*)(kbase + (size_t)(y1 * WSP + x0) * CC);
        uint2 u11 = *(const uint2*)(kbase + (size_t)(y1 * WSP + x1) * CC);
        float2 a00 = __half22float2(*(__half2*)&u00.x), b00 = __half22float2(*(__half2*)&u00.y);
        float2 a01 = __half22float2(*(__half2*)&u01.x), b01 = __half22float2(*(__half2*)&u01.y);
        float2 a10 = __half22float2(*(__half2*)&u10.x), b10 = __half22float2(*(__half2*)&u10.y);
        float2 a11 = __half22float2(*(__half2*)&u11.x), b11 = __half22float2(*(__half2*)&u11.y);

        float w00 = (1.0f - wy) * (1.0f - wx), w01 = (1.0f - wy) * wx;
        float w10 = wy * (1.0f - wx), w11 = wy * wx;
        float4 s;
        s.x = w00*a00.x + w01*a01.x + w10*a10.x + w11*a11.x;
        s.y = w00*a00.y + w01*a01.y + w10*a10.y + w11*a11.y;
        s.z = w00*b00.x + w01*b01.x + w10*b10.x + w11*b11.x;
        s.w = w00*b00.y + w01*b01.y + w10*b10.y + w11*b11.y;
        sv[p] = s;

        float d = q4.x*s.x + q4.y*s.y + q4.z*s.z + q4.w*s.w;
        #pragma unroll
        for (int o = 16; o; o >>= 1) d += __shfl_xor_sync(0xffffffffu, d, o);
        sc[p] = d * 0.088388347648318447f;
    }

    float m = sc[0];
    #pragma unroll
    for (int p = 1; p < PTS; p++) m = fmaxf(m, sc[p]);
    float e[PTS], denom = 0.0f;
    #pragma unroll
    for (int p = 0; p < PTS; p++) { e[p] = expf(sc[p] - m); denom += e[p]; }
    float inv = 1.0f / denom;

    float4 o = make_float4(0, 0, 0, 0);
    #pragma unroll
    for (int p = 0; p < PTS; p++) {
        float w = e[p] * inv;
        o.x += w * sv[p].x; o.y += w * sv[p].y; o.z += w * sv[p].z; o.w += w * sv[p].w;
    }

    int k = h * HD + lane * 4;
    int mb = bn >> 7, ml = bn & 127;
    int c = k >> 6, kl = k & 63;
    size_t tbase = ((size_t)(mb * NCH + c)) * TILE_BYTES;
    uint32_t off = SMEM_SWIZZLE_128B((uint32_t)(ml * 128 + kl * 2));

    __half h4[4], l4[4];
    float ov[4] = {o.x, o.y, o.z, o.w};
    #pragma unroll
    for (int i = 0; i < 4; i++) {
        h4[i] = __float2half(ov[i]);
        l4[i] = __float2half((ov[i] - __half2float(h4[i])) * LO_SCALE);
    }
    *(uint2*)((char*)g_ah + tbase + off) = *(uint2*)h4;
    *(uint2*)((char*)g_al + tbase + off) = *(uint2*)l4;
}

// Fallback attention (fp32 k, fp32 output to g_attn)
__global__ void attn_kernel(float* __restrict__ out)
{
    const int bn = blockIdx.x;
    const int h  = blockIdx.y;
    const int t  = threadIdx.x;
    const int lane = t & 31;
    const int wid  = t >> 5;
    const int b = bn / NPIX;
    const int n = bn % NPIX;
    const int row = n / WSP;
    const int col = n % WSP;
    const float step = 2.0f / 36.0f;
    const float ybase = -1.0f + row * step;
    const float xbase = -1.0f + col * step;
    const float qv = g_q[(size_t)bn * CC + h * HD + t];
    const float* kbase = g_k + (size_t)b * NPIX * CC + h * HD + t;
    const float* offp  = g_off + (size_t)bn * (HEADS * PTS * 2) + h * (PTS * 2);
    float sv[PTS];
    __shared__ float red[PTS][4];
    __shared__ float sc[PTS];
    #pragma unroll
    for (int p = 0; p < PTS; p++) {
        float o0 = offp[p * 2 + 0], o1 = offp[p * 2 + 1];
        float xn = ybase + o0, yn = xbase + o1;
        float ix = fminf(fmaxf((xn + 1.0f) * 0.5f * (WSP - 1), 0.0f), (float)(WSP - 1));
        float iy = fminf(fmaxf((yn + 1.0f) * 0.5f * (HSP - 1), 0.0f), (float)(HSP - 1));
        float x0f = floorf(ix), y0f = floorf(iy);
        float wx = ix - x0f, wy = iy - y0f;
        int x0 = (int)x0f, y0 = (int)y0f;
        int x1 = min(x0 + 1, WSP - 1), y1 = min(y0 + 1, HSP - 1);
        float v00 = kbase[(size_t)(y0 * WSP + x0) * CC];
        float v01 = kbase[(size_t)(y0 * WSP + x1) * CC];
        float v10 = kbase[(size_t)(y1 * WSP + x0) * CC];
        float v11 = kbase[(size_t)(y1 * WSP + x1) * CC];
        float s = (1.0f - wy) * ((1.0f - wx) * v00 + wx * v01)
                +          wy * ((1.0f - wx) * v10 + wx * v11);
        sv[p] = s;
        float d = qv * s;
        #pragma unroll
        for (int o = 16; o; o >>= 1) d += __shfl_down_sync(0xffffffffu, d, o);
        if (lane == 0) red[p][wid] = d;
    }
    __syncthreads();
    if (t < PTS) sc[t] = (red[t][0] + red[t][1] + red[t][2] + red[t][3]) * 0.088388347648318447f;
    __syncthreads();
    float m = sc[0];
    #pragma unroll
    for (int p = 1; p < PTS; p++) m = fmaxf(m, sc[p]);
    float e[PTS], denom = 0.0f;
    #pragma unroll
    for (int p = 0; p < PTS; p++) { e[p] = expf(sc[p] - m); denom += e[p]; }
    float inv = 1.0f / denom;
    float o = 0.0f;
    #pragma unroll
    for (int p = 0; p < PTS; p++) o += e[p] * inv * sv[p];
    out[(size_t)bn * CC + h * HD + t] = o;
}

// ============================ Launch ============================
extern "C" void kernel_launch(void* const* d_in, const int* in_sizes, int n_in,
                              void* d_out, int out_size)
{
    const float* query = (const float*)d_in[0];
    const float* ref   = (const float*)d_in[1];
    const float* Wq    = (const float*)d_in[2];
    const float* bq    = (const float*)d_in[3];
    const float* Wkv   = (const float*)d_in[4];
    const float* bkv   = (const float*)d_in[5];
    const float* Woff  = (const float*)d_in[6];
    const float* boff  = (const float*)d_in[7];
    const float* Wout  = (const float*)d_in[8];
    const float* bout  = (const float*)d_in[9];
    float* out = (float*)d_out;

    float *q_ptr, *k_ptr, *off_ptr, *attn_ptr;
    __half* kh_ptr;
    cudaGetSymbolAddress((void**)&q_ptr,    g_q);
    cudaGetSymbolAddress((void**)&k_ptr,    g_k);
    cudaGetSymbolAddress((void**)&kh_ptr,   g_kh);
    cudaGetSymbolAddress((void**)&off_ptr,  g_off);
    cudaGetSymbolAddress((void**)&attn_ptr, g_attn);

    cudaFuncAttributes fa;
    cudaFuncGetAttributes(&fa, gemm_tc<256, 1, float>);
    bool use_tc = (fa.numRegs > 32);

    if (use_tc) {
        char *qh, *ql, *rh, *rl, *ah, *al;
        char *wq, *wk, *wo, *wfh, *wfl;
        cudaGetSymbolAddress((void**)&qh, g_qh);   cudaGetSymbolAddress((void**)&ql, g_ql);
        cudaGetSymbolAddress((void**)&rh, g_rh);   cudaGetSymbolAddress((void**)&rl, g_rl);
        cudaGetSymbolAddress((void**)&ah, g_ah);   cudaGetSymbolAddress((void**)&al, g_al);
        cudaGetSymbolAddress((void**)&wq, g_Wq);
        cudaGetSymbolAddress((void**)&wk, g_Wk);
        cudaGetSymbolAddress((void**)&wo, g_Wo);
        cudaGetSymbolAddress((void**)&wfh, g_Wf_h); cudaGetSymbolAddress((void**)&wfl, g_Wf_l);

        static bool attr_set = false;
        if (!attr_set) {
            cudaFuncSetAttribute(gemm_tc<256, 1, float>,  cudaFuncAttributeMaxDynamicSharedMemorySize, 197632);
            cudaFuncSetAttribute(gemm_tc<256, 1, __half>, cudaFuncAttributeMaxDynamicSharedMemorySize, 197632);
            cudaFuncSetAttribute(gemm_tc<128, 2, float>,  cudaFuncAttributeMaxDynamicSharedMemorySize, 197632);
            attr_set = true;
        }

        split_act2_kernel<<<dim3(NCH, MBLK, 2), 128>>>(
            query, (__half*)qh, (__half*)ql,
            ref,   (__half*)rh, (__half*)rl, BN);
        pack_weights_all<<<dim3(NCH, 25), 512>>>(
            Wq, Wkv, Woff, Wout,
            (__half*)wq, (__half*)wk, (__half*)wfh, (__half*)wfl, (__half*)wo);

        gemm_tc<256, 1, float ><<<dim3(4, MBLK), 128, 197632>>>(qh, ql, wq, nullptr, bq,   q_ptr,   BN, CC);
        gemm_tc<256, 1, __half><<<dim3(4, MBLK), 128, 197632>>>(rh, rl, wk, nullptr, bkv,  kh_ptr,  BN, CC);
        gemm_tc<128, 2, float ><<<dim3(1, MBLK), 128, 197632>>>(qh, ql, wfh, wfl,    boff, off_ptr, BN, 128);

        attn_warp_kernel<<<BN, 256>>>();

        gemm_tc<256, 1, float><<<dim3(4, MBLK), 128, 197632>>>(ah, al, wo, nullptr, bout, out, BN, CC);
    } else {
        dim3 blk(256);
        dim3 gBig((CC + 63) / 64, (BN + 63) / 64);
        dim3 gOff((128 + 63) / 64, (BN + 63) / 64);
        sgemm_bias_kernel<<<gBig, blk>>>(query, Wq, bq, q_ptr, BN, CC, CC, CC);
        sgemm_bias_kernel<<<gBig, blk>>>(ref, Wkv, bkv, k_ptr, BN, CC, CC, 2 * CC);
        sgemm_bias_kernel<<<gOff, blk>>>(query, Woff, boff, off_ptr, BN, HEADS * PTS * 2, CC, HEADS * PTS * 2);
        attn_kernel<<<dim3(BN, HEADS), 128>>>(attn_ptr);
        sgemm_bias_kernel<<<gBig, blk>>>(attn_ptr, Wout, bout, out, BN, CC, CC, CC);
    }
}

// round 13
// speedup vs baseline: 1.4059x; 1.0702x over previous
#include <cuda_runtime.h>
#include <cuda_bf16.h>
#include <cuda_fp16.h>
#include <cstdint>
#include <math.h>

#define NB   8
#define HSP  37
#define WSP  37
#define NPIX 1369
#define BN   10952
#define CC   1024
#define HEADS 8
#define HD   128
#define PTS  8
#define MBLK 86
#define MPAD (MBLK * 128)   // 11008
#define NCH  16             // K chunks of 64
#define TILE_BYTES 16384    // 128 rows x 128B
#define LO_SCALE 1024.0f
#define LO_INV   0.0009765625f

#if defined(__CUDA_ARCH__) && (defined(__CUDA_ARCH_FEAT_SM103_ALL) || defined(__CUDA_ARCH_FEAT_SM100_ALL) || defined(__CUDA_ARCH_SPECIFIC__))
#define HAS_TCGEN05 1
#else
#define HAS_TCGEN05 0
#endif

#define SMEM_SWIZZLE_128B(byte_offset) ((byte_offset) ^ (((byte_offset) >> 3) & 0x70))

// ============================ Scratch ============================
__device__ float g_q[BN * CC];
__device__ float g_k[BN * CC];          // fallback path only
__device__ __half g_kh[BN * CC];        // tc path: k in fp16 for the gather
__device__ float g_off[BN * HEADS * PTS * 2];
__device__ float g_attn[BN * CC];

// Blocked+swizzled fp16 operands (16KB tiles, tile (r,c) at ((r*NCH)+c)*16KB)
__device__ __half g_qh[MPAD * CC];
__device__ __half g_ql[MPAD * CC];
__device__ __half g_rh[MPAD * CC];
__device__ __half g_rl[MPAD * CC];
__device__ __half g_ah[MPAD * CC];
__device__ __half g_al[MPAD * CC];
__device__ __half g_Wq[CC * CC];
__device__ __half g_Wk[CC * CC];
__device__ __half g_Wo[CC * CC];
__device__ __half g_Wf_h[128 * CC];
__device__ __half g_Wf_l[128 * CC];

// ============================ tcgen05 helpers (guarded) ============================
#if HAS_TCGEN05
__device__ __forceinline__ uint32_t smem_to_u32(const void* p) {
    uint32_t a;
    asm("{ .reg .u64 t; cvta.to.shared.u64 t, %1; cvt.u32.u64 %0, t; }" : "=r"(a) : "l"(p));
    return a;
}
#define TCGEN05_ALLOC(smem_result_addr, nCols) \
    asm volatile("tcgen05.alloc.cta_group::1.sync.aligned.shared::cta.b32 [%0], %1;" \
        :: "r"((uint32_t)(smem_result_addr)), "r"((uint32_t)(nCols)) : "memory")
#define TCGEN05_DEALLOC(tmem_addr, nCols) \
    asm volatile("tcgen05.dealloc.cta_group::1.sync.aligned.b32 %0, %1;" :: "r"(tmem_addr), "r"(nCols))
#define TCGEN05_RELINQUISH_ALLOC_PERMIT() \
    asm volatile("tcgen05.relinquish_alloc_permit.cta_group::1.sync.aligned;")
#define TCGEN05_COMMIT(mbar_smem_addr) \
    asm volatile("tcgen05.commit.cta_group::1.mbarrier::arrive::one.shared::cluster.b64 [%0];" \
        :: "r"((uint32_t)(mbar_smem_addr)) : "memory")
#define TCGEN05_WAIT_LD() asm volatile("tcgen05.wait::ld.sync.aligned;" ::: "memory")
#define TCGEN05_FENCE_AFTER() asm volatile("tcgen05.fence::after_thread_sync;" ::: "memory")
#define TCGEN05_FENCE_BEFORE() asm volatile("tcgen05.fence::before_thread_sync;" ::: "memory")
#define MBARRIER_INIT(mbar_smem_addr, count) \
    asm volatile("mbarrier.init.shared.b64 [%0], %1;" \
        :: "r"((uint32_t)(mbar_smem_addr)), "r"((uint32_t)(count)) : "memory")
#define MBARRIER_EXPECT_TX(mbar_smem_addr, tx_bytes) \
    asm volatile("mbarrier.arrive.expect_tx.shared.b64 _, [%0], %1;" \
        :: "r"((uint32_t)(mbar_smem_addr)), "r"((uint32_t)(tx_bytes)) : "memory")
#define MBARRIER_WAIT_PARITY(mbar_smem_addr, phase_parity) do { \
    uint32_t _mbar = (uint32_t)(mbar_smem_addr); \
    uint32_t _parity = (uint32_t)(phase_parity); \
    uint32_t _done; \
    asm volatile("{\n\t.reg .pred p;\n\t" \
        "mbarrier.try_wait.parity.acquire.cta.shared::cta.b64 p, [%1], %2;\n\t" \
        "selp.b32 %0, 1, 0, p;\n\t}" : "=r"(_done) : "r"(_mbar), "r"(_parity) : "memory"); \
    if (!_done) { \
        asm volatile("{\n\t.reg .pred P1;\n\t" \
            "WAIT_LOOP_%=:\n\t" \
            "mbarrier.try_wait.parity.acquire.cta.shared::cta.b64 P1, [%0], %1, 0x989680;\n\t" \
            "@P1 bra.uni WAIT_DONE_%=;\n\t" \
            "bra.uni WAIT_LOOP_%=;\n\t" \
            "WAIT_DONE_%=:\n\t}" :: "r"(_mbar), "r"(_parity) : "memory"); \
    } \
} while(0)
#define TCGEN05_LD_32X32B_X32(r, tmem_addr) \
    asm volatile("tcgen05.ld.sync.aligned.32x32b.x32.b32 " \
        "{%0, %1, %2, %3, %4, %5, %6, %7, %8, %9, %10, %11, %12, %13, %14, %15, " \
        " %16, %17, %18, %19, %20, %21, %22, %23, %24, %25, %26, %27, %28, %29, %30, %31}, [%32];" \
        : "=r"((r)[0]),  "=r"((r)[1]),  "=r"((r)[2]),  "=r"((r)[3]), \
          "=r"((r)[4]),  "=r"((r)[5]),  "=r"((r)[6]),  "=r"((r)[7]), \
          "=r"((r)[8]),  "=r"((r)[9]),  "=r"((r)[10]), "=r"((r)[11]), \
          "=r"((r)[12]), "=r"((r)[13]), "=r"((r)[14]), "=r"((r)[15]), \
          "=r"((r)[16]), "=r"((r)[17]), "=r"((r)[18]), "=r"((r)[19]), \
          "=r"((r)[20]), "=r"((r)[21]), "=r"((r)[22]), "=r"((r)[23]), \
          "=r"((r)[24]), "=r"((r)[25]), "=r"((r)[26]), "=r"((r)[27]), \
          "=r"((r)[28]), "=r"((r)[29]), "=r"((r)[30]), "=r"((r)[31]) \
        : "r"(tmem_addr))

static constexpr uint64_t SMEM_DESC_BASE_SW128 =
    (uint64_t(2)  << 61) | (uint64_t(1) << 46) | (uint64_t(64) << 32) | (uint64_t(1) << 16);
#define MAKE_SMEM_DESC(base_addr) (SMEM_DESC_BASE_SW128 | ((uint64_t)((base_addr) >> 4) & 0x3FFF))

__device__ __forceinline__ void mma_f16_ss(uint32_t d, uint64_t ad, uint64_t bd,
                                           uint32_t idesc, bool en) {
    uint32_t e = en ? 1u : 0u;
    asm volatile(
        "{\n\t.reg .pred p;\n\tsetp.ne.u32 p, %5, 0;\n\t"
        "tcgen05.mma.cta_group::1.kind::f16 [%0], %1, %2, %3, {%4, %4, %4, %4}, p;\n\t}"
        :: "r"(d), "l"(ad), "l"(bd), "r"(idesc), "r"(0u), "r"(e) : "memory");
}
__device__ __forceinline__ void bulk_g2s(uint32_t dst, const void* src, uint32_t bytes, uint32_t mbar) {
    asm volatile("cp.async.bulk.shared::cluster.global.mbarrier::complete_tx::bytes [%0], [%1], %2, [%3];"
        :: "r"(dst), "l"(src), "r"(bytes), "r"(mbar) : "memory");
}
#endif  // HAS_TCGEN05

// ============================ Pack kernels ============================
__global__ void split_act2_kernel(const float* __restrict__ src0,
                                  __half* __restrict__ hi0, __half* __restrict__ lo0,
                                  const float* __restrict__ src1,
                                  __half* __restrict__ hi1, __half* __restrict__ lo1, int M)
{
    const float* src = blockIdx.z ? src1 : src0;
    __half* hi = blockIdx.z ? hi1 : hi0;
    __half* lo = blockIdx.z ? lo1 : lo0;
    const int c  = blockIdx.x;
    const int mb = blockIdx.y;
    const int t  = threadIdx.x;
    const int j  = t & 7;
    char* hbase = (char*)hi + ((size_t)(mb * NCH + c)) * TILE_BYTES;
    char* lbase = (char*)lo + ((size_t)(mb * NCH + c)) * TILE_BYTES;

    #pragma unroll
    for (int g = 0; g < 8; g++) {
        int ml = g * 16 + (t >> 3);
        int m = mb * 128 + ml;
        float x[8];
        if (m < M) {
            float4 a = *(const float4*)(src + (size_t)m * CC + c * 64 + j * 8);
            float4 b = *(const float4*)(src + (size_t)m * CC + c * 64 + j * 8 + 4);
            x[0]=a.x; x[1]=a.y; x[2]=a.z; x[3]=a.w; x[4]=b.x; x[5]=b.y; x[6]=b.z; x[7]=b.w;
        } else {
            #pragma unroll
            for (int i = 0; i < 8; i++) x[i] = 0.0f;
        }
        __half h[8], l[8];
        #pragma unroll
        for (int i = 0; i < 8; i++) {
            h[i] = __float2half(x[i]);
            l[i] = __float2half((x[i] - __half2float(h[i])) * LO_SCALE);
        }
        uint32_t off = SMEM_SWIZZLE_128B((uint32_t)(ml * 128 + j * 16));
        *(uint4*)(hbase + off) = *(uint4*)h;
        *(uint4*)(lbase + off) = *(uint4*)l;
    }
}

__global__ void __launch_bounds__(512)
pack_weights_all(const float* __restrict__ Wq, const float* __restrict__ Wkv,
                 const float* __restrict__ Woff, const float* __restrict__ Wout,
                 __half* __restrict__ wq, __half* __restrict__ wk,
                 __half* __restrict__ wfh, __half* __restrict__ wfl,
                 __half* __restrict__ wo)
{
    __shared__ float ts[64][129];
    const int c = blockIdx.x;
    const int y = blockIdx.y;
    const int t = threadIdx.x;

    const float* W; int ldw, nb; __half *hi, *lo;
    if (y < 8)       { W = Wq;   ldw = CC;     nb = y;      hi = wq;  lo = nullptr; }
    else if (y < 16) { W = Wkv;  ldw = 2 * CC; nb = y - 8;  hi = wk;  lo = nullptr; }
    else if (y < 17) { W = Woff; ldw = 128;    nb = 0;      hi = wfh; lo = wfl; }
    else             { W = Wout; ldw = CC;     nb = y - 17; hi = wo;  lo = nullptr; }

    const int k0 = c * 64;
    const int n0 = nb * 128;
    const int lrow = t >> 7;
    const int lcol = t & 127;
    #pragma unroll
    for (int i = 0; i < 16; i++) {
        int row = i * 4 + lrow;
        ts[row][lcol] = W[(size_t)(k0 + row) * ldw + n0 + lcol];
    }
    __syncthreads();

    char* hbase = (char*)hi + ((size_t)(nb * NCH + c)) * TILE_BYTES;
    char* lbase = lo ? (char*)lo + ((size_t)(nb * NCH + c)) * TILE_BYTES : nullptr;
    #pragma unroll
    for (int it = 0; it < 2; it++) {
        int idx = t + it * 512;
        int nl = idx >> 3;
        int j  = idx & 7;
        __half h[8], l[8];
        #pragma unroll
        for (int jj = 0; jj < 8; jj++) {
            float x = ts[j * 8 + jj][nl];
            h[jj] = __float2half(x);
            l[jj] = __float2half((x - __half2float(h[jj])) * LO_SCALE);
        }
        uint32_t off = SMEM_SWIZZLE_128B((uint32_t)(nl * 128 + j * 16));
        *(uint4*)(hbase + off) = *(uint4*)h;
        if (lbase) *(uint4*)(lbase + off) = *(uint4*)l;
    }
}

// ===== FUSED q+k GEMM: grid (4, 172). y<86 -> q (float out), y>=86 -> k (half out). ===
// Warp-specialized: thread0 = MMA consumer, thread32 = copy producer. No cluster.
__global__ void __launch_bounds__(128, 1)
gemm_qk(const char* __restrict__ QAh, const char* __restrict__ QAl,
        const char* __restrict__ RAh, const char* __restrict__ RAl,
        const char* __restrict__ WqB, const char* __restrict__ WkB,
        const float* __restrict__ bq, const float* __restrict__ bkv,
        float* __restrict__ outQ, __half* __restrict__ outK)
{
#if HAS_TCGEN05
    constexpr int NT = 256;
    constexpr uint32_t SB = 4 * TILE_BYTES;   // A hi + A lo + 2 B tiles
    constexpr uint32_t HDR = 1024;
    constexpr uint32_t IDESC = 0x8000010u | ((NT / 8) << 17);

    extern __shared__ char smem[];
    uint32_t sb = smem_to_u32(smem);
    const int tid = threadIdx.x;
    const int wid = tid >> 5;
    const int lane = tid & 31;
    const bool isK = (blockIdx.y >= MBLK);
    const int my  = isK ? (blockIdx.y - MBLK) : blockIdx.y;
    const int m0 = my * 128;
    const int n0 = blockIdx.x * NT;
    const char* Ah = isK ? RAh : QAh;
    const char* Al = isK ? RAl : QAl;
    const char* B  = isK ? WkB : WqB;
    const float* bias = isK ? bkv : bq;

    if (wid == 0) TCGEN05_ALLOC(sb + 0, 512);
    if (tid == 0) {
        MBARRIER_INIT(sb + 16, 1);   // full0
        MBARRIER_INIT(sb + 24, 1);   // full1
        MBARRIER_INIT(sb + 32, 1);   // full2
        MBARRIER_INIT(sb + 48, 1);   // empty0
        MBARRIER_INIT(sb + 56, 1);   // empty1
        MBARRIER_INIT(sb + 64, 1);   // empty2
    }
    __syncthreads();
    uint32_t tmem;
    asm volatile("ld.shared.b32 %0, [%1];" : "=r"(tmem) : "r"(sb));

    if (tid == 0) {
        for (int c = 0; c < NCH; c++) {
            int s = c % 3;
            MBARRIER_WAIT_PARITY(sb + 16 + 8u * s, (uint32_t)((c / 3) & 1));
            uint32_t st = sb + HDR + (uint32_t)s * SB;
            uint64_t ahd = MAKE_SMEM_DESC(st);
            uint64_t ald = MAKE_SMEM_DESC(st + TILE_BYTES);
            uint64_t bhd = MAKE_SMEM_DESC(st + 2 * TILE_BYTES);
            #pragma unroll
            for (int ks = 0; ks < 4; ks++)
                mma_f16_ss(tmem, ahd + ks * 2, bhd + ks * 2, IDESC, !(c == 0 && ks == 0));
            #pragma unroll
            for (int ks = 0; ks < 4; ks++)
                mma_f16_ss(tmem + NT, ald + ks * 2, bhd + ks * 2, IDESC, !(c == 0 && ks == 0));
            TCGEN05_COMMIT(sb + 48 + 8u * s);
        }
        for (int c = NCH - 3; c < NCH; c++)
            MBARRIER_WAIT_PARITY(sb + 48 + 8u * (c % 3), (uint32_t)((c / 3) & 1));
    } else if (tid == 32) {
        auto issue = [&](int c) {
            int s = c % 3;
            uint32_t fb = sb + 16 + 8u * s;
            uint32_t st = sb + HDR + (uint32_t)s * SB;
            MBARRIER_EXPECT_TX(fb, SB);
            size_t aoff = ((size_t)my * NCH + c) * TILE_BYTES;
            bulk_g2s(st, Ah + aoff, TILE_BYTES, fb);
            bulk_g2s(st + TILE_BYTES, Al + aoff, TILE_BYTES, fb);
            #pragma unroll
            for (int i = 0; i < 2; i++)
                bulk_g2s(st + (2 + i) * TILE_BYTES,
                         B + ((size_t)(blockIdx.x * 2 + i) * NCH + c) * TILE_BYTES,
                         TILE_BYTES, fb);
        };
        issue(0); issue(1); issue(2);
        for (int c = 3; c < NCH; c++) {
            int s = c % 3;
            MBARRIER_WAIT_PARITY(sb + 48 + 8u * s, (uint32_t)((c / 3 - 1) & 1));
            issue(c);
        }
    }
    __syncthreads();
    TCGEN05_FENCE_AFTER();

    float* buf = (float*)(smem + HDR) + wid * (32 * 33);
    #pragma unroll
    for (int base = 0; base < NT; base += 32) {
        uint32_t r0[32], r1[32];
        TCGEN05_LD_32X32B_X32(r0, tmem + base);
        TCGEN05_LD_32X32B_X32(r1, tmem + NT + base);
        TCGEN05_WAIT_LD();
        #pragma unroll
        for (int q = 0; q < 32; q++)
            buf[lane * 33 + q] = __uint_as_float(r0[q]) + __uint_as_float(r1[q]) * LO_INV;
        __syncwarp();
        float bv = bias[n0 + base + lane];
        if (isK) {
            #pragma unroll 4
            for (int rr = 0; rr < 32; rr++) {
                int gm = m0 + wid * 32 + rr;
                if (gm < BN)
                    outK[(size_t)gm * CC + n0 + base + lane] = __float2half(buf[rr * 33 + lane] + bv);
            }
        } else {
            #pragma unroll 4
            for (int rr = 0; rr < 32; rr++) {
                int gm = m0 + wid * 32 + rr;
                if (gm < BN)
                    outQ[(size_t)gm * CC + n0 + base + lane] = buf[rr * 33 + lane] + bv;
            }
        }
        __syncwarp();
    }
    TCGEN05_FENCE_BEFORE();
    __syncthreads();
    if (wid == 0) {
        TCGEN05_RELINQUISH_ALLOC_PERMIT();
        TCGEN05_DEALLOC(tmem, 512);
    }
#endif
}

// ===== cg1 GEMM (off + out): warp-specialized, no cluster =====
template <int NT, int BPARTS, typename TOut>
__global__ void __launch_bounds__(128, 1)
gemm_tc(const char* __restrict__ Ah, const char* __restrict__ Al,
        const char* __restrict__ Bh, const char* __restrict__ Bl,
        const float* __restrict__ bias, TOut* __restrict__ C, int M, int Ncols)
{
#if HAS_TCGEN05
    constexpr int NBB = NT / 128;
    constexpr int NBT = BPARTS * NBB;
    constexpr uint32_t SB = (2 + NBT) * TILE_BYTES;
    constexpr uint32_t HDR = 1024;
    constexpr uint32_t IDESC = 0x8000010u | ((NT / 8) << 17);

    extern __shared__ char smem[];
    uint32_t sb = smem_to_u32(smem);
    const int tid = threadIdx.x;
    const int wid = tid >> 5;
    const int lane = tid & 31;
    const int m0 = blockIdx.y * 128;
    const int n0 = blockIdx.x * NT;

    if (wid == 0) TCGEN05_ALLOC(sb + 0, 512);
    if (tid == 0) {
        MBARRIER_INIT(sb + 16, 1);
        MBARRIER_INIT(sb + 24, 1);
        MBARRIER_INIT(sb + 32, 1);
        MBARRIER_INIT(sb + 48, 1);
        MBARRIER_INIT(sb + 56, 1);
        MBARRIER_INIT(sb + 64, 1);
    }
    __syncthreads();
    uint32_t tmem;
    asm volatile("ld.shared.b32 %0, [%1];" : "=r"(tmem) : "r"(sb));

    if (tid == 0) {
        for (int c = 0; c < NCH; c++) {
            int s = c % 3;
            MBARRIER_WAIT_PARITY(sb + 16 + 8u * s, (uint32_t)((c / 3) & 1));
            uint32_t st = sb + HDR + (uint32_t)s * SB;
            uint64_t ahd = MAKE_SMEM_DESC(st);
            uint64_t ald = MAKE_SMEM_DESC(st + TILE_BYTES);
            uint64_t bhd = MAKE_SMEM_DESC(st + 2 * TILE_BYTES);
            #pragma unroll
            for (int ks = 0; ks < 4; ks++)
                mma_f16_ss(tmem, ahd + ks * 2, bhd + ks * 2, IDESC, !(c == 0 && ks == 0));
            #pragma unroll
            for (int ks = 0; ks < 4; ks++)
                mma_f16_ss(tmem + NT, ald + ks * 2, bhd + ks * 2, IDESC, !(c == 0 && ks == 0));
            if (BPARTS == 2) {
                uint64_t bld = MAKE_SMEM_DESC(st + 3 * TILE_BYTES);
                #pragma unroll
                for (int ks = 0; ks < 4; ks++)
                    mma_f16_ss(tmem + NT, ahd + ks * 2, bld + ks * 2, IDESC, true);
            }
            TCGEN05_COMMIT(sb + 48 + 8u * s);
        }
        for (int c = NCH - 3; c < NCH; c++)
            MBARRIER_WAIT_PARITY(sb + 48 + 8u * (c % 3), (uint32_t)((c / 3) & 1));
    } else if (tid == 32) {
        auto issue = [&](int c) {
            int s = c % 3;
            uint32_t fb = sb + 16 + 8u * s;
            uint32_t st = sb + HDR + (uint32_t)s * SB;
            MBARRIER_EXPECT_TX(fb, SB);
            size_t aoff = ((size_t)blockIdx.y * NCH + c) * TILE_BYTES;
            bulk_g2s(st, Ah + aoff, TILE_BYTES, fb);
            bulk_g2s(st + TILE_BYTES, Al + aoff, TILE_BYTES, fb);
            #pragma unroll
            for (int i = 0; i < NBT; i++) {
                const char* src;
                if (BPARTS == 1)
                    src = Bh + ((size_t)(blockIdx.x * NBB + i) * NCH + c) * TILE_BYTES;
                else
                    src = (i == 0 ? Bh : Bl) + ((size_t)(blockIdx.x * NBB) * NCH + c) * TILE_BYTES;
                bulk_g2s(st + (2 + i) * TILE_BYTES, src, TILE_BYTES, fb);
            }
        };
        issue(0); issue(1); issue(2);
        for (int c = 3; c < NCH; c++) {
            int s = c % 3;
            MBARRIER_WAIT_PARITY(sb + 48 + 8u * s, (uint32_t)((c / 3 - 1) & 1));
            issue(c);
        }
    }
    __syncthreads();
    TCGEN05_FENCE_AFTER();

    float* buf = (float*)(smem + HDR) + wid * (32 * 33);
    #pragma unroll
    for (int base = 0; base < NT; base += 32) {
        uint32_t r0[32], r1[32];
        TCGEN05_LD_32X32B_X32(r0, tmem + base);
        TCGEN05_LD_32X32B_X32(r1, tmem + NT + base);
        TCGEN05_WAIT_LD();
        #pragma unroll
        for (int q = 0; q < 32; q++)
            buf[lane * 33 + q] = __uint_as_float(r0[q]) + __uint_as_float(r1[q]) * LO_INV;
        __syncwarp();
        float bv = bias[n0 + base + lane];
        #pragma unroll 4
        for (int rr = 0; rr < 32; rr++) {
            int gm = m0 + wid * 32 + rr;
            if (gm < M)
                C[(size_t)gm * Ncols + n0 + base + lane] = (TOut)(buf[rr * 33 + lane] + bv);
        }
        __syncwarp();
    }
    TCGEN05_FENCE_BEFORE();
    __syncthreads();
    if (wid == 0) {
        TCGEN05_RELINQUISH_ALLOC_PERMIT();
        TCGEN05_DEALLOC(tmem, 512);
    }
#endif
}

// ============================ Fallback SGEMM ============================
__global__ void sgemm_bias_kernel(const float* __restrict__ A,
                                  const float* __restrict__ Wt,
                                  const float* __restrict__ bias,
                                  float* __restrict__ C,
                                  int M, int Ncols, int K, int ldw)
{
    __shared__ float As[16][64];
    __shared__ float Bs[16][64];
    const int tid = threadIdx.x;
    const int tx = tid & 15;
    const int ty = tid >> 4;
    const int n0 = blockIdx.x * 64;
    const int m0 = blockIdx.y * 64;
    float acc[4][4] = {};
    for (int k0 = 0; k0 < K; k0 += 16) {
        #pragma unroll
        for (int i = 0; i < 4; i++) {
            int idx = tid + i * 256;
            int m  = idx >> 4, kk = idx & 15, gm = m0 + m;
            As[kk][m] = (gm < M) ? A[(size_t)gm * K + (k0 + kk)] : 0.0f;
        }
        #pragma unroll
        for (int i = 0; i < 4; i++) {
            int idx = tid + i * 256;
            int kk = idx >> 6, n = idx & 63, gn = n0 + n;
            Bs[kk][n] = (gn < Ncols) ? Wt[(size_t)(k0 + kk) * ldw + gn] : 0.0f;
        }
        __syncthreads();
        #pragma unroll
        for (int kk = 0; kk < 16; kk++) {
            float4 a = *(const float4*)&As[kk][ty * 4];
            float4 w = *(const float4*)&Bs[kk][tx * 4];
            acc[0][0] += a.x*w.x; acc[0][1] += a.x*w.y; acc[0][2] += a.x*w.z; acc[0][3] += a.x*w.w;
            acc[1][0] += a.y*w.x; acc[1][1] += a.y*w.y; acc[1][2] += a.y*w.z; acc[1][3] += a.y*w.w;
            acc[2][0] += a.z*w.x; acc[2][1] += a.z*w.y; acc[2][2] += a.z*w.z; acc[2][3] += a.z*w.w;
            acc[3][0] += a.w*w.x; acc[3][1] += a.w*w.y; acc[3][2] += a.w*w.z; acc[3][3] += a.w*w.w;
        }
        __syncthreads();
    }
    #pragma unroll
    for (int r = 0; r < 4; r++) {
        int gm = m0 + ty * 4 + r;
        if (gm >= M) continue;
        #pragma unroll
        for (int c = 0; c < 4; c++) {
            int gn = n0 + tx * 4 + c;
            if (gn < Ncols) C[(size_t)gm * Ncols + gn] = acc[r][c] + bias[gn];
        }
    }
}

// ============================ Attention (warp per (bn,h)), fp16 k gathers ============
__global__ void attn_warp_kernel()
{
    const int bn = blockIdx.x;
    const int h  = threadIdx.x >> 5;
    const int lane = threadIdx.x & 31;

    const int b = bn / NPIX;
    const int n = bn % NPIX;
    const int row = n / WSP;
    const int col = n % WSP;
    const float step = 2.0f / 36.0f;
    const float ybase = -1.0f + row * step;
    const float xbase = -1.0f + col * step;

    float4 q4 = *(const float4*)(g_q + (size_t)bn * CC + h * HD + lane * 4);
    const __half* kbase = g_kh + (size_t)b * NPIX * CC + h * HD + lane * 4;

    float offv = 0.0f;
    if (lane < 16) offv = g_off[(size_t)bn * (HEADS * PTS * 2) + h * (PTS * 2) + lane];

    float4 sv[PTS];
    float sc[PTS];
    #pragma unroll
    for (int p = 0; p < PTS; p++) {
        float o0 = __shfl_sync(0xffffffffu, offv, 2 * p);
        float o1 = __shfl_sync(0xffffffffu, offv, 2 * p + 1);
        float xn = ybase + o0;
        float yn = xbase + o1;
        float ix = fminf(fmaxf((xn + 1.0f) * 0.5f * (WSP - 1), 0.0f), (float)(WSP - 1));
        float iy = fminf(fmaxf((yn + 1.0f) * 0.5f * (HSP - 1), 0.0f), (float)(HSP - 1));
        float x0f = floorf(ix), y0f = floorf(iy);
        float wx = ix - x0f, wy = iy - y0f;
        int x0 = (int)x0f, y0 = (int)y0f;
        int x1 = min(x0 + 1, WSP - 1);
        int y1 = min(y0 + 1, HSP - 1);

        uint2 u00 = *(const uint2*)(kbase + (size_t)(y0 * WSP + x0) * CC);
        uint2 u01 = *(const uint2*)(kbase + (size_t)(y0 * WSP + x1) * CC);
        uint2 u10 = *(const uint2*)(kbase + (size_t)(y1 * WSP + x0) * CC);
        uint2 u11 = *(const uint2*)(kbase + (size_t)(y1 * WSP + x1) * CC);
        float2 a00 = __half22float2(*(__half2*)&u00.x), b00 = __half22float2(*(__half2*)&u00.y);
        float2 a01 = __half22float2(*(__half2*)&u01.x), b01 = __half22float2(*(__half2*)&u01.y);
        float2 a10 = __half22float2(*(__half2*)&u10.x), b10 = __half22float2(*(__half2*)&u10.y);
        float2 a11 = __half22float2(*(__half2*)&u11.x), b11 = __half22float2(*(__half2*)&u11.y);

        float w00 = (1.0f - wy) * (1.0f - wx), w01 = (1.0f - wy) * wx;
        float w10 = wy * (1.0f - wx), w11 = wy * wx;
        float4 s;
        s.x = w00*a00.x + w01*a01.x + w10*a10.x + w11*a11.x;
        s.y = w00*a00.y + w01*a01.y + w10*a10.y + w11*a11.y;
        s.z = w00*b00.x + w01*b01.x + w10*b10.x + w11*b11.x;
        s.w = w00*b00.y + w01*b01.y + w10*b10.y + w11*b11.y;
        sv[p] = s;

        float d = q4.x*s.x + q4.y*s.y + q4.z*s.z + q4.w*s.w;
        #pragma unroll
        for (int o = 16; o; o >>= 1) d += __shfl_xor_sync(0xffffffffu, d, o);
        sc[p] = d * 0.088388347648318447f;
    }

    float m = sc[0];
    #pragma unroll
    for (int p = 1; p < PTS; p++) m = fmaxf(m, sc[p]);
    float e[PTS], denom = 0.0f;
    #pragma unroll
    for (int p = 0; p < PTS; p++) { e[p] = expf(sc[p] - m); denom += e[p]; }
    float inv = 1.0f / denom;

    float4 o = make_float4(0, 0, 0, 0);
    #pragma unroll
    for (int p = 0; p < PTS; p++) {
        float w = e[p] * inv;
        o.x += w * sv[p].x; o.y += w * sv[p].y; o.z += w * sv[p].z; o.w += w * sv[p].w;
    }

    int k = h * HD + lane * 4;
    int mb = bn >> 7, ml = bn & 127;
    int c = k >> 6, kl = k & 63;
    size_t tbase = ((size_t)(mb * NCH + c)) * TILE_BYTES;
    uint32_t off = SMEM_SWIZZLE_128B((uint32_t)(ml * 128 + kl * 2));

    __half h4[4], l4[4];
    float ov[4] = {o.x, o.y, o.z, o.w};
    #pragma unroll
    for (int i = 0; i < 4; i++) {
        h4[i] = __float2half(ov[i]);
        l4[i] = __float2half((ov[i] - __half2float(h4[i])) * LO_SCALE);
    }
    *(uint2*)((char*)g_ah + tbase + off) = *(uint2*)h4;
    *(uint2*)((char*)g_al + tbase + off) = *(uint2*)l4;
}

// Fallback attention (fp32 k, fp32 output to g_attn)
__global__ void attn_kernel(float* __restrict__ out)
{
    const int bn = blockIdx.x;
    const int h  = blockIdx.y;
    const int t  = threadIdx.x;
    const int lane = t & 31;
    const int wid  = t >> 5;
    const int b = bn / NPIX;
    const int n = bn % NPIX;
    const int row = n / WSP;
    const int col = n % WSP;
    const float step = 2.0f / 36.0f;
    const float ybase = -1.0f + row * step;
    const float xbase = -1.0f + col * step;
    const float qv = g_q[(size_t)bn * CC + h * HD + t];
    const float* kbase = g_k + (size_t)b * NPIX * CC + h * HD + t;
    const float* offp  = g_off + (size_t)bn * (HEADS * PTS * 2) + h * (PTS * 2);
    float sv[PTS];
    __shared__ float red[PTS][4];
    __shared__ float sc[PTS];
    #pragma unroll
    for (int p = 0; p < PTS; p++) {
        float o0 = offp[p * 2 + 0], o1 = offp[p * 2 + 1];
        float xn = ybase + o0, yn = xbase + o1;
        float ix = fminf(fmaxf((xn + 1.0f) * 0.5f * (WSP - 1), 0.0f), (float)(WSP - 1));
        float iy = fminf(fmaxf((yn + 1.0f) * 0.5f * (HSP - 1), 0.0f), (float)(HSP - 1));
        float x0f = floorf(ix), y0f = floorf(iy);
        float wx = ix - x0f, wy = iy - y0f;
        int x0 = (int)x0f, y0 = (int)y0f;
        int x1 = min(x0 + 1, WSP - 1), y1 = min(y0 + 1, HSP - 1);
        float v00 = kbase[(size_t)(y0 * WSP + x0) * CC];
        float v01 = kbase[(size_t)(y0 * WSP + x1) * CC];
        float v10 = kbase[(size_t)(y1 * WSP + x0) * CC];
        float v11 = kbase[(size_t)(y1 * WSP + x1) * CC];
        float s = (1.0f - wy) * ((1.0f - wx) * v00 + wx * v01)
                +          wy * ((1.0f - wx) * v10 + wx * v11);
        sv[p] = s;
        float d = qv * s;
        #pragma unroll
        for (int o = 16; o; o >>= 1) d += __shfl_down_sync(0xffffffffu, d, o);
        if (lane == 0) red[p][wid] = d;
    }
    __syncthreads();
    if (t < PTS) sc[t] = (red[t][0] + red[t][1] + red[t][2] + red[t][3]) * 0.088388347648318447f;
    __syncthreads();
    float m = sc[0];
    #pragma unroll
    for (int p = 1; p < PTS; p++) m = fmaxf(m, sc[p]);
    float e[PTS], denom = 0.0f;
    #pragma unroll
    for (int p = 0; p < PTS; p++) { e[p] = expf(sc[p] - m); denom += e[p]; }
    float inv = 1.0f / denom;
    float o = 0.0f;
    #pragma unroll
    for (int p = 0; p < PTS; p++) o += e[p] * inv * sv[p];
    out[(size_t)bn * CC + h * HD + t] = o;
}

// ============================ Launch ============================
extern "C" void kernel_launch(void* const* d_in, const int* in_sizes, int n_in,
                              void* d_out, int out_size)
{
    const float* query = (const float*)d_in[0];
    const float* ref   = (const float*)d_in[1];
    const float* Wq    = (const float*)d_in[2];
    const float* bq    = (const float*)d_in[3];
    const float* Wkv   = (const float*)d_in[4];
    const float* bkv   = (const float*)d_in[5];
    const float* Woff  = (const float*)d_in[6];
    const float* boff  = (const float*)d_in[7];
    const float* Wout  = (const float*)d_in[8];
    const float* bout  = (const float*)d_in[9];
    float* out = (float*)d_out;

    float *q_ptr, *k_ptr, *off_ptr, *attn_ptr;
    __half* kh_ptr;
    cudaGetSymbolAddress((void**)&q_ptr,    g_q);
    cudaGetSymbolAddress((void**)&k_ptr,    g_k);
    cudaGetSymbolAddress((void**)&kh_ptr,   g_kh);
    cudaGetSymbolAddress((void**)&off_ptr,  g_off);
    cudaGetSymbolAddress((void**)&attn_ptr, g_attn);

    cudaFuncAttributes fa;
    cudaFuncGetAttributes(&fa, gemm_qk);
    bool use_tc = (fa.numRegs > 32);

    if (use_tc) {
        char *qh, *ql, *rh, *rl, *ah, *al;
        char *wq, *wk, *wo, *wfh, *wfl;
        cudaGetSymbolAddress((void**)&qh, g_qh);   cudaGetSymbolAddress((void**)&ql, g_ql);
        cudaGetSymbolAddress((void**)&rh, g_rh);   cudaGetSymbolAddress((void**)&rl, g_rl);
        cudaGetSymbolAddress((void**)&ah, g_ah);   cudaGetSymbolAddress((void**)&al, g_al);
        cudaGetSymbolAddress((void**)&wq, g_Wq);
        cudaGetSymbolAddress((void**)&wk, g_Wk);
        cudaGetSymbolAddress((void**)&wo, g_Wo);
        cudaGetSymbolAddress((void**)&wfh, g_Wf_h); cudaGetSymbolAddress((void**)&wfl, g_Wf_l);

        static bool attr_set = false;
        if (!attr_set) {
            cudaFuncSetAttribute(gemm_qk,                 cudaFuncAttributeMaxDynamicSharedMemorySize, 197632);
            cudaFuncSetAttribute(gemm_tc<256, 1, float>,  cudaFuncAttributeMaxDynamicSharedMemorySize, 197632);
            cudaFuncSetAttribute(gemm_tc<128, 2, float>,  cudaFuncAttributeMaxDynamicSharedMemorySize, 197632);
            attr_set = true;
        }

        split_act2_kernel<<<dim3(NCH, MBLK, 2), 128>>>(
            query, (__half*)qh, (__half*)ql,
            ref,   (__half*)rh, (__half*)rl, BN);
        pack_weights_all<<<dim3(NCH, 25), 512>>>(
            Wq, Wkv, Woff, Wout,
            (__half*)wq, (__half*)wk, (__half*)wfh, (__half*)wfl, (__half*)wo);

        // fused q+k GEMM: 688 CTAs, 5 waves instead of 3+3
        gemm_qk<<<dim3(4, 2 * MBLK), 128, 197632>>>(
            qh, ql, rh, rl, wq, wk, bq, bkv, q_ptr, kh_ptr);
        gemm_tc<128, 2, float><<<dim3(1, MBLK), 128, 197632>>>(qh, ql, wfh, wfl, boff, off_ptr, BN, 128);

        attn_warp_kernel<<<BN, 256>>>();

        gemm_tc<256, 1, float><<<dim3(4, MBLK), 128, 197632>>>(ah, al, wo, nullptr, bout, out, BN, CC);
    } else {
        dim3 blk(256);
        dim3 gBig((CC + 63) / 64, (BN + 63) / 64);
        dim3 gOff((128 + 63) / 64, (BN + 63) / 64);
        sgemm_bias_kernel<<<gBig, blk>>>(query, Wq, bq, q_ptr, BN, CC, CC, CC);
        sgemm_bias_kernel<<<gBig, blk>>>(ref, Wkv, bkv, k_ptr, BN, CC, CC, 2 * CC);
        sgemm_bias_kernel<<<gOff, blk>>>(query, Woff, boff, off_ptr, BN, HEADS * PTS * 2, CC, HEADS * PTS * 2);
        attn_kernel<<<dim3(BN, HEADS), 128>>>(attn_ptr);
        sgemm_bias_kernel<<<gBig, blk>>>(attn_ptr, Wout, bout, out, BN, CC, CC, CC);
    }
}

// round 14
// speedup vs baseline: 1.5033x; 1.0693x over previous
#include <cuda_runtime.h>
#include <cuda_bf16.h>
#include <cuda_fp16.h>
#include <cstdint>
#include <math.h>

#define NB   8
#define HSP  37
#define WSP  37
#define NPIX 1369
#define BN   10952
#define CC   1024
#define HEADS 8
#define HD   128
#define PTS  8
#define MBLK 86
#define MPAD (MBLK * 128)   // 11008
#define NCH  16             // K chunks of 64
#define TILE_BYTES 16384    // 128 rows x 128B
#define LO_SCALE 1024.0f
#define LO_INV   0.0009765625f

#if defined(__CUDA_ARCH__) && (defined(__CUDA_ARCH_FEAT_SM103_ALL) || defined(__CUDA_ARCH_FEAT_SM100_ALL) || defined(__CUDA_ARCH_SPECIFIC__))
#define HAS_TCGEN05 1
#else
#define HAS_TCGEN05 0
#endif

#define SMEM_SWIZZLE_128B(byte_offset) ((byte_offset) ^ (((byte_offset) >> 3) & 0x70))

// ============================ Scratch ============================
__device__ float g_q[BN * CC];
__device__ float g_k[BN * CC];          // fallback path only
__device__ __half g_kh[BN * CC];        // tc path: k in fp16 for the gather
__device__ float g_off[BN * HEADS * PTS * 2];
__device__ float g_attn[BN * CC];

// Blocked+swizzled fp16 operands (16KB tiles, tile (r,c) at ((r*NCH)+c)*16KB)
__device__ __half g_qh[MPAD * CC];
__device__ __half g_ql[MPAD * CC];
__device__ __half g_rh[MPAD * CC];
__device__ __half g_rl[MPAD * CC];
__device__ __half g_ah[MPAD * CC];
__device__ __half g_al[MPAD * CC];
__device__ __half g_Wq[CC * CC];
__device__ __half g_Wk[CC * CC];
__device__ __half g_Wo[CC * CC];
__device__ __half g_Wf_h[128 * CC];
__device__ __half g_Wf_l[128 * CC];

// ============================ tcgen05 helpers (guarded) ============================
#if HAS_TCGEN05
__device__ __forceinline__ uint32_t smem_to_u32(const void* p) {
    uint32_t a;
    asm("{ .reg .u64 t; cvta.to.shared.u64 t, %1; cvt.u32.u64 %0, t; }" : "=r"(a) : "l"(p));
    return a;
}
#define TCGEN05_ALLOC(smem_result_addr, nCols) \
    asm volatile("tcgen05.alloc.cta_group::1.sync.aligned.shared::cta.b32 [%0], %1;" \
        :: "r"((uint32_t)(smem_result_addr)), "r"((uint32_t)(nCols)) : "memory")
#define TCGEN05_DEALLOC(tmem_addr, nCols) \
    asm volatile("tcgen05.dealloc.cta_group::1.sync.aligned.b32 %0, %1;" :: "r"(tmem_addr), "r"(nCols))
#define TCGEN05_RELINQUISH_ALLOC_PERMIT() \
    asm volatile("tcgen05.relinquish_alloc_permit.cta_group::1.sync.aligned;")
#define TCGEN05_COMMIT(mbar_smem_addr) \
    asm volatile("tcgen05.commit.cta_group::1.mbarrier::arrive::one.shared::cluster.b64 [%0];" \
        :: "r"((uint32_t)(mbar_smem_addr)) : "memory")
#define TCGEN05_WAIT_LD() asm volatile("tcgen05.wait::ld.sync.aligned;" ::: "memory")
#define TCGEN05_FENCE_AFTER() asm volatile("tcgen05.fence::after_thread_sync;" ::: "memory")
#define TCGEN05_FENCE_BEFORE() asm volatile("tcgen05.fence::before_thread_sync;" ::: "memory")
#define MBARRIER_INIT(mbar_smem_addr, count) \
    asm volatile("mbarrier.init.shared.b64 [%0], %1;" \
        :: "r"((uint32_t)(mbar_smem_addr)), "r"((uint32_t)(count)) : "memory")
#define MBARRIER_EXPECT_TX(mbar_smem_addr, tx_bytes) \
    asm volatile("mbarrier.arrive.expect_tx.shared.b64 _, [%0], %1;" \
        :: "r"((uint32_t)(mbar_smem_addr)), "r"((uint32_t)(tx_bytes)) : "memory")
#define MBARRIER_WAIT_PARITY(mbar_smem_addr, phase_parity) do { \
    uint32_t _mbar = (uint32_t)(mbar_smem_addr); \
    uint32_t _parity = (uint32_t)(phase_parity); \
    uint32_t _done; \
    asm volatile("{\n\t.reg .pred p;\n\t" \
        "mbarrier.try_wait.parity.acquire.cta.shared::cta.b64 p, [%1], %2;\n\t" \
        "selp.b32 %0, 1, 0, p;\n\t}" : "=r"(_done) : "r"(_mbar), "r"(_parity) : "memory"); \
    if (!_done) { \
        asm volatile("{\n\t.reg .pred P1;\n\t" \
            "WAIT_LOOP_%=:\n\t" \
            "mbarrier.try_wait.parity.acquire.cta.shared::cta.b64 P1, [%0], %1, 0x989680;\n\t" \
            "@P1 bra.uni WAIT_DONE_%=;\n\t" \
            "bra.uni WAIT_LOOP_%=;\n\t" \
            "WAIT_DONE_%=:\n\t}" :: "r"(_mbar), "r"(_parity) : "memory"); \
    } \
} while(0)
#define TCGEN05_LD_32X32B_X32(r, tmem_addr) \
    asm volatile("tcgen05.ld.sync.aligned.32x32b.x32.b32 " \
        "{%0, %1, %2, %3, %4, %5, %6, %7, %8, %9, %10, %11, %12, %13, %14, %15, " \
        " %16, %17, %18, %19, %20, %21, %22, %23, %24, %25, %26, %27, %28, %29, %30, %31}, [%32];" \
        : "=r"((r)[0]),  "=r"((r)[1]),  "=r"((r)[2]),  "=r"((r)[3]), \
          "=r"((r)[4]),  "=r"((r)[5]),  "=r"((r)[6]),  "=r"((r)[7]), \
          "=r"((r)[8]),  "=r"((r)[9]),  "=r"((r)[10]), "=r"((r)[11]), \
          "=r"((r)[12]), "=r"((r)[13]), "=r"((r)[14]), "=r"((r)[15]), \
          "=r"((r)[16]), "=r"((r)[17]), "=r"((r)[18]), "=r"((r)[19]), \
          "=r"((r)[20]), "=r"((r)[21]), "=r"((r)[22]), "=r"((r)[23]), \
          "=r"((r)[24]), "=r"((r)[25]), "=r"((r)[26]), "=r"((r)[27]), \
          "=r"((r)[28]), "=r"((r)[29]), "=r"((r)[30]), "=r"((r)[31]) \
        : "r"(tmem_addr))

static constexpr uint64_t SMEM_DESC_BASE_SW128 =
    (uint64_t(2)  << 61) | (uint64_t(1) << 46) | (uint64_t(64) << 32) | (uint64_t(1) << 16);
#define MAKE_SMEM_DESC(base_addr) (SMEM_DESC_BASE_SW128 | ((uint64_t)((base_addr) >> 4) & 0x3FFF))

__device__ __forceinline__ void mma_f16_ss(uint32_t d, uint64_t ad, uint64_t bd,
                                           uint32_t idesc, bool en) {
    uint32_t e = en ? 1u : 0u;
    asm volatile(
        "{\n\t.reg .pred p;\n\tsetp.ne.u32 p, %5, 0;\n\t"
        "tcgen05.mma.cta_group::1.kind::f16 [%0], %1, %2, %3, {%4, %4, %4, %4}, p;\n\t}"
        :: "r"(d), "l"(ad), "l"(bd), "r"(idesc), "r"(0u), "r"(e) : "memory");
}
__device__ __forceinline__ void bulk_g2s(uint32_t dst, const void* src, uint32_t bytes, uint32_t mbar) {
    asm volatile("cp.async.bulk.shared::cluster.global.mbarrier::complete_tx::bytes [%0], [%1], %2, [%3];"
        :: "r"(dst), "l"(src), "r"(bytes), "r"(mbar) : "memory");
}
#endif  // HAS_TCGEN05

// ============================ Pack kernels ============================
__global__ void split_act2_kernel(const float* __restrict__ src0,
                                  __half* __restrict__ hi0, __half* __restrict__ lo0,
                                  const float* __restrict__ src1,
                                  __half* __restrict__ hi1, __half* __restrict__ lo1, int M)
{
    const float* src = blockIdx.z ? src1 : src0;
    __half* hi = blockIdx.z ? hi1 : hi0;
    __half* lo = blockIdx.z ? lo1 : lo0;
    const int c  = blockIdx.x;
    const int mb = blockIdx.y;
    const int t  = threadIdx.x;
    const int j  = t & 7;
    char* hbase = (char*)hi + ((size_t)(mb * NCH + c)) * TILE_BYTES;
    char* lbase = (char*)lo + ((size_t)(mb * NCH + c)) * TILE_BYTES;

    #pragma unroll
    for (int g = 0; g < 8; g++) {
        int ml = g * 16 + (t >> 3);
        int m = mb * 128 + ml;
        float x[8];
        if (m < M) {
            float4 a = *(const float4*)(src + (size_t)m * CC + c * 64 + j * 8);
            float4 b = *(const float4*)(src + (size_t)m * CC + c * 64 + j * 8 + 4);
            x[0]=a.x; x[1]=a.y; x[2]=a.z; x[3]=a.w; x[4]=b.x; x[5]=b.y; x[6]=b.z; x[7]=b.w;
        } else {
            #pragma unroll
            for (int i = 0; i < 8; i++) x[i] = 0.0f;
        }
        __half h[8], l[8];
        #pragma unroll
        for (int i = 0; i < 8; i++) {
            h[i] = __float2half(x[i]);
            l[i] = __float2half((x[i] - __half2float(h[i])) * LO_SCALE);
        }
        uint32_t off = SMEM_SWIZZLE_128B((uint32_t)(ml * 128 + j * 16));
        *(uint4*)(hbase + off) = *(uint4*)h;
        *(uint4*)(lbase + off) = *(uint4*)l;
    }
}

__global__ void __launch_bounds__(512)
pack_weights_all(const float* __restrict__ Wq, const float* __restrict__ Wkv,
                 const float* __restrict__ Woff, const float* __restrict__ Wout,
                 __half* __restrict__ wq, __half* __restrict__ wk,
                 __half* __restrict__ wfh, __half* __restrict__ wfl,
                 __half* __restrict__ wo)
{
    __shared__ float ts[64][129];
    const int c = blockIdx.x;
    const int y = blockIdx.y;
    const int t = threadIdx.x;

    const float* W; int ldw, nb; __half *hi, *lo;
    if (y < 8)       { W = Wq;   ldw = CC;     nb = y;      hi = wq;  lo = nullptr; }
    else if (y < 16) { W = Wkv;  ldw = 2 * CC; nb = y - 8;  hi = wk;  lo = nullptr; }
    else if (y < 17) { W = Woff; ldw = 128;    nb = 0;      hi = wfh; lo = wfl; }
    else             { W = Wout; ldw = CC;     nb = y - 17; hi = wo;  lo = nullptr; }

    const int k0 = c * 64;
    const int n0 = nb * 128;
    const int lrow = t >> 7;
    const int lcol = t & 127;
    #pragma unroll
    for (int i = 0; i < 16; i++) {
        int row = i * 4 + lrow;
        ts[row][lcol] = W[(size_t)(k0 + row) * ldw + n0 + lcol];
    }
    __syncthreads();

    char* hbase = (char*)hi + ((size_t)(nb * NCH + c)) * TILE_BYTES;
    char* lbase = lo ? (char*)lo + ((size_t)(nb * NCH + c)) * TILE_BYTES : nullptr;
    #pragma unroll
    for (int it = 0; it < 2; it++) {
        int idx = t + it * 512;
        int nl = idx >> 3;
        int j  = idx & 7;
        __half h[8], l[8];
        #pragma unroll
        for (int jj = 0; jj < 8; jj++) {
            float x = ts[j * 8 + jj][nl];
            h[jj] = __float2half(x);
            l[jj] = __float2half((x - __half2float(h[jj])) * LO_SCALE);
        }
        uint32_t off = SMEM_SWIZZLE_128B((uint32_t)(nl * 128 + j * 16));
        *(uint4*)(hbase + off) = *(uint4*)h;
        if (lbase) *(uint4*)(lbase + off) = *(uint4*)l;
    }
}

// ===== FUSED q+k+off GEMM: 1D grid of 774 CTAs. =====
//   bid in [0,344):   q   (NT=256, B single, float out)  ntile=bid&3, my=bid>>2
//   bid in [344,688): k   (NT=256, B single, half out)
//   bid in [688,774): off (NT=128, B hi/lo,  float out)  my=bid-688
// All segments use identical 64KB 4-tile stages; warp-specialized producer/consumer.
__global__ void __launch_bounds__(128, 1)
gemm_fused(const char* __restrict__ QAh, const char* __restrict__ QAl,
           const char* __restrict__ RAh, const char* __restrict__ RAl,
           const char* __restrict__ WqB, const char* __restrict__ WkB,
           const char* __restrict__ WfH, const char* __restrict__ WfL,
           const float* __restrict__ bq, const float* __restrict__ bkv,
           const float* __restrict__ boff,
           float* __restrict__ outQ, __half* __restrict__ outK,
           float* __restrict__ outOff)
{
#if HAS_TCGEN05
    constexpr uint32_t SB = 4 * TILE_BYTES;
    constexpr uint32_t HDR = 1024;

    extern __shared__ char smem[];
    uint32_t sb = smem_to_u32(smem);
    const int tid = threadIdx.x;
    const int wid = tid >> 5;
    const int lane = tid & 31;
    const int bid = blockIdx.x;

    const int seg = (bid < 344) ? 0 : (bid < 688 ? 1 : 2);
    const bool isOff = (seg == 2);
    const int nt = isOff ? 128 : 256;
    const int my = isOff ? (bid - 688) : ((seg ? bid - 344 : bid) >> 2);
    const int ntile = isOff ? 0 : ((seg ? bid - 344 : bid) & 3);
    const int m0 = my * 128;
    const int n0 = ntile * 256;
    const uint32_t idesc = 0x8000010u | ((uint32_t)(nt / 8) << 17);

    const char* Ah = (seg == 1) ? RAh : QAh;   // off uses query activations too
    const char* Al = (seg == 1) ? RAl : QAl;
    const float* bias = (seg == 0) ? bq : (seg == 1 ? bkv : boff);

    if (wid == 0) TCGEN05_ALLOC(sb + 0, 512);
    if (tid == 0) {
        MBARRIER_INIT(sb + 16, 1);   // full0..2
        MBARRIER_INIT(sb + 24, 1);
        MBARRIER_INIT(sb + 32, 1);
        MBARRIER_INIT(sb + 48, 1);   // empty0..2
        MBARRIER_INIT(sb + 56, 1);
        MBARRIER_INIT(sb + 64, 1);
    }
    __syncthreads();
    uint32_t tmem;
    asm volatile("ld.shared.b32 %0, [%1];" : "=r"(tmem) : "r"(sb));

    if (tid == 0) {
        // ---- MMA consumer ----
        for (int c = 0; c < NCH; c++) {
            int s = c % 3;
            MBARRIER_WAIT_PARITY(sb + 16 + 8u * s, (uint32_t)((c / 3) & 1));
            uint32_t st = sb + HDR + (uint32_t)s * SB;
            uint64_t ahd = MAKE_SMEM_DESC(st);
            uint64_t ald = MAKE_SMEM_DESC(st + TILE_BYTES);
            uint64_t bhd = MAKE_SMEM_DESC(st + 2 * TILE_BYTES);
            #pragma unroll
            for (int ks = 0; ks < 4; ks++)
                mma_f16_ss(tmem, ahd + ks * 2, bhd + ks * 2, idesc, !(c == 0 && ks == 0));
            #pragma unroll
            for (int ks = 0; ks < 4; ks++)
                mma_f16_ss(tmem + nt, ald + ks * 2, bhd + ks * 2, idesc, !(c == 0 && ks == 0));
            if (isOff) {
                uint64_t bld = MAKE_SMEM_DESC(st + 3 * TILE_BYTES);
                #pragma unroll
                for (int ks = 0; ks < 4; ks++)
                    mma_f16_ss(tmem + nt, ahd + ks * 2, bld + ks * 2, idesc, true);
            }
            TCGEN05_COMMIT(sb + 48 + 8u * s);
        }
        for (int c = NCH - 3; c < NCH; c++)
            MBARRIER_WAIT_PARITY(sb + 48 + 8u * (c % 3), (uint32_t)((c / 3) & 1));
    } else if (tid == 32) {
        // ---- copy producer ----
        auto issue = [&](int c) {
            int s = c % 3;
            uint32_t fb = sb + 16 + 8u * s;
            uint32_t st = sb + HDR + (uint32_t)s * SB;
            // off stage: A hi, A lo, B hi, B lo (4 tiles). qk stage: A hi, A lo, B0, B1.
            MBARRIER_EXPECT_TX(fb, SB);
            size_t aoff = ((size_t)my * NCH + c) * TILE_BYTES;
            bulk_g2s(st, Ah + aoff, TILE_BYTES, fb);
            bulk_g2s(st + TILE_BYTES, Al + aoff, TILE_BYTES, fb);
            if (isOff) {
                size_t boff2 = (size_t)c * TILE_BYTES;   // single 128-row B block
                bulk_g2s(st + 2 * TILE_BYTES, WfH + boff2, TILE_BYTES, fb);
                bulk_g2s(st + 3 * TILE_BYTES, WfL + boff2, TILE_BYTES, fb);
            } else {
                const char* B = (seg == 1) ? WkB : WqB;
                #pragma unroll
                for (int i = 0; i < 2; i++)
                    bulk_g2s(st + (2 + i) * TILE_BYTES,
                             B + ((size_t)(ntile * 2 + i) * NCH + c) * TILE_BYTES,
                             TILE_BYTES, fb);
            }
        };
        issue(0); issue(1); issue(2);
        for (int c = 3; c < NCH; c++) {
            int s = c % 3;
            MBARRIER_WAIT_PARITY(sb + 48 + 8u * s, (uint32_t)((c / 3 - 1) & 1));
            issue(c);
        }
    }
    __syncthreads();
    TCGEN05_FENCE_AFTER();

    // Epilogue: combine acc0 + acc1*2^-10, per-warp transpose, coalesced STG.
    float* buf = (float*)(smem + HDR) + wid * (32 * 33);
    for (int base = 0; base < nt; base += 32) {
        uint32_t r0[32], r1[32];
        TCGEN05_LD_32X32B_X32(r0, tmem + base);
        TCGEN05_LD_32X32B_X32(r1, tmem + nt + base);
        TCGEN05_WAIT_LD();
        #pragma unroll
        for (int q = 0; q < 32; q++)
            buf[lane * 33 + q] = __uint_as_float(r0[q]) + __uint_as_float(r1[q]) * LO_INV;
        __syncwarp();
        float bv = bias[n0 + base + lane];
        if (seg == 0) {
            #pragma unroll 4
            for (int rr = 0; rr < 32; rr++) {
                int gm = m0 + wid * 32 + rr;
                if (gm < BN) outQ[(size_t)gm * CC + n0 + base + lane] = buf[rr * 33 + lane] + bv;
            }
        } else if (seg == 1) {
            #pragma unroll 4
            for (int rr = 0; rr < 32; rr++) {
                int gm = m0 + wid * 32 + rr;
                if (gm < BN) outK[(size_t)gm * CC + n0 + base + lane] = __float2half(buf[rr * 33 + lane] + bv);
            }
        } else {
            #pragma unroll 4
            for (int rr = 0; rr < 32; rr++) {
                int gm = m0 + wid * 32 + rr;
                if (gm < BN) outOff[(size_t)gm * 128 + base + lane] = buf[rr * 33 + lane] + bv;
            }
        }
        __syncwarp();
    }
    TCGEN05_FENCE_BEFORE();
    __syncthreads();
    if (wid == 0) {
        TCGEN05_RELINQUISH_ALLOC_PERMIT();
        TCGEN05_DEALLOC(tmem, 512);
    }
#endif
}

// ===== cg1 GEMM for the out projection (NT=256, B single) =====
template <int NT, int BPARTS, typename TOut>
__global__ void __launch_bounds__(128, 1)
gemm_tc(const char* __restrict__ Ah, const char* __restrict__ Al,
        const char* __restrict__ Bh, const char* __restrict__ Bl,
        const float* __restrict__ bias, TOut* __restrict__ C, int M, int Ncols)
{
#if HAS_TCGEN05
    constexpr int NBB = NT / 128;
    constexpr int NBT = BPARTS * NBB;
    constexpr uint32_t SB = (2 + NBT) * TILE_BYTES;
    constexpr uint32_t HDR = 1024;
    constexpr uint32_t IDESC = 0x8000010u | ((NT / 8) << 17);

    extern __shared__ char smem[];
    uint32_t sb = smem_to_u32(smem);
    const int tid = threadIdx.x;
    const int wid = tid >> 5;
    const int lane = tid & 31;
    const int m0 = blockIdx.y * 128;
    const int n0 = blockIdx.x * NT;

    if (wid == 0) TCGEN05_ALLOC(sb + 0, 512);
    if (tid == 0) {
        MBARRIER_INIT(sb + 16, 1);
        MBARRIER_INIT(sb + 24, 1);
        MBARRIER_INIT(sb + 32, 1);
        MBARRIER_INIT(sb + 48, 1);
        MBARRIER_INIT(sb + 56, 1);
        MBARRIER_INIT(sb + 64, 1);
    }
    __syncthreads();
    uint32_t tmem;
    asm volatile("ld.shared.b32 %0, [%1];" : "=r"(tmem) : "r"(sb));

    if (tid == 0) {
        for (int c = 0; c < NCH; c++) {
            int s = c % 3;
            MBARRIER_WAIT_PARITY(sb + 16 + 8u * s, (uint32_t)((c / 3) & 1));
            uint32_t st = sb + HDR + (uint32_t)s * SB;
            uint64_t ahd = MAKE_SMEM_DESC(st);
            uint64_t ald = MAKE_SMEM_DESC(st + TILE_BYTES);
            uint64_t bhd = MAKE_SMEM_DESC(st + 2 * TILE_BYTES);
            #pragma unroll
            for (int ks = 0; ks < 4; ks++)
                mma_f16_ss(tmem, ahd + ks * 2, bhd + ks * 2, IDESC, !(c == 0 && ks == 0));
            #pragma unroll
            for (int ks = 0; ks < 4; ks++)
                mma_f16_ss(tmem + NT, ald + ks * 2, bhd + ks * 2, IDESC, !(c == 0 && ks == 0));
            if (BPARTS == 2) {
                uint64_t bld = MAKE_SMEM_DESC(st + 3 * TILE_BYTES);
                #pragma unroll
                for (int ks = 0; ks < 4; ks++)
                    mma_f16_ss(tmem + NT, ahd + ks * 2, bld + ks * 2, IDESC, true);
            }
            TCGEN05_COMMIT(sb + 48 + 8u * s);
        }
        for (int c = NCH - 3; c < NCH; c++)
            MBARRIER_WAIT_PARITY(sb + 48 + 8u * (c % 3), (uint32_t)((c / 3) & 1));
    } else if (tid == 32) {
        auto issue = [&](int c) {
            int s = c % 3;
            uint32_t fb = sb + 16 + 8u * s;
            uint32_t st = sb + HDR + (uint32_t)s * SB;
            MBARRIER_EXPECT_TX(fb, SB);
            size_t aoff = ((size_t)blockIdx.y * NCH + c) * TILE_BYTES;
            bulk_g2s(st, Ah + aoff, TILE_BYTES, fb);
            bulk_g2s(st + TILE_BYTES, Al + aoff, TILE_BYTES, fb);
            #pragma unroll
            for (int i = 0; i < NBT; i++) {
                const char* src;
                if (BPARTS == 1)
                    src = Bh + ((size_t)(blockIdx.x * NBB + i) * NCH + c) * TILE_BYTES;
                else
                    src = (i == 0 ? Bh : Bl) + ((size_t)(blockIdx.x * NBB) * NCH + c) * TILE_BYTES;
                bulk_g2s(st + (2 + i) * TILE_BYTES, src, TILE_BYTES, fb);
            }
        };
        issue(0); issue(1); issue(2);
        for (int c = 3; c < NCH; c++) {
            int s = c % 3;
            MBARRIER_WAIT_PARITY(sb + 48 + 8u * s, (uint32_t)((c / 3 - 1) & 1));
            issue(c);
        }
    }
    __syncthreads();
    TCGEN05_FENCE_AFTER();

    float* buf = (float*)(smem + HDR) + wid * (32 * 33);
    #pragma unroll
    for (int base = 0; base < NT; base += 32) {
        uint32_t r0[32], r1[32];
        TCGEN05_LD_32X32B_X32(r0, tmem + base);
        TCGEN05_LD_32X32B_X32(r1, tmem + NT + base);
        TCGEN05_WAIT_LD();
        #pragma unroll
        for (int q = 0; q < 32; q++)
            buf[lane * 33 + q] = __uint_as_float(r0[q]) + __uint_as_float(r1[q]) * LO_INV;
        __syncwarp();
        float bv = bias[n0 + base + lane];
        #pragma unroll 4
        for (int rr = 0; rr < 32; rr++) {
            int gm = m0 + wid * 32 + rr;
            if (gm < M)
                C[(size_t)gm * Ncols + n0 + base + lane] = (TOut)(buf[rr * 33 + lane] + bv);
        }
        __syncwarp();
    }
    TCGEN05_FENCE_BEFORE();
    __syncthreads();
    if (wid == 0) {
        TCGEN05_RELINQUISH_ALLOC_PERMIT();
        TCGEN05_DEALLOC(tmem, 512);
    }
#endif
}

// ============================ Fallback SGEMM ============================
__global__ void sgemm_bias_kernel(const float* __restrict__ A,
                                  const float* __restrict__ Wt,
                                  const float* __restrict__ bias,
                                  float* __restrict__ C,
                                  int M, int Ncols, int K, int ldw)
{
    __shared__ float As[16][64];
    __shared__ float Bs[16][64];
    const int tid = threadIdx.x;
    const int tx = tid & 15;
    const int ty = tid >> 4;
    const int n0 = blockIdx.x * 64;
    const int m0 = blockIdx.y * 64;
    float acc[4][4] = {};
    for (int k0 = 0; k0 < K; k0 += 16) {
        #pragma unroll
        for (int i = 0; i < 4; i++) {
            int idx = tid + i * 256;
            int m  = idx >> 4, kk = idx & 15, gm = m0 + m;
            As[kk][m] = (gm < M) ? A[(size_t)gm * K + (k0 + kk)] : 0.0f;
        }
        #pragma unroll
        for (int i = 0; i < 4; i++) {
            int idx = tid + i * 256;
            int kk = idx >> 6, n = idx & 63, gn = n0 + n;
            Bs[kk][n] = (gn < Ncols) ? Wt[(size_t)(k0 + kk) * ldw + gn] : 0.0f;
        }
        __syncthreads();
        #pragma unroll
        for (int kk = 0; kk < 16; kk++) {
            float4 a = *(const float4*)&As[kk][ty * 4];
            float4 w = *(const float4*)&Bs[kk][tx * 4];
            acc[0][0] += a.x*w.x; acc[0][1] += a.x*w.y; acc[0][2] += a.x*w.z; acc[0][3] += a.x*w.w;
            acc[1][0] += a.y*w.x; acc[1][1] += a.y*w.y; acc[1][2] += a.y*w.z; acc[1][3] += a.y*w.w;
            acc[2][0] += a.z*w.x; acc[2][1] += a.z*w.y; acc[2][2] += a.z*w.z; acc[2][3] += a.z*w.w;
            acc[3][0] += a.w*w.x; acc[3][1] += a.w*w.y; acc[3][2] += a.w*w.z; acc[3][3] += a.w*w.w;
        }
        __syncthreads();
    }
    #pragma unroll
    for (int r = 0; r < 4; r++) {
        int gm = m0 + ty * 4 + r;
        if (gm >= M) continue;
        #pragma unroll
        for (int c = 0; c < 4; c++) {
            int gn = n0 + tx * 4 + c;
            if (gn < Ncols) C[(size_t)gm * Ncols + gn] = acc[r][c] + bias[gn];
        }
    }
}

// ============================ Attention (warp per (bn,h)), fp16 k gathers ============
__global__ void attn_warp_kernel()
{
    const int bn = blockIdx.x;
    const int h  = threadIdx.x >> 5;
    const int lane = threadIdx.x & 31;

    const int b = bn / NPIX;
    const int n = bn % NPIX;
    const int row = n / WSP;
    const int col = n % WSP;
    const float step = 2.0f / 36.0f;
    const float ybase = -1.0f + row * step;
    const float xbase = -1.0f + col * step;

    float4 q4 = *(const float4*)(g_q + (size_t)bn * CC + h * HD + lane * 4);
    const __half* kbase = g_kh + (size_t)b * NPIX * CC + h * HD + lane * 4;

    float offv = 0.0f;
    if (lane < 16) offv = g_off[(size_t)bn * (HEADS * PTS * 2) + h * (PTS * 2) + lane];

    float4 sv[PTS];
    float sc[PTS];
    #pragma unroll
    for (int p = 0; p < PTS; p++) {
        float o0 = __shfl_sync(0xffffffffu, offv, 2 * p);
        float o1 = __shfl_sync(0xffffffffu, offv, 2 * p + 1);
        float xn = ybase + o0;
        float yn = xbase + o1;
        float ix = fminf(fmaxf((xn + 1.0f) * 0.5f * (WSP - 1), 0.0f), (float)(WSP - 1));
        float iy = fminf(fmaxf((yn + 1.0f) * 0.5f * (HSP - 1), 0.0f), (float)(HSP - 1));
        float x0f = floorf(ix), y0f = floorf(iy);
        float wx = ix - x0f, wy = iy - y0f;
        int x0 = (int)x0f, y0 = (int)y0f;
        int x1 = min(x0 + 1, WSP - 1);
        int y1 = min(y0 + 1, HSP - 1);

        uint2 u00 = *(const uint2*)(kbase + (size_t)(y0 * WSP + x0) * CC);
        uint2 u01 = *(const uint2*)(kbase + (size_t)(y0 * WSP + x1) * CC);
        uint2 u10 = *(const uint2*)(kbase + (size_t)(y1 * WSP + x0) * CC);
        uint2 u11 = *(const uint2*)(kbase + (size_t)(y1 * WSP + x1) * CC);
        float2 a00 = __half22float2(*(__half2*)&u00.x), b00 = __half22float2(*(__half2*)&u00.y);
        float2 a01 = __half22float2(*(__half2*)&u01.x), b01 = __half22float2(*(__half2*)&u01.y);
        float2 a10 = __half22float2(*(__half2*)&u10.x), b10 = __half22float2(*(__half2*)&u10.y);
        float2 a11 = __half22float2(*(__half2*)&u11.x), b11 = __half22float2(*(__half2*)&u11.y);

        float w00 = (1.0f - wy) * (1.0f - wx), w01 = (1.0f - wy) * wx;
        float w10 = wy * (1.0f - wx), w11 = wy * wx;
        float4 s;
        s.x = w00*a00.x + w01*a01.x + w10*a10.x + w11*a11.x;
        s.y = w00*a00.y + w01*a01.y + w10*a10.y + w11*a11.y;
        s.z = w00*b00.x + w01*b01.x + w10*b10.x + w11*b11.x;
        s.w = w00*b00.y + w01*b01.y + w10*b10.y + w11*b11.y;
        sv[p] = s;

        float d = q4.x*s.x + q4.y*s.y + q4.z*s.z + q4.w*s.w;
        #pragma unroll
        for (int o = 16; o; o >>= 1) d += __shfl_xor_sync(0xffffffffu, d, o);
        sc[p] = d * 0.088388347648318447f;
    }

    float m = sc[0];
    #pragma unroll
    for (int p = 1; p < PTS; p++) m = fmaxf(m, sc[p]);
    float e[PTS], denom = 0.0f;
    #pragma unroll
    for (int p = 0; p < PTS; p++) { e[p] = expf(sc[p] - m); denom += e[p]; }
    float inv = 1.0f / denom;

    float4 o = make_float4(0, 0, 0, 0);
    #pragma unroll
    for (int p = 0; p < PTS; p++) {
        float w = e[p] * inv;
        o.x += w * sv[p].x; o.y += w * sv[p].y; o.z += w * sv[p].z; o.w += w * sv[p].w;
    }

    int k = h * HD + lane * 4;
    int mb = bn >> 7, ml = bn & 127;
    int c = k >> 6, kl = k & 63;
    size_t tbase = ((size_t)(mb * NCH + c)) * TILE_BYTES;
    uint32_t off = SMEM_SWIZZLE_128B((uint32_t)(ml * 128 + kl * 2));

    __half h4[4], l4[4];
    float ov[4] = {o.x, o.y, o.z, o.w};
    #pragma unroll
    for (int i = 0; i < 4; i++) {
        h4[i] = __float2half(ov[i]);
        l4[i] = __float2half((ov[i] - __half2float(h4[i])) * LO_SCALE);
    }
    *(uint2*)((char*)g_ah + tbase + off) = *(uint2*)h4;
    *(uint2*)((char*)g_al + tbase + off) = *(uint2*)l4;
}

// Fallback attention (fp32 k, fp32 output to g_attn)
__global__ void attn_kernel(float* __restrict__ out)
{
    const int bn = blockIdx.x;
    const int h  = blockIdx.y;
    const int t  = threadIdx.x;
    const int lane = t & 31;
    const int wid  = t >> 5;
    const int b = bn / NPIX;
    const int n = bn % NPIX;
    const int row = n / WSP;
    const int col = n % WSP;
    const float step = 2.0f / 36.0f;
    const float ybase = -1.0f + row * step;
    const float xbase = -1.0f + col * step;
    const float qv = g_q[(size_t)bn * CC + h * HD + t];
    const float* kbase = g_k + (size_t)b * NPIX * CC + h * HD + t;
    const float* offp  = g_off + (size_t)bn * (HEADS * PTS * 2) + h * (PTS * 2);
    float sv[PTS];
    __shared__ float red[PTS][4];
    __shared__ float sc[PTS];
    #pragma unroll
    for (int p = 0; p < PTS; p++) {
        float o0 = offp[p * 2 + 0], o1 = offp[p * 2 + 1];
        float xn = ybase + o0, yn = xbase + o1;
        float ix = fminf(fmaxf((xn + 1.0f) * 0.5f * (WSP - 1), 0.0f), (float)(WSP - 1));
        float iy = fminf(fmaxf((yn + 1.0f) * 0.5f * (HSP - 1), 0.0f), (float)(HSP - 1));
        float x0f = floorf(ix), y0f = floorf(iy);
        float wx = ix - x0f, wy = iy - y0f;
        int x0 = (int)x0f, y0 = (int)y0f;
        int x1 = min(x0 + 1, WSP - 1), y1 = min(y0 + 1, HSP - 1);
        float v00 = kbase[(size_t)(y0 * WSP + x0) * CC];
        float v01 = kbase[(size_t)(y0 * WSP + x1) * CC];
        float v10 = kbase[(size_t)(y1 * WSP + x0) * CC];
        float v11 = kbase[(size_t)(y1 * WSP + x1) * CC];
        float s = (1.0f - wy) * ((1.0f - wx) * v00 + wx * v01)
                +          wy * ((1.0f - wx) * v10 + wx * v11);
        sv[p] = s;
        float d = qv * s;
        #pragma unroll
        for (int o = 16; o; o >>= 1) d += __shfl_down_sync(0xffffffffu, d, o);
        if (lane == 0) red[p][wid] = d;
    }
    __syncthreads();
    if (t < PTS) sc[t] = (red[t][0] + red[t][1] + red[t][2] + red[t][3]) * 0.088388347648318447f;
    __syncthreads();
    float m = sc[0];
    #pragma unroll
    for (int p = 1; p < PTS; p++) m = fmaxf(m, sc[p]);
    float e[PTS], denom = 0.0f;
    #pragma unroll
    for (int p = 0; p < PTS; p++) { e[p] = expf(sc[p] - m); denom += e[p]; }
    float inv = 1.0f / denom;
    float o = 0.0f;
    #pragma unroll
    for (int p = 0; p < PTS; p++) o += e[p] * inv * sv[p];
    out[(size_t)bn * CC + h * HD + t] = o;
}

// ============================ Launch ============================
extern "C" void kernel_launch(void* const* d_in, const int* in_sizes, int n_in,
                              void* d_out, int out_size)
{
    const float* query = (const float*)d_in[0];
    const float* ref   = (const float*)d_in[1];
    const float* Wq    = (const float*)d_in[2];
    const float* bq    = (const float*)d_in[3];
    const float* Wkv   = (const float*)d_in[4];
    const float* bkv   = (const float*)d_in[5];
    const float* Woff  = (const float*)d_in[6];
    const float* boff  = (const float*)d_in[7];
    const float* Wout  = (const float*)d_in[8];
    const float* bout  = (const float*)d_in[9];
    float* out = (float*)d_out;

    float *q_ptr, *k_ptr, *off_ptr, *attn_ptr;
    __half* kh_ptr;
    cudaGetSymbolAddress((void**)&q_ptr,    g_q);
    cudaGetSymbolAddress((void**)&k_ptr,    g_k);
    cudaGetSymbolAddress((void**)&kh_ptr,   g_kh);
    cudaGetSymbolAddress((void**)&off_ptr,  g_off);
    cudaGetSymbolAddress((void**)&attn_ptr, g_attn);

    cudaFuncAttributes fa;
    cudaFuncGetAttributes(&fa, gemm_fused);
    bool use_tc = (fa.numRegs > 32);

    if (use_tc) {
        char *qh, *ql, *rh, *rl, *ah, *al;
        char *wq, *wk, *wo, *wfh, *wfl;
        cudaGetSymbolAddress((void**)&qh, g_qh);   cudaGetSymbolAddress((void**)&ql, g_ql);
        cudaGetSymbolAddress((void**)&rh, g_rh);   cudaGetSymbolAddress((void**)&rl, g_rl);
        cudaGetSymbolAddress((void**)&ah, g_ah);   cudaGetSymbolAddress((void**)&al, g_al);
        cudaGetSymbolAddress((void**)&wq, g_Wq);
        cudaGetSymbolAddress((void**)&wk, g_Wk);
        cudaGetSymbolAddress((void**)&wo, g_Wo);
        cudaGetSymbolAddress((void**)&wfh, g_Wf_h); cudaGetSymbolAddress((void**)&wfl, g_Wf_l);

        static bool attr_set = false;
        if (!attr_set) {
            cudaFuncSetAttribute(gemm_fused,              cudaFuncAttributeMaxDynamicSharedMemorySize, 197632);
            cudaFuncSetAttribute(gemm_tc<256, 1, float>,  cudaFuncAttributeMaxDynamicSharedMemorySize, 197632);
            attr_set = true;
        }

        split_act2_kernel<<<dim3(NCH, MBLK, 2), 128>>>(
            query, (__half*)qh, (__half*)ql,
            ref,   (__half*)rh, (__half*)rl, BN);
        pack_weights_all<<<dim3(NCH, 25), 512>>>(
            Wq, Wkv, Woff, Wout,
            (__half*)wq, (__half*)wk, (__half*)wfh, (__half*)wfl, (__half*)wo);

        // fused q + k + off GEMM: 774 CTAs in one launch
        gemm_fused<<<774, 128, 197632>>>(
            qh, ql, rh, rl, wq, wk, wfh, wfl, bq, bkv, boff,
            q_ptr, kh_ptr, off_ptr);

        attn_warp_kernel<<<BN, 256>>>();

        gemm_tc<256, 1, float><<<dim3(4, MBLK), 128, 197632>>>(ah, al, wo, nullptr, bout, out, BN, CC);
    } else {
        dim3 blk(256);
        dim3 gBig((CC + 63) / 64, (BN + 63) / 64);
        dim3 gOff((128 + 63) / 64, (BN + 63) / 64);
        sgemm_bias_kernel<<<gBig, blk>>>(query, Wq, bq, q_ptr, BN, CC, CC, CC);
        sgemm_bias_kernel<<<gBig, blk>>>(ref, Wkv, bkv, k_ptr, BN, CC, CC, 2 * CC);
        sgemm_bias_kernel<<<gOff, blk>>>(query, Woff, boff, off_ptr, BN, HEADS * PTS * 2, CC, HEADS * PTS * 2);
        attn_kernel<<<dim3(BN, HEADS), 128>>>(attn_ptr);
        sgemm_bias_kernel<<<gBig, blk>>>(attn_ptr, Wout, bout, out, BN, CC, CC, CC);
    }
}

// round 15
// speedup vs baseline: 1.5380x; 1.0231x over previous
#include <cuda_runtime.h>
#include <cuda_bf16.h>
#include <cuda_fp16.h>
#include <cstdint>
#include <math.h>

#define NB   8
#define HSP  37
#define WSP  37
#define NPIX 1369
#define BN   10952
#define CC   1024
#define HEADS 8
#define HD   128
#define PTS  8
#define MBLK 86
#define MPAD (MBLK * 128)   // 11008
#define NCH  16             // K chunks of 64
#define TILE_BYTES 16384    // 128 rows x 128B
#define LO_SCALE 1024.0f
#define LO_INV   0.0009765625f

#if defined(__CUDA_ARCH__) && (defined(__CUDA_ARCH_FEAT_SM103_ALL) || defined(__CUDA_ARCH_FEAT_SM100_ALL) || defined(__CUDA_ARCH_SPECIFIC__))
#define HAS_TCGEN05 1
#else
#define HAS_TCGEN05 0
#endif

#define SMEM_SWIZZLE_128B(byte_offset) ((byte_offset) ^ (((byte_offset) >> 3) & 0x70))

// ============================ Scratch ============================
__device__ float g_q[BN * CC];
__device__ float g_k[BN * CC];          // fallback path only
__device__ __half g_kh[BN * CC];        // tc path: k in fp16 for the gather
__device__ float g_off[BN * HEADS * PTS * 2];
__device__ float g_attn[BN * CC];

// Blocked+swizzled fp16 operands (16KB tiles, tile (r,c) at ((r*NCH)+c)*16KB)
__device__ __half g_qh[MPAD * CC];
__device__ __half g_ql[MPAD * CC];
__device__ __half g_rh[MPAD * CC];
__device__ __half g_rl[MPAD * CC];
__device__ __half g_ah[MPAD * CC];
__device__ __half g_al[MPAD * CC];
__device__ __half g_Wq[CC * CC];
__device__ __half g_Wk[CC * CC];
__device__ __half g_Wo[CC * CC];
__device__ __half g_Wf_h[128 * CC];
__device__ __half g_Wf_l[128 * CC];

// ============================ tcgen05 helpers (guarded) ============================
#if HAS_TCGEN05
__device__ __forceinline__ uint32_t smem_to_u32(const void* p) {
    uint32_t a;
    asm("{ .reg .u64 t; cvta.to.shared.u64 t, %1; cvt.u32.u64 %0, t; }" : "=r"(a) : "l"(p));
    return a;
}
#define TCGEN05_ALLOC(smem_result_addr, nCols) \
    asm volatile("tcgen05.alloc.cta_group::1.sync.aligned.shared::cta.b32 [%0], %1;" \
        :: "r"((uint32_t)(smem_result_addr)), "r"((uint32_t)(nCols)) : "memory")
#define TCGEN05_DEALLOC(tmem_addr, nCols) \
    asm volatile("tcgen05.dealloc.cta_group::1.sync.aligned.b32 %0, %1;" :: "r"(tmem_addr), "r"(nCols))
#define TCGEN05_RELINQUISH_ALLOC_PERMIT() \
    asm volatile("tcgen05.relinquish_alloc_permit.cta_group::1.sync.aligned;")
#define TCGEN05_COMMIT(mbar_smem_addr) \
    asm volatile("tcgen05.commit.cta_group::1.mbarrier::arrive::one.shared::cluster.b64 [%0];" \
        :: "r"((uint32_t)(mbar_smem_addr)) : "memory")
#define TCGEN05_WAIT_LD() asm volatile("tcgen05.wait::ld.sync.aligned;" ::: "memory")
#define TCGEN05_FENCE_AFTER() asm volatile("tcgen05.fence::after_thread_sync;" ::: "memory")
#define TCGEN05_FENCE_BEFORE() asm volatile("tcgen05.fence::before_thread_sync;" ::: "memory")
#define MBARRIER_INIT(mbar_smem_addr, count) \
    asm volatile("mbarrier.init.shared.b64 [%0], %1;" \
        :: "r"((uint32_t)(mbar_smem_addr)), "r"((uint32_t)(count)) : "memory")
#define MBARRIER_EXPECT_TX(mbar_smem_addr, tx_bytes) \
    asm volatile("mbarrier.arrive.expect_tx.shared.b64 _, [%0], %1;" \
        :: "r"((uint32_t)(mbar_smem_addr)), "r"((uint32_t)(tx_bytes)) : "memory")
#define MBARRIER_WAIT_PARITY(mbar_smem_addr, phase_parity) do { \
    uint32_t _mbar = (uint32_t)(mbar_smem_addr); \
    uint32_t _parity = (uint32_t)(phase_parity); \
    uint32_t _done; \
    asm volatile("{\n\t.reg .pred p;\n\t" \
        "mbarrier.try_wait.parity.acquire.cta.shared::cta.b64 p, [%1], %2;\n\t" \
        "selp.b32 %0, 1, 0, p;\n\t}" : "=r"(_done) : "r"(_mbar), "r"(_parity) : "memory"); \
    if (!_done) { \
        asm volatile("{\n\t.reg .pred P1;\n\t" \
            "WAIT_LOOP_%=:\n\t" \
            "mbarrier.try_wait.parity.acquire.cta.shared::cta.b64 P1, [%0], %1, 0x989680;\n\t" \
            "@P1 bra.uni WAIT_DONE_%=;\n\t" \
            "bra.uni WAIT_LOOP_%=;\n\t" \
            "WAIT_DONE_%=:\n\t}" :: "r"(_mbar), "r"(_parity) : "memory"); \
    } \
} while(0)
#define TCGEN05_LD_32X32B_X32(r, tmem_addr) \
    asm volatile("tcgen05.ld.sync.aligned.32x32b.x32.b32 " \
        "{%0, %1, %2, %3, %4, %5, %6, %7, %8, %9, %10, %11, %12, %13, %14, %15, " \
        " %16, %17, %18, %19, %20, %21, %22, %23, %24, %25, %26, %27, %28, %29, %30, %31}, [%32];" \
        : "=r"((r)[0]),  "=r"((r)[1]),  "=r"((r)[2]),  "=r"((r)[3]), \
          "=r"((r)[4]),  "=r"((r)[5]),  "=r"((r)[6]),  "=r"((r)[7]), \
          "=r"((r)[8]),  "=r"((r)[9]),  "=r"((r)[10]), "=r"((r)[11]), \
          "=r"((r)[12]), "=r"((r)[13]), "=r"((r)[14]), "=r"((r)[15]), \
          "=r"((r)[16]), "=r"((r)[17]), "=r"((r)[18]), "=r"((r)[19]), \
          "=r"((r)[20]), "=r"((r)[21]), "=r"((r)[22]), "=r"((r)[23]), \
          "=r"((r)[24]), "=r"((r)[25]), "=r"((r)[26]), "=r"((r)[27]), \
          "=r"((r)[28]), "=r"((r)[29]), "=r"((r)[30]), "=r"((r)[31]) \
        : "r"(tmem_addr))

static constexpr uint64_t SMEM_DESC_BASE_SW128 =
    (uint64_t(2)  << 61) | (uint64_t(1) << 46) | (uint64_t(64) << 32) | (uint64_t(1) << 16);
#define MAKE_SMEM_DESC(base_addr) (SMEM_DESC_BASE_SW128 | ((uint64_t)((base_addr) >> 4) & 0x3FFF))

__device__ __forceinline__ void mma_f16_ss(uint32_t d, uint64_t ad, uint64_t bd,
                                           uint32_t idesc, bool en) {
    uint32_t e = en ? 1u : 0u;
    asm volatile(
        "{\n\t.reg .pred p;\n\tsetp.ne.u32 p, %5, 0;\n\t"
        "tcgen05.mma.cta_group::1.kind::f16 [%0], %1, %2, %3, {%4, %4, %4, %4}, p;\n\t}"
        :: "r"(d), "l"(ad), "l"(bd), "r"(idesc), "r"(0u), "r"(e) : "memory");
}
__device__ __forceinline__ void bulk_g2s(uint32_t dst, const void* src, uint32_t bytes, uint32_t mbar) {
    asm volatile("cp.async.bulk.shared::cluster.global.mbarrier::complete_tx::bytes [%0], [%1], %2, [%3];"
        :: "r"(dst), "l"(src), "r"(bytes), "r"(mbar) : "memory");
}
#endif  // HAS_TCGEN05

// ============================ Pack kernels ============================
__global__ void split_act2_kernel(const float* __restrict__ src0,
                                  __half* __restrict__ hi0, __half* __restrict__ lo0,
                                  const float* __restrict__ src1,
                                  __half* __restrict__ hi1, __half* __restrict__ lo1, int M)
{
    const float* src = blockIdx.z ? src1 : src0;
    __half* hi = blockIdx.z ? hi1 : hi0;
    __half* lo = blockIdx.z ? lo1 : lo0;
    const int c  = blockIdx.x;
    const int mb = blockIdx.y;
    const int t  = threadIdx.x;
    const int j  = t & 7;
    char* hbase = (char*)hi + ((size_t)(mb * NCH + c)) * TILE_BYTES;
    char* lbase = (char*)lo + ((size_t)(mb * NCH + c)) * TILE_BYTES;

    #pragma unroll
    for (int g = 0; g < 8; g++) {
        int ml = g * 16 + (t >> 3);
        int m = mb * 128 + ml;
        float x[8];
        if (m < M) {
            float4 a = *(const float4*)(src + (size_t)m * CC + c * 64 + j * 8);
            float4 b = *(const float4*)(src + (size_t)m * CC + c * 64 + j * 8 + 4);
            x[0]=a.x; x[1]=a.y; x[2]=a.z; x[3]=a.w; x[4]=b.x; x[5]=b.y; x[6]=b.z; x[7]=b.w;
        } else {
            #pragma unroll
            for (int i = 0; i < 8; i++) x[i] = 0.0f;
        }
        __half h[8], l[8];
        #pragma unroll
        for (int i = 0; i < 8; i++) {
            h[i] = __float2half(x[i]);
            l[i] = __float2half((x[i] - __half2float(h[i])) * LO_SCALE);
        }
        uint32_t off = SMEM_SWIZZLE_128B((uint32_t)(ml * 128 + j * 16));
        *(uint4*)(hbase + off) = *(uint4*)h;
        *(uint4*)(lbase + off) = *(uint4*)l;
    }
}

__global__ void __launch_bounds__(512)
pack_weights_all(const float* __restrict__ Wq, const float* __restrict__ Wkv,
                 const float* __restrict__ Woff, const float* __restrict__ Wout,
                 __half* __restrict__ wq, __half* __restrict__ wk,
                 __half* __restrict__ wfh, __half* __restrict__ wfl,
                 __half* __restrict__ wo)
{
    __shared__ float ts[64][129];
    const int c = blockIdx.x;
    const int y = blockIdx.y;
    const int t = threadIdx.x;

    const float* W; int ldw, nb; __half *hi, *lo;
    if (y < 8)       { W = Wq;   ldw = CC;     nb = y;      hi = wq;  lo = nullptr; }
    else if (y < 16) { W = Wkv;  ldw = 2 * CC; nb = y - 8;  hi = wk;  lo = nullptr; }
    else if (y < 17) { W = Woff; ldw = 128;    nb = 0;      hi = wfh; lo = wfl; }
    else             { W = Wout; ldw = CC;     nb = y - 17; hi = wo;  lo = nullptr; }

    const int k0 = c * 64;
    const int n0 = nb * 128;
    const int lrow = t >> 7;
    const int lcol = t & 127;
    #pragma unroll
    for (int i = 0; i < 16; i++) {
        int row = i * 4 + lrow;
        ts[row][lcol] = W[(size_t)(k0 + row) * ldw + n0 + lcol];
    }
    __syncthreads();

    char* hbase = (char*)hi + ((size_t)(nb * NCH + c)) * TILE_BYTES;
    char* lbase = lo ? (char*)lo + ((size_t)(nb * NCH + c)) * TILE_BYTES : nullptr;
    #pragma unroll
    for (int it = 0; it < 2; it++) {
        int idx = t + it * 512;
        int nl = idx >> 3;
        int j  = idx & 7;
        __half h[8], l[8];
        #pragma unroll
        for (int jj = 0; jj < 8; jj++) {
            float x = ts[j * 8 + jj][nl];
            h[jj] = __float2half(x);
            l[jj] = __float2half((x - __half2float(h[jj])) * LO_SCALE);
        }
        uint32_t off = SMEM_SWIZZLE_128B((uint32_t)(nl * 128 + j * 16));
        *(uint4*)(hbase + off) = *(uint4*)h;
        if (lbase) *(uint4*)(lbase + off) = *(uint4*)l;
    }
}

// ===== FUSED q+k+off GEMM: 1D grid of 774 CTAs. =====
__global__ void __launch_bounds__(128, 1)
gemm_fused(const char* __restrict__ QAh, const char* __restrict__ QAl,
           const char* __restrict__ RAh, const char* __restrict__ RAl,
           const char* __restrict__ WqB, const char* __restrict__ WkB,
           const char* __restrict__ WfH, const char* __restrict__ WfL,
           const float* __restrict__ bq, const float* __restrict__ bkv,
           const float* __restrict__ boff,
           float* __restrict__ outQ, __half* __restrict__ outK,
           float* __restrict__ outOff)
{
#if HAS_TCGEN05
    constexpr uint32_t SB = 4 * TILE_BYTES;
    constexpr uint32_t HDR = 1024;

    extern __shared__ char smem[];
    uint32_t sb = smem_to_u32(smem);
    const int tid = threadIdx.x;
    const int wid = tid >> 5;
    const int lane = tid & 31;
    const int bid = blockIdx.x;

    const int seg = (bid < 344) ? 0 : (bid < 688 ? 1 : 2);
    const bool isOff = (seg == 2);
    const int nt = isOff ? 128 : 256;
    const int my = isOff ? (bid - 688) : ((seg ? bid - 344 : bid) >> 2);
    const int ntile = isOff ? 0 : ((seg ? bid - 344 : bid) & 3);
    const int m0 = my * 128;
    const int n0 = ntile * 256;
    const uint32_t idesc = 0x8000010u | ((uint32_t)(nt / 8) << 17);

    const char* Ah = (seg == 1) ? RAh : QAh;
    const char* Al = (seg == 1) ? RAl : QAl;
    const float* bias = (seg == 0) ? bq : (seg == 1 ? bkv : boff);

    if (wid == 0) TCGEN05_ALLOC(sb + 0, 512);
    if (tid == 0) {
        MBARRIER_INIT(sb + 16, 1);
        MBARRIER_INIT(sb + 24, 1);
        MBARRIER_INIT(sb + 32, 1);
        MBARRIER_INIT(sb + 48, 1);
        MBARRIER_INIT(sb + 56, 1);
        MBARRIER_INIT(sb + 64, 1);
    }
    __syncthreads();
    uint32_t tmem;
    asm volatile("ld.shared.b32 %0, [%1];" : "=r"(tmem) : "r"(sb));

    if (tid == 0) {
        for (int c = 0; c < NCH; c++) {
            int s = c % 3;
            MBARRIER_WAIT_PARITY(sb + 16 + 8u * s, (uint32_t)((c / 3) & 1));
            uint32_t st = sb + HDR + (uint32_t)s * SB;
            uint64_t ahd = MAKE_SMEM_DESC(st);
            uint64_t ald = MAKE_SMEM_DESC(st + TILE_BYTES);
            uint64_t bhd = MAKE_SMEM_DESC(st + 2 * TILE_BYTES);
            #pragma unroll
            for (int ks = 0; ks < 4; ks++)
                mma_f16_ss(tmem, ahd + ks * 2, bhd + ks * 2, idesc, !(c == 0 && ks == 0));
            #pragma unroll
            for (int ks = 0; ks < 4; ks++)
                mma_f16_ss(tmem + nt, ald + ks * 2, bhd + ks * 2, idesc, !(c == 0 && ks == 0));
            if (isOff) {
                uint64_t bld = MAKE_SMEM_DESC(st + 3 * TILE_BYTES);
                #pragma unroll
                for (int ks = 0; ks < 4; ks++)
                    mma_f16_ss(tmem + nt, ahd + ks * 2, bld + ks * 2, idesc, true);
            }
            TCGEN05_COMMIT(sb + 48 + 8u * s);
        }
        for (int c = NCH - 3; c < NCH; c++)
            MBARRIER_WAIT_PARITY(sb + 48 + 8u * (c % 3), (uint32_t)((c / 3) & 1));
    } else if (tid == 32) {
        auto issue = [&](int c) {
            int s = c % 3;
            uint32_t fb = sb + 16 + 8u * s;
            uint32_t st = sb + HDR + (uint32_t)s * SB;
            MBARRIER_EXPECT_TX(fb, SB);
            size_t aoff = ((size_t)my * NCH + c) * TILE_BYTES;
            bulk_g2s(st, Ah + aoff, TILE_BYTES, fb);
            bulk_g2s(st + TILE_BYTES, Al + aoff, TILE_BYTES, fb);
            if (isOff) {
                size_t boff2 = (size_t)c * TILE_BYTES;
                bulk_g2s(st + 2 * TILE_BYTES, WfH + boff2, TILE_BYTES, fb);
                bulk_g2s(st + 3 * TILE_BYTES, WfL + boff2, TILE_BYTES, fb);
            } else {
                const char* B = (seg == 1) ? WkB : WqB;
                #pragma unroll
                for (int i = 0; i < 2; i++)
                    bulk_g2s(st + (2 + i) * TILE_BYTES,
                             B + ((size_t)(ntile * 2 + i) * NCH + c) * TILE_BYTES,
                             TILE_BYTES, fb);
            }
        };
        issue(0); issue(1); issue(2);
        for (int c = 3; c < NCH; c++) {
            int s = c % 3;
            MBARRIER_WAIT_PARITY(sb + 48 + 8u * s, (uint32_t)((c / 3 - 1) & 1));
            issue(c);
        }
    }
    __syncthreads();
    TCGEN05_FENCE_AFTER();

    float* buf = (float*)(smem + HDR) + wid * (32 * 33);
    for (int base = 0; base < nt; base += 32) {
        uint32_t r0[32], r1[32];
        TCGEN05_LD_32X32B_X32(r0, tmem + base);
        TCGEN05_LD_32X32B_X32(r1, tmem + nt + base);
        TCGEN05_WAIT_LD();
        #pragma unroll
        for (int q = 0; q < 32; q++)
            buf[lane * 33 + q] = __uint_as_float(r0[q]) + __uint_as_float(r1[q]) * LO_INV;
        __syncwarp();
        float bv = bias[n0 + base + lane];
        if (seg == 0) {
            #pragma unroll 4
            for (int rr = 0; rr < 32; rr++) {
                int gm = m0 + wid * 32 + rr;
                if (gm < BN) outQ[(size_t)gm * CC + n0 + base + lane] = buf[rr * 33 + lane] + bv;
            }
        } else if (seg == 1) {
            #pragma unroll 4
            for (int rr = 0; rr < 32; rr++) {
                int gm = m0 + wid * 32 + rr;
                if (gm < BN) outK[(size_t)gm * CC + n0 + base + lane] = __float2half(buf[rr * 33 + lane] + bv);
            }
        } else {
            #pragma unroll 4
            for (int rr = 0; rr < 32; rr++) {
                int gm = m0 + wid * 32 + rr;
                if (gm < BN) outOff[(size_t)gm * 128 + base + lane] = buf[rr * 33 + lane] + bv;
            }
        }
        __syncwarp();
    }
    TCGEN05_FENCE_BEFORE();
    __syncthreads();
    if (wid == 0) {
        TCGEN05_RELINQUISH_ALLOC_PERMIT();
        TCGEN05_DEALLOC(tmem, 512);
    }
#endif
}

// ===== cg1 GEMM for the out projection (NT=256, B single) =====
template <int NT, int BPARTS, typename TOut>
__global__ void __launch_bounds__(128, 1)
gemm_tc(const char* __restrict__ Ah, const char* __restrict__ Al,
        const char* __restrict__ Bh, const char* __restrict__ Bl,
        const float* __restrict__ bias, TOut* __restrict__ C, int M, int Ncols)
{
#if HAS_TCGEN05
    constexpr int NBB = NT / 128;
    constexpr int NBT = BPARTS * NBB;
    constexpr uint32_t SB = (2 + NBT) * TILE_BYTES;
    constexpr uint32_t HDR = 1024;
    constexpr uint32_t IDESC = 0x8000010u | ((NT / 8) << 17);

    extern __shared__ char smem[];
    uint32_t sb = smem_to_u32(smem);
    const int tid = threadIdx.x;
    const int wid = tid >> 5;
    const int lane = tid & 31;
    const int m0 = blockIdx.y * 128;
    const int n0 = blockIdx.x * NT;

    if (wid == 0) TCGEN05_ALLOC(sb + 0, 512);
    if (tid == 0) {
        MBARRIER_INIT(sb + 16, 1);
        MBARRIER_INIT(sb + 24, 1);
        MBARRIER_INIT(sb + 32, 1);
        MBARRIER_INIT(sb + 48, 1);
        MBARRIER_INIT(sb + 56, 1);
        MBARRIER_INIT(sb + 64, 1);
    }
    __syncthreads();
    uint32_t tmem;
    asm volatile("ld.shared.b32 %0, [%1];" : "=r"(tmem) : "r"(sb));

    if (tid == 0) {
        for (int c = 0; c < NCH; c++) {
            int s = c % 3;
            MBARRIER_WAIT_PARITY(sb + 16 + 8u * s, (uint32_t)((c / 3) & 1));
            uint32_t st = sb + HDR + (uint32_t)s * SB;
            uint64_t ahd = MAKE_SMEM_DESC(st);
            uint64_t ald = MAKE_SMEM_DESC(st + TILE_BYTES);
            uint64_t bhd = MAKE_SMEM_DESC(st + 2 * TILE_BYTES);
            #pragma unroll
            for (int ks = 0; ks < 4; ks++)
                mma_f16_ss(tmem, ahd + ks * 2, bhd + ks * 2, IDESC, !(c == 0 && ks == 0));
            #pragma unroll
            for (int ks = 0; ks < 4; ks++)
                mma_f16_ss(tmem + NT, ald + ks * 2, bhd + ks * 2, IDESC, !(c == 0 && ks == 0));
            if (BPARTS == 2) {
                uint64_t bld = MAKE_SMEM_DESC(st + 3 * TILE_BYTES);
                #pragma unroll
                for (int ks = 0; ks < 4; ks++)
                    mma_f16_ss(tmem + NT, ahd + ks * 2, bld + ks * 2, IDESC, true);
            }
            TCGEN05_COMMIT(sb + 48 + 8u * s);
        }
        for (int c = NCH - 3; c < NCH; c++)
            MBARRIER_WAIT_PARITY(sb + 48 + 8u * (c % 3), (uint32_t)((c / 3) & 1));
    } else if (tid == 32) {
        auto issue = [&](int c) {
            int s = c % 3;
            uint32_t fb = sb + 16 + 8u * s;
            uint32_t st = sb + HDR + (uint32_t)s * SB;
            MBARRIER_EXPECT_TX(fb, SB);
            size_t aoff = ((size_t)blockIdx.y * NCH + c) * TILE_BYTES;
            bulk_g2s(st, Ah + aoff, TILE_BYTES, fb);
            bulk_g2s(st + TILE_BYTES, Al + aoff, TILE_BYTES, fb);
            #pragma unroll
            for (int i = 0; i < NBT; i++) {
                const char* src;
                if (BPARTS == 1)
                    src = Bh + ((size_t)(blockIdx.x * NBB + i) * NCH + c) * TILE_BYTES;
                else
                    src = (i == 0 ? Bh : Bl) + ((size_t)(blockIdx.x * NBB) * NCH + c) * TILE_BYTES;
                bulk_g2s(st + (2 + i) * TILE_BYTES, src, TILE_BYTES, fb);
            }
        };
        issue(0); issue(1); issue(2);
        for (int c = 3; c < NCH; c++) {
            int s = c % 3;
            MBARRIER_WAIT_PARITY(sb + 48 + 8u * s, (uint32_t)((c / 3 - 1) & 1));
            issue(c);
        }
    }
    __syncthreads();
    TCGEN05_FENCE_AFTER();

    float* buf = (float*)(smem + HDR) + wid * (32 * 33);
    #pragma unroll
    for (int base = 0; base < NT; base += 32) {
        uint32_t r0[32], r1[32];
        TCGEN05_LD_32X32B_X32(r0, tmem + base);
        TCGEN05_LD_32X32B_X32(r1, tmem + NT + base);
        TCGEN05_WAIT_LD();
        #pragma unroll
        for (int q = 0; q < 32; q++)
            buf[lane * 33 + q] = __uint_as_float(r0[q]) + __uint_as_float(r1[q]) * LO_INV;
        __syncwarp();
        float bv = bias[n0 + base + lane];
        #pragma unroll 4
        for (int rr = 0; rr < 32; rr++) {
            int gm = m0 + wid * 32 + rr;
            if (gm < M)
                C[(size_t)gm * Ncols + n0 + base + lane] = (TOut)(buf[rr * 33 + lane] + bv);
        }
        __syncwarp();
    }
    TCGEN05_FENCE_BEFORE();
    __syncthreads();
    if (wid == 0) {
        TCGEN05_RELINQUISH_ALLOC_PERMIT();
        TCGEN05_DEALLOC(tmem, 512);
    }
#endif
}

// ============================ Fallback SGEMM ============================
__global__ void sgemm_bias_kernel(const float* __restrict__ A,
                                  const float* __restrict__ Wt,
                                  const float* __restrict__ bias,
                                  float* __restrict__ C,
                                  int M, int Ncols, int K, int ldw)
{
    __shared__ float As[16][64];
    __shared__ float Bs[16][64];
    const int tid = threadIdx.x;
    const int tx = tid & 15;
    const int ty = tid >> 4;
    const int n0 = blockIdx.x * 64;
    const int m0 = blockIdx.y * 64;
    float acc[4][4] = {};
    for (int k0 = 0; k0 < K; k0 += 16) {
        #pragma unroll
        for (int i = 0; i < 4; i++) {
            int idx = tid + i * 256;
            int m  = idx >> 4, kk = idx & 15, gm = m0 + m;
            As[kk][m] = (gm < M) ? A[(size_t)gm * K + (k0 + kk)] : 0.0f;
        }
        #pragma unroll
        for (int i = 0; i < 4; i++) {
            int idx = tid + i * 256;
            int kk = idx >> 6, n = idx & 63, gn = n0 + n;
            Bs[kk][n] = (gn < Ncols) ? Wt[(size_t)(k0 + kk) * ldw + gn] : 0.0f;
        }
        __syncthreads();
        #pragma unroll
        for (int kk = 0; kk < 16; kk++) {
            float4 a = *(const float4*)&As[kk][ty * 4];
            float4 w = *(const float4*)&Bs[kk][tx * 4];
            acc[0][0] += a.x*w.x; acc[0][1] += a.x*w.y; acc[0][2] += a.x*w.z; acc[0][3] += a.x*w.w;
            acc[1][0] += a.y*w.x; acc[1][1] += a.y*w.y; acc[1][2] += a.y*w.z; acc[1][3] += a.y*w.w;
            acc[2][0] += a.z*w.x; acc[2][1] += a.z*w.y; acc[2][2] += a.z*w.z; acc[2][3] += a.z*w.w;
            acc[3][0] += a.w*w.x; acc[3][1] += a.w*w.y; acc[3][2] += a.w*w.z; acc[3][3] += a.w*w.w;
        }
        __syncthreads();
    }
    #pragma unroll
    for (int r = 0; r < 4; r++) {
        int gm = m0 + ty * 4 + r;
        if (gm >= M) continue;
        #pragma unroll
        for (int c = 0; c < 4; c++) {
            int gn = n0 + tx * 4 + c;
            if (gn < Ncols) C[(size_t)gm * Ncols + gn] = acc[r][c] + bias[gn];
        }
    }
}

// ======= Attention (warp per (bn,h)), fp16 k gathers, hoisted coordinates =======
// Lane l computes coords for point l&7 ONCE (identical ops/order as the old
// per-point computation -> bit-exact); the per-point loop shuffles them in.
__global__ void attn_warp_kernel()
{
    const int bn = blockIdx.x;
    const int h  = threadIdx.x >> 5;
    const int lane = threadIdx.x & 31;

    const int b = bn / NPIX;
    const int n = bn % NPIX;
    const int row = n / WSP;
    const int col = n % WSP;
    const float step = 2.0f / 36.0f;
    const float ybase = -1.0f + row * step;
    const float xbase = -1.0f + col * step;

    float4 q4 = *(const float4*)(g_q + (size_t)bn * CC + h * HD + lane * 4);
    const __half* kbase = g_kh + (size_t)b * NPIX * CC + h * HD + lane * 4;

    float offv = 0.0f;
    if (lane < 16) offv = g_off[(size_t)bn * (HEADS * PTS * 2) + h * (PTS * 2) + lane];

    // ---- per-point coords computed once, in lane (l & 7) ----
    const int pp2 = (lane & 7) * 2;
    float o0 = __shfl_sync(0xffffffffu, offv, pp2);
    float o1 = __shfl_sync(0xffffffffu, offv, pp2 + 1);
    float xn = ybase + o0;
    float yn = xbase + o1;
    float ix = fminf(fmaxf((xn + 1.0f) * 0.5f * (WSP - 1), 0.0f), (float)(WSP - 1));
    float iy = fminf(fmaxf((yn + 1.0f) * 0.5f * (HSP - 1), 0.0f), (float)(HSP - 1));
    float x0f = floorf(ix), y0f = floorf(iy);
    float wxl = ix - x0f, wyl = iy - y0f;
    int x0 = (int)x0f, y0 = (int)y0f;
    int x1 = min(x0 + 1, WSP - 1);
    int y1 = min(y0 + 1, HSP - 1);
    int c00l = (y0 * WSP + x0) * CC;
    int c01l = (y0 * WSP + x1) * CC;
    int c10l = (y1 * WSP + x0) * CC;
    int c11l = (y1 * WSP + x1) * CC;

    float4 sv[PTS];
    float sc[PTS];
    #pragma unroll
    for (int p = 0; p < PTS; p++) {
        int i00 = __shfl_sync(0xffffffffu, c00l, p);
        int i01 = __shfl_sync(0xffffffffu, c01l, p);
        int i10 = __shfl_sync(0xffffffffu, c10l, p);
        int i11 = __shfl_sync(0xffffffffu, c11l, p);
        float wx = __shfl_sync(0xffffffffu, wxl, p);
        float wy = __shfl_sync(0xffffffffu, wyl, p);

        uint2 u00 = *(const uint2*)(kbase + i00);
        uint2 u01 = *(const uint2*)(kbase + i01);
        uint2 u10 = *(const uint2*)(kbase + i10);
        uint2 u11 = *(const uint2*)(kbase + i11);
        float2 a00 = __half22float2(*(__half2*)&u00.x), b00 = __half22float2(*(__half2*)&u00.y);
        float2 a01 = __half22float2(*(__half2*)&u01.x), b01 = __half22float2(*(__half2*)&u01.y);
        float2 a10 = __half22float2(*(__half2*)&u10.x), b10 = __half22float2(*(__half2*)&u10.y);
        float2 a11 = __half22float2(*(__half2*)&u11.x), b11 = __half22float2(*(__half2*)&u11.y);

        float w00 = (1.0f - wy) * (1.0f - wx), w01 = (1.0f - wy) * wx;
        float w10 = wy * (1.0f - wx), w11 = wy * wx;
        float4 s;
        s.x = w00*a00.x + w01*a01.x + w10*a10.x + w11*a11.x;
        s.y = w00*a00.y + w01*a01.y + w10*a10.y + w11*a11.y;
        s.z = w00*b00.x + w01*b01.x + w10*b10.x + w11*b11.x;
        s.w = w00*b00.y + w01*b01.y + w10*b10.y + w11*b11.y;
        sv[p] = s;

        float d = q4.x*s.x + q4.y*s.y + q4.z*s.z + q4.w*s.w;
        #pragma unroll
        for (int o = 16; o; o >>= 1) d += __shfl_xor_sync(0xffffffffu, d, o);
        sc[p] = d * 0.088388347648318447f;
    }

    float m = sc[0];
    #pragma unroll
    for (int p = 1; p < PTS; p++) m = fmaxf(m, sc[p]);
    float e[PTS], denom = 0.0f;
    #pragma unroll
    for (int p = 0; p < PTS; p++) { e[p] = expf(sc[p] - m); denom += e[p]; }
    float inv = 1.0f / denom;

    float4 o = make_float4(0, 0, 0, 0);
    #pragma unroll
    for (int p = 0; p < PTS; p++) {
        float w = e[p] * inv;
        o.x += w * sv[p].x; o.y += w * sv[p].y; o.z += w * sv[p].z; o.w += w * sv[p].w;
    }

    int k = h * HD + lane * 4;
    int mb = bn >> 7, ml = bn & 127;
    int c = k >> 6, kl = k & 63;
    size_t tbase = ((size_t)(mb * NCH + c)) * TILE_BYTES;
    uint32_t off = SMEM_SWIZZLE_128B((uint32_t)(ml * 128 + kl * 2));

    __half h4[4], l4[4];
    float ov[4] = {o.x, o.y, o.z, o.w};
    #pragma unroll
    for (int i = 0; i < 4; i++) {
        h4[i] = __float2half(ov[i]);
        l4[i] = __float2half((ov[i] - __half2float(h4[i])) * LO_SCALE);
    }
    *(uint2*)((char*)g_ah + tbase + off) = *(uint2*)h4;
    *(uint2*)((char*)g_al + tbase + off) = *(uint2*)l4;
}

// Fallback attention (fp32 k, fp32 output to g_attn)
__global__ void attn_kernel(float* __restrict__ out)
{
    const int bn = blockIdx.x;
    const int h  = blockIdx.y;
    const int t  = threadIdx.x;
    const int lane = t & 31;
    const int wid  = t >> 5;
    const int b = bn / NPIX;
    const int n = bn % NPIX;
    const int row = n / WSP;
    const int col = n % WSP;
    const float step = 2.0f / 36.0f;
    const float ybase = -1.0f + row * step;
    const float xbase = -1.0f + col * step;
    const float qv = g_q[(size_t)bn * CC + h * HD + t];
    const float* kbase = g_k + (size_t)b * NPIX * CC + h * HD + t;
    const float* offp  = g_off + (size_t)bn * (HEADS * PTS * 2) + h * (PTS * 2);
    float sv[PTS];
    __shared__ float red[PTS][4];
    __shared__ float sc[PTS];
    #pragma unroll
    for (int p = 0; p < PTS; p++) {
        float o0 = offp[p * 2 + 0], o1 = offp[p * 2 + 1];
        float xn = ybase + o0, yn = xbase + o1;
        float ix = fminf(fmaxf((xn + 1.0f) * 0.5f * (WSP - 1), 0.0f), (float)(WSP - 1));
        float iy = fminf(fmaxf((yn + 1.0f) * 0.5f * (HSP - 1), 0.0f), (float)(HSP - 1));
        float x0f = floorf(ix), y0f = floorf(iy);
        float wx = ix - x0f, wy = iy - y0f;
        int x0 = (int)x0f, y0 = (int)y0f;
        int x1 = min(x0 + 1, WSP - 1), y1 = min(y0 + 1, HSP - 1);
        float v00 = kbase[(size_t)(y0 * WSP + x0) * CC];
        float v01 = kbase[(size_t)(y0 * WSP + x1) * CC];
        float v10 = kbase[(size_t)(y1 * WSP + x0) * CC];
        float v11 = kbase[(size_t)(y1 * WSP + x1) * CC];
        float s = (1.0f - wy) * ((1.0f - wx) * v00 + wx * v01)
                +          wy * ((1.0f - wx) * v10 + wx * v11);
        sv[p] = s;
        float d = qv * s;
        #pragma unroll
        for (int o = 16; o; o >>= 1) d += __shfl_down_sync(0xffffffffu, d, o);
        if (lane == 0) red[p][wid] = d;
    }
    __syncthreads();
    if (t < PTS) sc[t] = (red[t][0] + red[t][1] + red[t][2] + red[t][3]) * 0.088388347648318447f;
    __syncthreads();
    float m = sc[0];
    #pragma unroll
    for (int p = 1; p < PTS; p++) m = fmaxf(m, sc[p]);
    float e[PTS], denom = 0.0f;
    #pragma unroll
    for (int p = 0; p < PTS; p++) { e[p] = expf(sc[p] - m); denom += e[p]; }
    float inv = 1.0f / denom;
    float o = 0.0f;
    #pragma unroll
    for (int p = 0; p < PTS; p++) o += e[p] * inv * sv[p];
    out[(size_t)bn * CC + h * HD + t] = o;
}

// ============================ Launch ============================
extern "C" void kernel_launch(void* const* d_in, const int* in_sizes, int n_in,
                              void* d_out, int out_size)
{
    const float* query = (const float*)d_in[0];
    const float* ref   = (const float*)d_in[1];
    const float* Wq    = (const float*)d_in[2];
    const float* bq    = (const float*)d_in[3];
    const float* Wkv   = (const float*)d_in[4];
    const float* bkv   = (const float*)d_in[5];
    const float* Woff  = (const float*)d_in[6];
    const float* boff  = (const float*)d_in[7];
    const float* Wout  = (const float*)d_in[8];
    const float* bout  = (const float*)d_in[9];
    float* out = (float*)d_out;

    float *q_ptr, *k_ptr, *off_ptr, *attn_ptr;
    __half* kh_ptr;
    cudaGetSymbolAddress((void**)&q_ptr,    g_q);
    cudaGetSymbolAddress((void**)&k_ptr,    g_k);
    cudaGetSymbolAddress((void**)&kh_ptr,   g_kh);
    cudaGetSymbolAddress((void**)&off_ptr,  g_off);
    cudaGetSymbolAddress((void**)&attn_ptr, g_attn);

    cudaFuncAttributes fa;
    cudaFuncGetAttributes(&fa, gemm_fused);
    bool use_tc = (fa.numRegs > 32);

    if (use_tc) {
        char *qh, *ql, *rh, *rl, *ah, *al;
        char *wq, *wk, *wo, *wfh, *wfl;
        cudaGetSymbolAddress((void**)&qh, g_qh);   cudaGetSymbolAddress((void**)&ql, g_ql);
        cudaGetSymbolAddress((void**)&rh, g_rh);   cudaGetSymbolAddress((void**)&rl, g_rl);
        cudaGetSymbolAddress((void**)&ah, g_ah);   cudaGetSymbolAddress((void**)&al, g_al);
        cudaGetSymbolAddress((void**)&wq, g_Wq);
        cudaGetSymbolAddress((void**)&wk, g_Wk);
        cudaGetSymbolAddress((void**)&wo, g_Wo);
        cudaGetSymbolAddress((void**)&wfh, g_Wf_h); cudaGetSymbolAddress((void**)&wfl, g_Wf_l);

        static bool attr_set = false;
        if (!attr_set) {
            cudaFuncSetAttribute(gemm_fused,              cudaFuncAttributeMaxDynamicSharedMemorySize, 197632);
            cudaFuncSetAttribute(gemm_tc<256, 1, float>,  cudaFuncAttributeMaxDynamicSharedMemorySize, 197632);
            attr_set = true;
        }

        split_act2_kernel<<<dim3(NCH, MBLK, 2), 128>>>(
            query, (__half*)qh, (__half*)ql,
            ref,   (__half*)rh, (__half*)rl, BN);
        pack_weights_all<<<dim3(NCH, 25), 512>>>(
            Wq, Wkv, Woff, Wout,
            (__half*)wq, (__half*)wk, (__half*)wfh, (__half*)wfl, (__half*)wo);

        gemm_fused<<<774, 128, 197632>>>(
            qh, ql, rh, rl, wq, wk, wfh, wfl, bq, bkv, boff,
            q_ptr, kh_ptr, off_ptr);

        attn_warp_kernel<<<BN, 256>>>();

        gemm_tc<256, 1, float><<<dim3(4, MBLK), 128, 197632>>>(ah, al, wo, nullptr, bout, out, BN, CC);
    } else {
        dim3 blk(256);
        dim3 gBig((CC + 63) / 64, (BN + 63) / 64);
        dim3 gOff((128 + 63) / 64, (BN + 63) / 64);
        sgemm_bias_kernel<<<gBig, blk>>>(query, Wq, bq, q_ptr, BN, CC, CC, CC);
        sgemm_bias_kernel<<<gBig, blk>>>(ref, Wkv, bkv, k_ptr, BN, CC, CC, 2 * CC);
        sgemm_bias_kernel<<<gOff, blk>>>(query, Woff, boff, off_ptr, BN, HEADS * PTS * 2, CC, HEADS * PTS * 2);
        attn_kernel<<<dim3(BN, HEADS), 128>>>(attn_ptr);
        sgemm_bias_kernel<<<gBig, blk>>>(attn_ptr, Wout, bout, out, BN, CC, CC, CC);
    }
}

// round 16
// speedup vs baseline: 1.6540x; 1.0754x over previous
#include <cuda_runtime.h>
#include <cuda_bf16.h>
#include <cuda_fp16.h>
#include <cstdint>
#include <math.h>

#define NB   8
#define HSP  37
#define WSP  37
#define NPIX 1369
#define BN   10952
#define CC   1024
#define HEADS 8
#define HD   128
#define PTS  8
#define MBLK 86
#define MPAD (MBLK * 128)   // 11008
#define NCH  16             // K chunks of 64
#define TILE_BYTES 16384    // 128 rows x 128B
#define LO_SCALE 1024.0f
#define LO_INV   0.0009765625f

#if defined(__CUDA_ARCH__) && (defined(__CUDA_ARCH_FEAT_SM103_ALL) || defined(__CUDA_ARCH_FEAT_SM100_ALL) || defined(__CUDA_ARCH_SPECIFIC__))
#define HAS_TCGEN05 1
#else
#define HAS_TCGEN05 0
#endif

#define SMEM_SWIZZLE_128B(byte_offset) ((byte_offset) ^ (((byte_offset) >> 3) & 0x70))

// ============================ Scratch ============================
__device__ float g_q[BN * CC];
__device__ float g_k[BN * CC];          // fallback path only
__device__ __half g_kh[BN * CC];        // tc path: k in fp16 for the gather
__device__ float g_off[BN * HEADS * PTS * 2];
__device__ float g_attn[BN * CC];

// Blocked+swizzled fp16 operands (16KB tiles, tile (r,c) at ((r*NCH)+c)*16KB)
__device__ __half g_qh[MPAD * CC];
__device__ __half g_ql[MPAD * CC];
__device__ __half g_rh[MPAD * CC];
__device__ __half g_rl[MPAD * CC];
__device__ __half g_ah[MPAD * CC];      // attention output (hi only now)
__device__ __half g_Wq[CC * CC];
__device__ __half g_Wk[CC * CC];
__device__ __half g_Wo[CC * CC];
__device__ __half g_Wf_h[128 * CC];
__device__ __half g_Wf_l[128 * CC];

// ============================ tcgen05 helpers (guarded) ============================
#if HAS_TCGEN05
__device__ __forceinline__ uint32_t smem_to_u32(const void* p) {
    uint32_t a;
    asm("{ .reg .u64 t; cvta.to.shared.u64 t, %1; cvt.u32.u64 %0, t; }" : "=r"(a) : "l"(p));
    return a;
}
#define TCGEN05_ALLOC(smem_result_addr, nCols) \
    asm volatile("tcgen05.alloc.cta_group::1.sync.aligned.shared::cta.b32 [%0], %1;" \
        :: "r"((uint32_t)(smem_result_addr)), "r"((uint32_t)(nCols)) : "memory")
#define TCGEN05_DEALLOC(tmem_addr, nCols) \
    asm volatile("tcgen05.dealloc.cta_group::1.sync.aligned.b32 %0, %1;" :: "r"(tmem_addr), "r"(nCols))
#define TCGEN05_RELINQUISH_ALLOC_PERMIT() \
    asm volatile("tcgen05.relinquish_alloc_permit.cta_group::1.sync.aligned;")
#define TCGEN05_COMMIT(mbar_smem_addr) \
    asm volatile("tcgen05.commit.cta_group::1.mbarrier::arrive::one.shared::cluster.b64 [%0];" \
        :: "r"((uint32_t)(mbar_smem_addr)) : "memory")
#define TCGEN05_WAIT_LD() asm volatile("tcgen05.wait::ld.sync.aligned;" ::: "memory")
#define TCGEN05_FENCE_AFTER() asm volatile("tcgen05.fence::after_thread_sync;" ::: "memory")
#define TCGEN05_FENCE_BEFORE() asm volatile("tcgen05.fence::before_thread_sync;" ::: "memory")
#define MBARRIER_INIT(mbar_smem_addr, count) \
    asm volatile("mbarrier.init.shared.b64 [%0], %1;" \
        :: "r"((uint32_t)(mbar_smem_addr)), "r"((uint32_t)(count)) : "memory")
#define MBARRIER_EXPECT_TX(mbar_smem_addr, tx_bytes) \
    asm volatile("mbarrier.arrive.expect_tx.shared.b64 _, [%0], %1;" \
        :: "r"((uint32_t)(mbar_smem_addr)), "r"((uint32_t)(tx_bytes)) : "memory")
#define MBARRIER_WAIT_PARITY(mbar_smem_addr, phase_parity) do { \
    uint32_t _mbar = (uint32_t)(mbar_smem_addr); \
    uint32_t _parity = (uint32_t)(phase_parity); \
    uint32_t _done; \
    asm volatile("{\n\t.reg .pred p;\n\t" \
        "mbarrier.try_wait.parity.acquire.cta.shared::cta.b64 p, [%1], %2;\n\t" \
        "selp.b32 %0, 1, 0, p;\n\t}" : "=r"(_done) : "r"(_mbar), "r"(_parity) : "memory"); \
    if (!_done) { \
        asm volatile("{\n\t.reg .pred P1;\n\t" \
            "WAIT_LOOP_%=:\n\t" \
            "mbarrier.try_wait.parity.acquire.cta.shared::cta.b64 P1, [%0], %1, 0x989680;\n\t" \
            "@P1 bra.uni WAIT_DONE_%=;\n\t" \
            "bra.uni WAIT_LOOP_%=;\n\t" \
            "WAIT_DONE_%=:\n\t}" :: "r"(_mbar), "r"(_parity) : "memory"); \
    } \
} while(0)
#define TCGEN05_LD_32X32B_X32(r, tmem_addr) \
    asm volatile("tcgen05.ld.sync.aligned.32x32b.x32.b32 " \
        "{%0, %1, %2, %3, %4, %5, %6, %7, %8, %9, %10, %11, %12, %13, %14, %15, " \
        " %16, %17, %18, %19, %20, %21, %22, %23, %24, %25, %26, %27, %28, %29, %30, %31}, [%32];" \
        : "=r"((r)[0]),  "=r"((r)[1]),  "=r"((r)[2]),  "=r"((r)[3]), \
          "=r"((r)[4]),  "=r"((r)[5]),  "=r"((r)[6]),  "=r"((r)[7]), \
          "=r"((r)[8]),  "=r"((r)[9]),  "=r"((r)[10]), "=r"((r)[11]), \
          "=r"((r)[12]), "=r"((r)[13]), "=r"((r)[14]), "=r"((r)[15]), \
          "=r"((r)[16]), "=r"((r)[17]), "=r"((r)[18]), "=r"((r)[19]), \
          "=r"((r)[20]), "=r"((r)[21]), "=r"((r)[22]), "=r"((r)[23]), \
          "=r"((r)[24]), "=r"((r)[25]), "=r"((r)[26]), "=r"((r)[27]), \
          "=r"((r)[28]), "=r"((r)[29]), "=r"((r)[30]), "=r"((r)[31]) \
        : "r"(tmem_addr))

static constexpr uint64_t SMEM_DESC_BASE_SW128 =
    (uint64_t(2)  << 61) | (uint64_t(1) << 46) | (uint64_t(64) << 32) | (uint64_t(1) << 16);
#define MAKE_SMEM_DESC(base_addr) (SMEM_DESC_BASE_SW128 | ((uint64_t)((base_addr) >> 4) & 0x3FFF))

__device__ __forceinline__ void mma_f16_ss(uint32_t d, uint64_t ad, uint64_t bd,
                                           uint32_t idesc, bool en) {
    uint32_t e = en ? 1u : 0u;
    asm volatile(
        "{\n\t.reg .pred p;\n\tsetp.ne.u32 p, %5, 0;\n\t"
        "tcgen05.mma.cta_group::1.kind::f16 [%0], %1, %2, %3, {%4, %4, %4, %4}, p;\n\t}"
        :: "r"(d), "l"(ad), "l"(bd), "r"(idesc), "r"(0u), "r"(e) : "memory");
}
__device__ __forceinline__ void bulk_g2s(uint32_t dst, const void* src, uint32_t bytes, uint32_t mbar) {
    asm volatile("cp.async.bulk.shared::cluster.global.mbarrier::complete_tx::bytes [%0], [%1], %2, [%3];"
        :: "r"(dst), "l"(src), "r"(bytes), "r"(mbar) : "memory");
}
#endif  // HAS_TCGEN05

// ============================ Pack kernels ============================
__global__ void split_act2_kernel(const float* __restrict__ src0,
                                  __half* __restrict__ hi0, __half* __restrict__ lo0,
                                  const float* __restrict__ src1,
                                  __half* __restrict__ hi1, __half* __restrict__ lo1, int M)
{
    const float* src = blockIdx.z ? src1 : src0;
    __half* hi = blockIdx.z ? hi1 : hi0;
    __half* lo = blockIdx.z ? lo1 : lo0;
    const int c  = blockIdx.x;
    const int mb = blockIdx.y;
    const int t  = threadIdx.x;
    const int j  = t & 7;
    char* hbase = (char*)hi + ((size_t)(mb * NCH + c)) * TILE_BYTES;
    char* lbase = (char*)lo + ((size_t)(mb * NCH + c)) * TILE_BYTES;

    #pragma unroll
    for (int g = 0; g < 8; g++) {
        int ml = g * 16 + (t >> 3);
        int m = mb * 128 + ml;
        float x[8];
        if (m < M) {
            float4 a = *(const float4*)(src + (size_t)m * CC + c * 64 + j * 8);
            float4 b = *(const float4*)(src + (size_t)m * CC + c * 64 + j * 8 + 4);
            x[0]=a.x; x[1]=a.y; x[2]=a.z; x[3]=a.w; x[4]=b.x; x[5]=b.y; x[6]=b.z; x[7]=b.w;
        } else {
            #pragma unroll
            for (int i = 0; i < 8; i++) x[i] = 0.0f;
        }
        __half h[8], l[8];
        #pragma unroll
        for (int i = 0; i < 8; i++) {
            h[i] = __float2half(x[i]);
            l[i] = __float2half((x[i] - __half2float(h[i])) * LO_SCALE);
        }
        uint32_t off = SMEM_SWIZZLE_128B((uint32_t)(ml * 128 + j * 16));
        *(uint4*)(hbase + off) = *(uint4*)h;
        *(uint4*)(lbase + off) = *(uint4*)l;
    }
}

__global__ void __launch_bounds__(512)
pack_weights_all(const float* __restrict__ Wq, const float* __restrict__ Wkv,
                 const float* __restrict__ Woff, const float* __restrict__ Wout,
                 __half* __restrict__ wq, __half* __restrict__ wk,
                 __half* __restrict__ wfh, __half* __restrict__ wfl,
                 __half* __restrict__ wo)
{
    __shared__ float ts[64][129];
    const int c = blockIdx.x;
    const int y = blockIdx.y;
    const int t = threadIdx.x;

    const float* W; int ldw, nb; __half *hi, *lo;
    if (y < 8)       { W = Wq;   ldw = CC;     nb = y;      hi = wq;  lo = nullptr; }
    else if (y < 16) { W = Wkv;  ldw = 2 * CC; nb = y - 8;  hi = wk;  lo = nullptr; }
    else if (y < 17) { W = Woff; ldw = 128;    nb = 0;      hi = wfh; lo = wfl; }
    else             { W = Wout; ldw = CC;     nb = y - 17; hi = wo;  lo = nullptr; }

    const int k0 = c * 64;
    const int n0 = nb * 128;
    const int lrow = t >> 7;
    const int lcol = t & 127;
    #pragma unroll
    for (int i = 0; i < 16; i++) {
        int row = i * 4 + lrow;
        ts[row][lcol] = W[(size_t)(k0 + row) * ldw + n0 + lcol];
    }
    __syncthreads();

    char* hbase = (char*)hi + ((size_t)(nb * NCH + c)) * TILE_BYTES;
    char* lbase = lo ? (char*)lo + ((size_t)(nb * NCH + c)) * TILE_BYTES : nullptr;
    #pragma unroll
    for (int it = 0; it < 2; it++) {
        int idx = t + it * 512;
        int nl = idx >> 3;
        int j  = idx & 7;
        __half h[8], l[8];
        #pragma unroll
        for (int jj = 0; jj < 8; jj++) {
            float x = ts[j * 8 + jj][nl];
            h[jj] = __float2half(x);
            l[jj] = __float2half((x - __half2float(h[jj])) * LO_SCALE);
        }
        uint32_t off = SMEM_SWIZZLE_128B((uint32_t)(nl * 128 + j * 16));
        *(uint4*)(hbase + off) = *(uint4*)h;
        if (lbase) *(uint4*)(lbase + off) = *(uint4*)l;
    }
}

// ===== FUSED q+k+off GEMM: 1D grid of 774 CTAs. =====
//   seg0 q:   A hi/lo, B single  (4 tiles/chunk)
//   seg1 k:   A hi ONLY, B single (3 tiles/chunk, 4 MMAs)  [k is fp16 anyway]
//   seg2 off: A hi/lo, B hi/lo   (4 tiles/chunk)
__global__ void __launch_bounds__(128, 1)
gemm_fused(const char* __restrict__ QAh, const char* __restrict__ QAl,
           const char* __restrict__ RAh,
           const char* __restrict__ WqB, const char* __restrict__ WkB,
           const char* __restrict__ WfH, const char* __restrict__ WfL,
           const float* __restrict__ bq, const float* __restrict__ bkv,
           const float* __restrict__ boff,
           float* __restrict__ outQ, __half* __restrict__ outK,
           float* __restrict__ outOff)
{
#if HAS_TCGEN05
    constexpr uint32_t SB = 4 * TILE_BYTES;   // smem stage stride (fixed)
    constexpr uint32_t HDR = 1024;

    extern __shared__ char smem[];
    uint32_t sb = smem_to_u32(smem);
    const int tid = threadIdx.x;
    const int wid = tid >> 5;
    const int lane = tid & 31;
    const int bid = blockIdx.x;

    const int seg = (bid < 344) ? 0 : (bid < 688 ? 1 : 2);
    const bool isOff = (seg == 2);
    const bool hasALo = (seg != 1);
    const int nt = isOff ? 128 : 256;
    const int my = isOff ? (bid - 688) : ((seg ? bid - 344 : bid) >> 2);
    const int ntile = isOff ? 0 : ((seg ? bid - 344 : bid) & 3);
    const int m0 = my * 128;
    const int n0 = ntile * 256;
    const uint32_t idesc = 0x8000010u | ((uint32_t)(nt / 8) << 17);
    const uint32_t txb = (hasALo ? 4u : 3u) * TILE_BYTES;

    const char* Ah = (seg == 1) ? RAh : QAh;
    const float* bias = (seg == 0) ? bq : (seg == 1 ? bkv : boff);

    if (wid == 0) TCGEN05_ALLOC(sb + 0, 512);
    if (tid == 0) {
        MBARRIER_INIT(sb + 16, 1);
        MBARRIER_INIT(sb + 24, 1);
        MBARRIER_INIT(sb + 32, 1);
        MBARRIER_INIT(sb + 48, 1);
        MBARRIER_INIT(sb + 56, 1);
        MBARRIER_INIT(sb + 64, 1);
    }
    __syncthreads();
    uint32_t tmem;
    asm volatile("ld.shared.b32 %0, [%1];" : "=r"(tmem) : "r"(sb));

    if (tid == 0) {
        for (int c = 0; c < NCH; c++) {
            int s = c % 3;
            MBARRIER_WAIT_PARITY(sb + 16 + 8u * s, (uint32_t)((c / 3) & 1));
            uint32_t st = sb + HDR + (uint32_t)s * SB;
            uint64_t ahd = MAKE_SMEM_DESC(st);
            uint64_t bhd = MAKE_SMEM_DESC(st + 2 * TILE_BYTES);
            #pragma unroll
            for (int ks = 0; ks < 4; ks++)
                mma_f16_ss(tmem, ahd + ks * 2, bhd + ks * 2, idesc, !(c == 0 && ks == 0));
            if (hasALo) {
                uint64_t ald = MAKE_SMEM_DESC(st + TILE_BYTES);
                #pragma unroll
                for (int ks = 0; ks < 4; ks++)
                    mma_f16_ss(tmem + nt, ald + ks * 2, bhd + ks * 2, idesc, !(c == 0 && ks == 0));
            }
            if (isOff) {
                uint64_t ald = MAKE_SMEM_DESC(st + TILE_BYTES);
                (void)ald;
                uint64_t bld = MAKE_SMEM_DESC(st + 3 * TILE_BYTES);
                #pragma unroll
                for (int ks = 0; ks < 4; ks++)
                    mma_f16_ss(tmem + nt, ahd + ks * 2, bld + ks * 2, idesc, true);
            }
            TCGEN05_COMMIT(sb + 48 + 8u * s);
        }
        for (int c = NCH - 3; c < NCH; c++)
            MBARRIER_WAIT_PARITY(sb + 48 + 8u * (c % 3), (uint32_t)((c / 3) & 1));
    } else if (tid == 32) {
        auto issue = [&](int c) {
            int s = c % 3;
            uint32_t fb = sb + 16 + 8u * s;
            uint32_t st = sb + HDR + (uint32_t)s * SB;
            MBARRIER_EXPECT_TX(fb, txb);
            size_t aoff = ((size_t)my * NCH + c) * TILE_BYTES;
            bulk_g2s(st, Ah + aoff, TILE_BYTES, fb);
            if (seg == 0) bulk_g2s(st + TILE_BYTES, QAl + aoff, TILE_BYTES, fb);
            else if (seg == 2) bulk_g2s(st + TILE_BYTES, QAl + aoff, TILE_BYTES, fb);
            if (isOff) {
                size_t boff2 = (size_t)c * TILE_BYTES;
                bulk_g2s(st + 2 * TILE_BYTES, WfH + boff2, TILE_BYTES, fb);
                bulk_g2s(st + 3 * TILE_BYTES, WfL + boff2, TILE_BYTES, fb);
            } else {
                const char* B = (seg == 1) ? WkB : WqB;
                #pragma unroll
                for (int i = 0; i < 2; i++)
                    bulk_g2s(st + (2 + i) * TILE_BYTES,
                             B + ((size_t)(ntile * 2 + i) * NCH + c) * TILE_BYTES,
                             TILE_BYTES, fb);
            }
        };
        issue(0); issue(1); issue(2);
        for (int c = 3; c < NCH; c++) {
            int s = c % 3;
            MBARRIER_WAIT_PARITY(sb + 48 + 8u * s, (uint32_t)((c / 3 - 1) & 1));
            issue(c);
        }
    }
    __syncthreads();
    TCGEN05_FENCE_AFTER();

    float* buf = (float*)(smem + HDR) + wid * (32 * 33);
    for (int base = 0; base < nt; base += 32) {
        uint32_t r0[32], r1[32];
        TCGEN05_LD_32X32B_X32(r0, tmem + base);
        if (hasALo) { TCGEN05_LD_32X32B_X32(r1, tmem + nt + base); }
        TCGEN05_WAIT_LD();
        if (hasALo) {
            #pragma unroll
            for (int q = 0; q < 32; q++)
                buf[lane * 33 + q] = __uint_as_float(r0[q]) + __uint_as_float(r1[q]) * LO_INV;
        } else {
            #pragma unroll
            for (int q = 0; q < 32; q++)
                buf[lane * 33 + q] = __uint_as_float(r0[q]);
        }
        __syncwarp();
        float bv = bias[n0 + base + lane];
        if (seg == 0) {
            #pragma unroll 4
            for (int rr = 0; rr < 32; rr++) {
                int gm = m0 + wid * 32 + rr;
                if (gm < BN) outQ[(size_t)gm * CC + n0 + base + lane] = buf[rr * 33 + lane] + bv;
            }
        } else if (seg == 1) {
            #pragma unroll 4
            for (int rr = 0; rr < 32; rr++) {
                int gm = m0 + wid * 32 + rr;
                if (gm < BN) outK[(size_t)gm * CC + n0 + base + lane] = __float2half(buf[rr * 33 + lane] + bv);
            }
        } else {
            #pragma unroll 4
            for (int rr = 0; rr < 32; rr++) {
                int gm = m0 + wid * 32 + rr;
                if (gm < BN) outOff[(size_t)gm * 128 + base + lane] = buf[rr * 33 + lane] + bv;
            }
        }
        __syncwarp();
    }
    TCGEN05_FENCE_BEFORE();
    __syncthreads();
    if (wid == 0) {
        TCGEN05_RELINQUISH_ALLOC_PERMIT();
        TCGEN05_DEALLOC(tmem, 512);
    }
#endif
}

// ===== out-GEMM: NT=256, A single (attention output fp16), B single =====
__global__ void __launch_bounds__(128, 1)
gemm_out(const char* __restrict__ Ah, const char* __restrict__ B,
         const float* __restrict__ bias, float* __restrict__ C)
{
#if HAS_TCGEN05
    constexpr int NT = 256;
    constexpr uint32_t SB = 3 * TILE_BYTES;   // A + 2 B tiles
    constexpr uint32_t HDR = 1024;
    constexpr uint32_t IDESC = 0x8000010u | ((NT / 8) << 17);

    extern __shared__ char smem[];
    uint32_t sb = smem_to_u32(smem);
    const int tid = threadIdx.x;
    const int wid = tid >> 5;
    const int lane = tid & 31;
    const int m0 = blockIdx.y * 128;
    const int n0 = blockIdx.x * NT;

    if (wid == 0) TCGEN05_ALLOC(sb + 0, 512);
    if (tid == 0) {
        MBARRIER_INIT(sb + 16, 1);
        MBARRIER_INIT(sb + 24, 1);
        MBARRIER_INIT(sb + 32, 1);
        MBARRIER_INIT(sb + 48, 1);
        MBARRIER_INIT(sb + 56, 1);
        MBARRIER_INIT(sb + 64, 1);
    }
    __syncthreads();
    uint32_t tmem;
    asm volatile("ld.shared.b32 %0, [%1];" : "=r"(tmem) : "r"(sb));

    if (tid == 0) {
        for (int c = 0; c < NCH; c++) {
            int s = c % 3;
            MBARRIER_WAIT_PARITY(sb + 16 + 8u * s, (uint32_t)((c / 3) & 1));
            uint32_t st = sb + HDR + (uint32_t)s * SB;
            uint64_t ahd = MAKE_SMEM_DESC(st);
            uint64_t bhd = MAKE_SMEM_DESC(st + TILE_BYTES);
            #pragma unroll
            for (int ks = 0; ks < 4; ks++)
                mma_f16_ss(tmem, ahd + ks * 2, bhd + ks * 2, IDESC, !(c == 0 && ks == 0));
            TCGEN05_COMMIT(sb + 48 + 8u * s);
        }
        for (int c = NCH - 3; c < NCH; c++)
            MBARRIER_WAIT_PARITY(sb + 48 + 8u * (c % 3), (uint32_t)((c / 3) & 1));
    } else if (tid == 32) {
        auto issue = [&](int c) {
            int s = c % 3;
            uint32_t fb = sb + 16 + 8u * s;
            uint32_t st = sb + HDR + (uint32_t)s * SB;
            MBARRIER_EXPECT_TX(fb, SB);
            size_t aoff = ((size_t)blockIdx.y * NCH + c) * TILE_BYTES;
            bulk_g2s(st, Ah + aoff, TILE_BYTES, fb);
            #pragma unroll
            for (int i = 0; i < 2; i++)
                bulk_g2s(st + (1 + i) * TILE_BYTES,
                         B + ((size_t)(blockIdx.x * 2 + i) * NCH + c) * TILE_BYTES,
                         TILE_BYTES, fb);
        };
        issue(0); issue(1); issue(2);
        for (int c = 3; c < NCH; c++) {
            int s = c % 3;
            MBARRIER_WAIT_PARITY(sb + 48 + 8u * s, (uint32_t)((c / 3 - 1) & 1));
            issue(c);
        }
    }
    __syncthreads();
    TCGEN05_FENCE_AFTER();

    float* buf = (float*)(smem + HDR) + wid * (32 * 33);
    #pragma unroll
    for (int base = 0; base < NT; base += 32) {
        uint32_t r0[32];
        TCGEN05_LD_32X32B_X32(r0, tmem + base);
        TCGEN05_WAIT_LD();
        #pragma unroll
        for (int q = 0; q < 32; q++)
            buf[lane * 33 + q] = __uint_as_float(r0[q]);
        __syncwarp();
        float bv = bias[n0 + base + lane];
        #pragma unroll 4
        for (int rr = 0; rr < 32; rr++) {
            int gm = m0 + wid * 32 + rr;
            if (gm < BN)
                C[(size_t)gm * CC + n0 + base + lane] = buf[rr * 33 + lane] + bv;
        }
        __syncwarp();
    }
    TCGEN05_FENCE_BEFORE();
    __syncthreads();
    if (wid == 0) {
        TCGEN05_RELINQUISH_ALLOC_PERMIT();
        TCGEN05_DEALLOC(tmem, 512);
    }
#endif
}

// ============================ Fallback SGEMM ============================
__global__ void sgemm_bias_kernel(const float* __restrict__ A,
                                  const float* __restrict__ Wt,
                                  const float* __restrict__ bias,
                                  float* __restrict__ C,
                                  int M, int Ncols, int K, int ldw)
{
    __shared__ float As[16][64];
    __shared__ float Bs[16][64];
    const int tid = threadIdx.x;
    const int tx = tid & 15;
    const int ty = tid >> 4;
    const int n0 = blockIdx.x * 64;
    const int m0 = blockIdx.y * 64;
    float acc[4][4] = {};
    for (int k0 = 0; k0 < K; k0 += 16) {
        #pragma unroll
        for (int i = 0; i < 4; i++) {
            int idx = tid + i * 256;
            int m  = idx >> 4, kk = idx & 15, gm = m0 + m;
            As[kk][m] = (gm < M) ? A[(size_t)gm * K + (k0 + kk)] : 0.0f;
        }
        #pragma unroll
        for (int i = 0; i < 4; i++) {
            int idx = tid + i * 256;
            int kk = idx >> 6, n = idx & 63, gn = n0 + n;
            Bs[kk][n] = (gn < Ncols) ? Wt[(size_t)(k0 + kk) * ldw + gn] : 0.0f;
        }
        __syncthreads();
        #pragma unroll
        for (int kk = 0; kk < 16; kk++) {
            float4 a = *(const float4*)&As[kk][ty * 4];
            float4 w = *(const float4*)&Bs[kk][tx * 4];
            acc[0][0] += a.x*w.x; acc[0][1] += a.x*w.y; acc[0][2] += a.x*w.z; acc[0][3] += a.x*w.w;
            acc[1][0] += a.y*w.x; acc[1][1] += a.y*w.y; acc[1][2] += a.y*w.z; acc[1][3] += a.y*w.w;
            acc[2][0] += a.z*w.x; acc[2][1] += a.z*w.y; acc[2][2] += a.z*w.z; acc[2][3] += a.z*w.w;
            acc[3][0] += a.w*w.x; acc[3][1] += a.w*w.y; acc[3][2] += a.w*w.z; acc[3][3] += a.w*w.w;
        }
        __syncthreads();
    }
    #pragma unroll
    for (int r = 0; r < 4; r++) {
        int gm = m0 + ty * 4 + r;
        if (gm >= M) continue;
        #pragma unroll
        for (int c = 0; c < 4; c++) {
            int gn = n0 + tx * 4 + c;
            if (gn < Ncols) C[(size_t)gm * Ncols + gn] = acc[r][c] + bias[gn];
        }
    }
}

// ======= Attention (warp per (bn,h)), fp16 k gathers, hoisted coords, hi-only out ==
__global__ void attn_warp_kernel()
{
    const int bn = blockIdx.x;
    const int h  = threadIdx.x >> 5;
    const int lane = threadIdx.x & 31;

    const int b = bn / NPIX;
    const int n = bn % NPIX;
    const int row = n / WSP;
    const int col = n % WSP;
    const float step = 2.0f / 36.0f;
    const float ybase = -1.0f + row * step;
    const float xbase = -1.0f + col * step;

    float4 q4 = *(const float4*)(g_q + (size_t)bn * CC + h * HD + lane * 4);
    const __half* kbase = g_kh + (size_t)b * NPIX * CC + h * HD + lane * 4;

    float offv = 0.0f;
    if (lane < 16) offv = g_off[(size_t)bn * (HEADS * PTS * 2) + h * (PTS * 2) + lane];

    const int pp2 = (lane & 7) * 2;
    float o0 = __shfl_sync(0xffffffffu, offv, pp2);
    float o1 = __shfl_sync(0xffffffffu, offv, pp2 + 1);
    float xn = ybase + o0;
    float yn = xbase + o1;
    float ix = fminf(fmaxf((xn + 1.0f) * 0.5f * (WSP - 1), 0.0f), (float)(WSP - 1));
    float iy = fminf(fmaxf((yn + 1.0f) * 0.5f * (HSP - 1), 0.0f), (float)(HSP - 1));
    float x0f = floorf(ix), y0f = floorf(iy);
    float wxl = ix - x0f, wyl = iy - y0f;
    int x0 = (int)x0f, y0 = (int)y0f;
    int x1 = min(x0 + 1, WSP - 1);
    int y1 = min(y0 + 1, HSP - 1);
    int c00l = (y0 * WSP + x0) * CC;
    int c01l = (y0 * WSP + x1) * CC;
    int c10l = (y1 * WSP + x0) * CC;
    int c11l = (y1 * WSP + x1) * CC;

    float4 sv[PTS];
    float sc[PTS];
    #pragma unroll
    for (int p = 0; p < PTS; p++) {
        int i00 = __shfl_sync(0xffffffffu, c00l, p);
        int i01 = __shfl_sync(0xffffffffu, c01l, p);
        int i10 = __shfl_sync(0xffffffffu, c10l, p);
        int i11 = __shfl_sync(0xffffffffu, c11l, p);
        float wx = __shfl_sync(0xffffffffu, wxl, p);
        float wy = __shfl_sync(0xffffffffu, wyl, p);

        uint2 u00 = *(const uint2*)(kbase + i00);
        uint2 u01 = *(const uint2*)(kbase + i01);
        uint2 u10 = *(const uint2*)(kbase + i10);
        uint2 u11 = *(const uint2*)(kbase + i11);
        float2 a00 = __half22float2(*(__half2*)&u00.x), b00 = __half22float2(*(__half2*)&u00.y);
        float2 a01 = __half22float2(*(__half2*)&u01.x), b01 = __half22float2(*(__half2*)&u01.y);
        float2 a10 = __half22float2(*(__half2*)&u10.x), b10 = __half22float2(*(__half2*)&u10.y);
        float2 a11 = __half22float2(*(__half2*)&u11.x), b11 = __half22float2(*(__half2*)&u11.y);

        float w00 = (1.0f - wy) * (1.0f - wx), w01 = (1.0f - wy) * wx;
        float w10 = wy * (1.0f - wx), w11 = wy * wx;
        float4 s;
        s.x = w00*a00.x + w01*a01.x + w10*a10.x + w11*a11.x;
        s.y = w00*a00.y + w01*a01.y + w10*a10.y + w11*a11.y;
        s.z = w00*b00.x + w01*b01.x + w10*b10.x + w11*b11.x;
        s.w = w00*b00.y + w01*b01.y + w10*b10.y + w11*b11.y;
        sv[p] = s;

        float d = q4.x*s.x + q4.y*s.y + q4.z*s.z + q4.w*s.w;
        #pragma unroll
        for (int o = 16; o; o >>= 1) d += __shfl_xor_sync(0xffffffffu, d, o);
        sc[p] = d * 0.088388347648318447f;
    }

    float m = sc[0];
    #pragma unroll
    for (int p = 1; p < PTS; p++) m = fmaxf(m, sc[p]);
    float e[PTS], denom = 0.0f;
    #pragma unroll
    for (int p = 0; p < PTS; p++) { e[p] = expf(sc[p] - m); denom += e[p]; }
    float inv = 1.0f / denom;

    float4 o = make_float4(0, 0, 0, 0);
    #pragma unroll
    for (int p = 0; p < PTS; p++) {
        float w = e[p] * inv;
        o.x += w * sv[p].x; o.y += w * sv[p].y; o.z += w * sv[p].z; o.w += w * sv[p].w;
    }

    int k = h * HD + lane * 4;
    int mb = bn >> 7, ml = bn & 127;
    int c = k >> 6, kl = k & 63;
    size_t tbase = ((size_t)(mb * NCH + c)) * TILE_BYTES;
    uint32_t off = SMEM_SWIZZLE_128B((uint32_t)(ml * 128 + kl * 2));

    __half h4[4];
    h4[0] = __float2half(o.x); h4[1] = __float2half(o.y);
    h4[2] = __float2half(o.z); h4[3] = __float2half(o.w);
    *(uint2*)((char*)g_ah + tbase + off) = *(uint2*)h4;
}

// Fallback attention (fp32 k, fp32 output to g_attn)
__global__ void attn_kernel(float* __restrict__ out)
{
    const int bn = blockIdx.x;
    const int h  = blockIdx.y;
    const int t  = threadIdx.x;
    const int lane = t & 31;
    const int wid  = t >> 5;
    const int b = bn / NPIX;
    const int n = bn % NPIX;
    const int row = n / WSP;
    const int col = n % WSP;
    const float step = 2.0f / 36.0f;
    const float ybase = -1.0f + row * step;
    const float xbase = -1.0f + col * step;
    const float qv = g_q[(size_t)bn * CC + h * HD + t];
    const float* kbase = g_k + (size_t)b * NPIX * CC + h * HD + t;
    const float* offp  = g_off + (size_t)bn * (HEADS * PTS * 2) + h * (PTS * 2);
    float sv[PTS];
    __shared__ float red[PTS][4];
    __shared__ float sc[PTS];
    #pragma unroll
    for (int p = 0; p < PTS; p++) {
        float o0 = offp[p * 2 + 0], o1 = offp[p * 2 + 1];
        float xn = ybase + o0, yn = xbase + o1;
        float ix = fminf(fmaxf((xn + 1.0f) * 0.5f * (WSP - 1), 0.0f), (float)(WSP - 1));
        float iy = fminf(fmaxf((yn + 1.0f) * 0.5f * (HSP - 1), 0.0f), (float)(HSP - 1));
        float x0f = floorf(ix), y0f = floorf(iy);
        float wx = ix - x0f, wy = iy - y0f;
        int x0 = (int)x0f, y0 = (int)y0f;
        int x1 = min(x0 + 1, WSP - 1), y1 = min(y0 + 1, HSP - 1);
        float v00 = kbase[(size_t)(y0 * WSP + x0) * CC];
        float v01 = kbase[(size_t)(y0 * WSP + x1) * CC];
        float v10 = kbase[(size_t)(y1 * WSP + x0) * CC];
        float v11 = kbase[(size_t)(y1 * WSP + x1) * CC];
        float s = (1.0f - wy) * ((1.0f - wx) * v00 + wx * v01)
                +          wy * ((1.0f - wx) * v10 + wx * v11);
        sv[p] = s;
        float d = qv * s;
        #pragma unroll
        for (int o = 16; o; o >>= 1) d += __shfl_down_sync(0xffffffffu, d, o);
        if (lane == 0) red[p][wid] = d;
    }
    __syncthreads();
    if (t < PTS) sc[t] = (red[t][0] + red[t][1] + red[t][2] + red[t][3]) * 0.088388347648318447f;
    __syncthreads();
    float m = sc[0];
    #pragma unroll
    for (int p = 1; p < PTS; p++) m = fmaxf(m, sc[p]);
    float e[PTS], denom = 0.0f;
    #pragma unroll
    for (int p = 0; p < PTS; p++) { e[p] = expf(sc[p] - m); denom += e[p]; }
    float inv = 1.0f / denom;
    float o = 0.0f;
    #pragma unroll
    for (int p = 0; p < PTS; p++) o += e[p] * inv * sv[p];
    out[(size_t)bn * CC + h * HD + t] = o;
}

// ============================ Launch ============================
extern "C" void kernel_launch(void* const* d_in, const int* in_sizes, int n_in,
                              void* d_out, int out_size)
{
    const float* query = (const float*)d_in[0];
    const float* ref   = (const float*)d_in[1];
    const float* Wq    = (const float*)d_in[2];
    const float* bq    = (const float*)d_in[3];
    const float* Wkv   = (const float*)d_in[4];
    const float* bkv   = (const float*)d_in[5];
    const float* Woff  = (const float*)d_in[6];
    const float* boff  = (const float*)d_in[7];
    const float* Wout  = (const float*)d_in[8];
    const float* bout  = (const float*)d_in[9];
    float* out = (float*)d_out;

    float *q_ptr, *k_ptr, *off_ptr, *attn_ptr;
    __half* kh_ptr;
    cudaGetSymbolAddress((void**)&q_ptr,    g_q);
    cudaGetSymbolAddress((void**)&k_ptr,    g_k);
    cudaGetSymbolAddress((void**)&kh_ptr,   g_kh);
    cudaGetSymbolAddress((void**)&off_ptr,  g_off);
    cudaGetSymbolAddress((void**)&attn_ptr, g_attn);

    cudaFuncAttributes fa;
    cudaFuncGetAttributes(&fa, gemm_fused);
    bool use_tc = (fa.numRegs > 32);

    if (use_tc) {
        char *qh, *ql, *rh, *rl, *ah;
        char *wq, *wk, *wo, *wfh, *wfl;
        cudaGetSymbolAddress((void**)&qh, g_qh);   cudaGetSymbolAddress((void**)&ql, g_ql);
        cudaGetSymbolAddress((void**)&rh, g_rh);   cudaGetSymbolAddress((void**)&rl, g_rl);
        cudaGetSymbolAddress((void**)&ah, g_ah);
        cudaGetSymbolAddress((void**)&wq, g_Wq);
        cudaGetSymbolAddress((void**)&wk, g_Wk);
        cudaGetSymbolAddress((void**)&wo, g_Wo);
        cudaGetSymbolAddress((void**)&wfh, g_Wf_h); cudaGetSymbolAddress((void**)&wfl, g_Wf_l);

        static bool attr_set = false;
        if (!attr_set) {
            cudaFuncSetAttribute(gemm_fused, cudaFuncAttributeMaxDynamicSharedMemorySize, 197632);
            cudaFuncSetAttribute(gemm_out,   cudaFuncAttributeMaxDynamicSharedMemorySize, 197632);
            attr_set = true;
        }

        // ref still packs hi/lo (lo unused by k now, but split_act2 writes both;
        // harmless — rl buffer exists). Could be trimmed later.
        split_act2_kernel<<<dim3(NCH, MBLK, 2), 128>>>(
            query, (__half*)qh, (__half*)ql,
            ref,   (__half*)rh, (__half*)rl, BN);
        pack_weights_all<<<dim3(NCH, 25), 512>>>(
            Wq, Wkv, Woff, Wout,
            (__half*)wq, (__half*)wk, (__half*)wfh, (__half*)wfl, (__half*)wo);

        gemm_fused<<<774, 128, 197632>>>(
            qh, ql, rh, wq, wk, wfh, wfl, bq, bkv, boff,
            q_ptr, kh_ptr, off_ptr);

        attn_warp_kernel<<<BN, 256>>>();

        gemm_out<<<dim3(4, MBLK), 128, 197632>>>(ah, wo, bout, out);
    } else {
        dim3 blk(256);
        dim3 gBig((CC + 63) / 64, (BN + 63) / 64);
        dim3 gOff((128 + 63) / 64, (BN + 63) / 64);
        sgemm_bias_kernel<<<gBig, blk>>>(query, Wq, bq, q_ptr, BN, CC, CC, CC);
        sgemm_bias_kernel<<<gBig, blk>>>(ref, Wkv, bkv, k_ptr, BN, CC, CC, 2 * CC);
        sgemm_bias_kernel<<<gOff, blk>>>(query, Woff, boff, off_ptr, BN, HEADS * PTS * 2, CC, HEADS * PTS * 2);
        attn_kernel<<<dim3(BN, HEADS), 128>>>(attn_ptr);
        sgemm_bias_kernel<<<gBig, blk>>>(attn_ptr, Wout, bout, out, BN, CC, CC, CC);
    }
}

// round 17
// speedup vs baseline: 1.8217x; 1.1014x over previous
#include <cuda_runtime.h>
#include <cuda_bf16.h>
#include <cuda_fp16.h>
#include <cstdint>
#include <math.h>

#define NB   8
#define HSP  37
#define WSP  37
#define NPIX 1369
#define BN   10952
#define CC   1024
#define HEADS 8
#define HD   128
#define PTS  8
#define MBLK 86
#define MPAD (MBLK * 128)   // 11008
#define NCH  16             // K chunks of 64
#define TILE_BYTES 16384    // 128 rows x 128B
#define LO_SCALE 1024.0f
#define LO_INV   0.0009765625f

#if defined(__CUDA_ARCH__) && (defined(__CUDA_ARCH_FEAT_SM103_ALL) || defined(__CUDA_ARCH_FEAT_SM100_ALL) || defined(__CUDA_ARCH_SPECIFIC__))
#define HAS_TCGEN05 1
#else
#define HAS_TCGEN05 0
#endif

#define SMEM_SWIZZLE_128B(byte_offset) ((byte_offset) ^ (((byte_offset) >> 3) & 0x70))

// ============================ Scratch ============================
__device__ float g_q[BN * CC];          // fallback path only
__device__ float g_k[BN * CC];          // fallback path only
__device__ __half g_qhf[BN * CC];       // tc path: q in fp16 for attention
__device__ __half g_kh[BN * CC];        // tc path: k in fp16 for the gather
__device__ float g_off[BN * HEADS * PTS * 2];
__device__ float g_attn[BN * CC];

// Blocked+swizzled fp16 operands (16KB tiles, tile (r,c) at ((r*NCH)+c)*16KB)
__device__ __half g_qh[MPAD * CC];
__device__ __half g_ql[MPAD * CC];      // q lo: used by the off segment only
__device__ __half g_rh[MPAD * CC];
__device__ __half g_ah[MPAD * CC];      // attention output (hi only)
__device__ __half g_Wq[CC * CC];
__device__ __half g_Wk[CC * CC];
__device__ __half g_Wo[CC * CC];
__device__ __half g_Wf_h[128 * CC];
__device__ __half g_Wf_l[128 * CC];

// ============================ tcgen05 helpers (guarded) ============================
#if HAS_TCGEN05
__device__ __forceinline__ uint32_t smem_to_u32(const void* p) {
    uint32_t a;
    asm("{ .reg .u64 t; cvta.to.shared.u64 t, %1; cvt.u32.u64 %0, t; }" : "=r"(a) : "l"(p));
    return a;
}
#define TCGEN05_ALLOC(smem_result_addr, nCols) \
    asm volatile("tcgen05.alloc.cta_group::1.sync.aligned.shared::cta.b32 [%0], %1;" \
        :: "r"((uint32_t)(smem_result_addr)), "r"((uint32_t)(nCols)) : "memory")
#define TCGEN05_DEALLOC(tmem_addr, nCols) \
    asm volatile("tcgen05.dealloc.cta_group::1.sync.aligned.b32 %0, %1;" :: "r"(tmem_addr), "r"(nCols))
#define TCGEN05_RELINQUISH_ALLOC_PERMIT() \
    asm volatile("tcgen05.relinquish_alloc_permit.cta_group::1.sync.aligned;")
#define TCGEN05_COMMIT(mbar_smem_addr) \
    asm volatile("tcgen05.commit.cta_group::1.mbarrier::arrive::one.shared::cluster.b64 [%0];" \
        :: "r"((uint32_t)(mbar_smem_addr)) : "memory")
#define TCGEN05_WAIT_LD() asm volatile("tcgen05.wait::ld.sync.aligned;" ::: "memory")
#define TCGEN05_FENCE_AFTER() asm volatile("tcgen05.fence::after_thread_sync;" ::: "memory")
#define TCGEN05_FENCE_BEFORE() asm volatile("tcgen05.fence::before_thread_sync;" ::: "memory")
#define MBARRIER_INIT(mbar_smem_addr, count) \
    asm volatile("mbarrier.init.shared.b64 [%0], %1;" \
        :: "r"((uint32_t)(mbar_smem_addr)), "r"((uint32_t)(count)) : "memory")
#define MBARRIER_EXPECT_TX(mbar_smem_addr, tx_bytes) \
    asm volatile("mbarrier.arrive.expect_tx.shared.b64 _, [%0], %1;" \
        :: "r"((uint32_t)(mbar_smem_addr)), "r"((uint32_t)(tx_bytes)) : "memory")
#define MBARRIER_WAIT_PARITY(mbar_smem_addr, phase_parity) do { \
    uint32_t _mbar = (uint32_t)(mbar_smem_addr); \
    uint32_t _parity = (uint32_t)(phase_parity); \
    uint32_t _done; \
    asm volatile("{\n\t.reg .pred p;\n\t" \
        "mbarrier.try_wait.parity.acquire.cta.shared::cta.b64 p, [%1], %2;\n\t" \
        "selp.b32 %0, 1, 0, p;\n\t}" : "=r"(_done) : "r"(_mbar), "r"(_parity) : "memory"); \
    if (!_done) { \
        asm volatile("{\n\t.reg .pred P1;\n\t" \
            "WAIT_LOOP_%=:\n\t" \
            "mbarrier.try_wait.parity.acquire.cta.shared::cta.b64 P1, [%0], %1, 0x989680;\n\t" \
            "@P1 bra.uni WAIT_DONE_%=;\n\t" \
            "bra.uni WAIT_LOOP_%=;\n\t" \
            "WAIT_DONE_%=:\n\t}" :: "r"(_mbar), "r"(_parity) : "memory"); \
    } \
} while(0)
#define TCGEN05_LD_32X32B_X32(r, tmem_addr) \
    asm volatile("tcgen05.ld.sync.aligned.32x32b.x32.b32 " \
        "{%0, %1, %2, %3, %4, %5, %6, %7, %8, %9, %10, %11, %12, %13, %14, %15, " \
        " %16, %17, %18, %19, %20, %21, %22, %23, %24, %25, %26, %27, %28, %29, %30, %31}, [%32];" \
        : "=r"((r)[0]),  "=r"((r)[1]),  "=r"((r)[2]),  "=r"((r)[3]), \
          "=r"((r)[4]),  "=r"((r)[5]),  "=r"((r)[6]),  "=r"((r)[7]), \
          "=r"((r)[8]),  "=r"((r)[9]),  "=r"((r)[10]), "=r"((r)[11]), \
          "=r"((r)[12]), "=r"((r)[13]), "=r"((r)[14]), "=r"((r)[15]), \
          "=r"((r)[16]), "=r"((r)[17]), "=r"((r)[18]), "=r"((r)[19]), \
          "=r"((r)[20]), "=r"((r)[21]), "=r"((r)[22]), "=r"((r)[23]), \
          "=r"((r)[24]), "=r"((r)[25]), "=r"((r)[26]), "=r"((r)[27]), \
          "=r"((r)[28]), "=r"((r)[29]), "=r"((r)[30]), "=r"((r)[31]) \
        : "r"(tmem_addr))

static constexpr uint64_t SMEM_DESC_BASE_SW128 =
    (uint64_t(2)  << 61) | (uint64_t(1) << 46) | (uint64_t(64) << 32) | (uint64_t(1) << 16);
#define MAKE_SMEM_DESC(base_addr) (SMEM_DESC_BASE_SW128 | ((uint64_t)((base_addr) >> 4) & 0x3FFF))

__device__ __forceinline__ void mma_f16_ss(uint32_t d, uint64_t ad, uint64_t bd,
                                           uint32_t idesc, bool en) {
    uint32_t e = en ? 1u : 0u;
    asm volatile(
        "{\n\t.reg .pred p;\n\tsetp.ne.u32 p, %5, 0;\n\t"
        "tcgen05.mma.cta_group::1.kind::f16 [%0], %1, %2, %3, {%4, %4, %4, %4}, p;\n\t}"
        :: "r"(d), "l"(ad), "l"(bd), "r"(idesc), "r"(0u), "r"(e) : "memory");
}
__device__ __forceinline__ void bulk_g2s(uint32_t dst, const void* src, uint32_t bytes, uint32_t mbar) {
    asm volatile("cp.async.bulk.shared::cluster.global.mbarrier::complete_tx::bytes [%0], [%1], %2, [%3];"
        :: "r"(dst), "l"(src), "r"(bytes), "r"(mbar) : "memory");
}
#endif  // HAS_TCGEN05

// ============================ Pack kernels ============================
// z=0: query -> hi + lo.  z=1: ref -> hi only (lo never consumed).
__global__ void split_act2_kernel(const float* __restrict__ src0,
                                  __half* __restrict__ hi0, __half* __restrict__ lo0,
                                  const float* __restrict__ src1,
                                  __half* __restrict__ hi1, int M)
{
    const bool isRef = (blockIdx.z != 0);
    const float* src = isRef ? src1 : src0;
    __half* hi = isRef ? hi1 : hi0;
    __half* lo = isRef ? nullptr : lo0;
    const int c  = blockIdx.x;
    const int mb = blockIdx.y;
    const int t  = threadIdx.x;
    const int j  = t & 7;
    char* hbase = (char*)hi + ((size_t)(mb * NCH + c)) * TILE_BYTES;
    char* lbase = lo ? (char*)lo + ((size_t)(mb * NCH + c)) * TILE_BYTES : nullptr;

    #pragma unroll
    for (int g = 0; g < 8; g++) {
        int ml = g * 16 + (t >> 3);
        int m = mb * 128 + ml;
        float x[8];
        if (m < M) {
            float4 a = *(const float4*)(src + (size_t)m * CC + c * 64 + j * 8);
            float4 b = *(const float4*)(src + (size_t)m * CC + c * 64 + j * 8 + 4);
            x[0]=a.x; x[1]=a.y; x[2]=a.z; x[3]=a.w; x[4]=b.x; x[5]=b.y; x[6]=b.z; x[7]=b.w;
        } else {
            #pragma unroll
            for (int i = 0; i < 8; i++) x[i] = 0.0f;
        }
        __half h[8], l[8];
        #pragma unroll
        for (int i = 0; i < 8; i++) {
            h[i] = __float2half(x[i]);
            l[i] = __float2half((x[i] - __half2float(h[i])) * LO_SCALE);
        }
        uint32_t off = SMEM_SWIZZLE_128B((uint32_t)(ml * 128 + j * 16));
        *(uint4*)(hbase + off) = *(uint4*)h;
        if (lbase) *(uint4*)(lbase + off) = *(uint4*)l;
    }
}

__global__ void __launch_bounds__(512)
pack_weights_all(const float* __restrict__ Wq, const float* __restrict__ Wkv,
                 const float* __restrict__ Woff, const float* __restrict__ Wout,
                 __half* __restrict__ wq, __half* __restrict__ wk,
                 __half* __restrict__ wfh, __half* __restrict__ wfl,
                 __half* __restrict__ wo)
{
    __shared__ float ts[64][129];
    const int c = blockIdx.x;
    const int y = blockIdx.y;
    const int t = threadIdx.x;

    const float* W; int ldw, nb; __half *hi, *lo;
    if (y < 8)       { W = Wq;   ldw = CC;     nb = y;      hi = wq;  lo = nullptr; }
    else if (y < 16) { W = Wkv;  ldw = 2 * CC; nb = y - 8;  hi = wk;  lo = nullptr; }
    else if (y < 17) { W = Woff; ldw = 128;    nb = 0;      hi = wfh; lo = wfl; }
    else             { W = Wout; ldw = CC;     nb = y - 17; hi = wo;  lo = nullptr; }

    const int k0 = c * 64;
    const int n0 = nb * 128;
    const int lrow = t >> 7;
    const int lcol = t & 127;
    #pragma unroll
    for (int i = 0; i < 16; i++) {
        int row = i * 4 + lrow;
        ts[row][lcol] = W[(size_t)(k0 + row) * ldw + n0 + lcol];
    }
    __syncthreads();

    char* hbase = (char*)hi + ((size_t)(nb * NCH + c)) * TILE_BYTES;
    char* lbase = lo ? (char*)lo + ((size_t)(nb * NCH + c)) * TILE_BYTES : nullptr;
    #pragma unroll
    for (int it = 0; it < 2; it++) {
        int idx = t + it * 512;
        int nl = idx >> 3;
        int j  = idx & 7;
        __half h[8], l[8];
        #pragma unroll
        for (int jj = 0; jj < 8; jj++) {
            float x = ts[j * 8 + jj][nl];
            h[jj] = __float2half(x);
            l[jj] = __float2half((x - __half2float(h[jj])) * LO_SCALE);
        }
        uint32_t off = SMEM_SWIZZLE_128B((uint32_t)(nl * 128 + j * 16));
        *(uint4*)(hbase + off) = *(uint4*)h;
        if (lbase) *(uint4*)(lbase + off) = *(uint4*)l;
    }
}

// ===== FUSED q+k+off GEMM: 1D grid of 774 CTAs. =====
//   seg0 q:   A hi only, B single (3 tiles, 4 MMAs) -> fp16 out
//   seg1 k:   A hi only, B single (3 tiles, 4 MMAs) -> fp16 out
//   seg2 off: A hi/lo, B hi/lo   (4 tiles, 12 MMAs) -> fp32 out
__global__ void __launch_bounds__(128, 1)
gemm_fused(const char* __restrict__ QAh, const char* __restrict__ QAl,
           const char* __restrict__ RAh,
           const char* __restrict__ WqB, const char* __restrict__ WkB,
           const char* __restrict__ WfH, const char* __restrict__ WfL,
           const float* __restrict__ bq, const float* __restrict__ bkv,
           const float* __restrict__ boff,
           __half* __restrict__ outQ, __half* __restrict__ outK,
           float* __restrict__ outOff)
{
#if HAS_TCGEN05
    constexpr uint32_t SB = 4 * TILE_BYTES;
    constexpr uint32_t HDR = 1024;

    extern __shared__ char smem[];
    uint32_t sb = smem_to_u32(smem);
    const int tid = threadIdx.x;
    const int wid = tid >> 5;
    const int lane = tid & 31;
    const int bid = blockIdx.x;

    const int seg = (bid < 344) ? 0 : (bid < 688 ? 1 : 2);
    const bool isOff = (seg == 2);
    const int nt = isOff ? 128 : 256;
    const int my = isOff ? (bid - 688) : ((seg ? bid - 344 : bid) >> 2);
    const int ntile = isOff ? 0 : ((seg ? bid - 344 : bid) & 3);
    const int m0 = my * 128;
    const int n0 = ntile * 256;
    const uint32_t idesc = 0x8000010u | ((uint32_t)(nt / 8) << 17);
    const uint32_t txb = (isOff ? 4u : 3u) * TILE_BYTES;

    const char* Ah = (seg == 1) ? RAh : QAh;
    const float* bias = (seg == 0) ? bq : (seg == 1 ? bkv : boff);

    if (wid == 0) TCGEN05_ALLOC(sb + 0, 512);
    if (tid == 0) {
        MBARRIER_INIT(sb + 16, 1);
        MBARRIER_INIT(sb + 24, 1);
        MBARRIER_INIT(sb + 32, 1);
        MBARRIER_INIT(sb + 48, 1);
        MBARRIER_INIT(sb + 56, 1);
        MBARRIER_INIT(sb + 64, 1);
    }
    __syncthreads();
    uint32_t tmem;
    asm volatile("ld.shared.b32 %0, [%1];" : "=r"(tmem) : "r"(sb));

    if (tid == 0) {
        for (int c = 0; c < NCH; c++) {
            int s = c % 3;
            MBARRIER_WAIT_PARITY(sb + 16 + 8u * s, (uint32_t)((c / 3) & 1));
            uint32_t st = sb + HDR + (uint32_t)s * SB;
            uint64_t ahd = MAKE_SMEM_DESC(st);
            uint64_t bhd = MAKE_SMEM_DESC(st + 2 * TILE_BYTES);
            #pragma unroll
            for (int ks = 0; ks < 4; ks++)
                mma_f16_ss(tmem, ahd + ks * 2, bhd + ks * 2, idesc, !(c == 0 && ks == 0));
            if (isOff) {
                uint64_t ald = MAKE_SMEM_DESC(st + TILE_BYTES);
                #pragma unroll
                for (int ks = 0; ks < 4; ks++)
                    mma_f16_ss(tmem + nt, ald + ks * 2, bhd + ks * 2, idesc, !(c == 0 && ks == 0));
                uint64_t bld = MAKE_SMEM_DESC(st + 3 * TILE_BYTES);
                #pragma unroll
                for (int ks = 0; ks < 4; ks++)
                    mma_f16_ss(tmem + nt, ahd + ks * 2, bld + ks * 2, idesc, true);
            }
            TCGEN05_COMMIT(sb + 48 + 8u * s);
        }
        for (int c = NCH - 3; c < NCH; c++)
            MBARRIER_WAIT_PARITY(sb + 48 + 8u * (c % 3), (uint32_t)((c / 3) & 1));
    } else if (tid == 32) {
        auto issue = [&](int c) {
            int s = c % 3;
            uint32_t fb = sb + 16 + 8u * s;
            uint32_t st = sb + HDR + (uint32_t)s * SB;
            MBARRIER_EXPECT_TX(fb, txb);
            size_t aoff = ((size_t)my * NCH + c) * TILE_BYTES;
            bulk_g2s(st, Ah + aoff, TILE_BYTES, fb);
            if (isOff) {
                bulk_g2s(st + TILE_BYTES, QAl + aoff, TILE_BYTES, fb);
                size_t boff2 = (size_t)c * TILE_BYTES;
                bulk_g2s(st + 2 * TILE_BYTES, WfH + boff2, TILE_BYTES, fb);
                bulk_g2s(st + 3 * TILE_BYTES, WfL + boff2, TILE_BYTES, fb);
            } else {
                const char* B = (seg == 1) ? WkB : WqB;
                #pragma unroll
                for (int i = 0; i < 2; i++)
                    bulk_g2s(st + (2 + i) * TILE_BYTES,
                             B + ((size_t)(ntile * 2 + i) * NCH + c) * TILE_BYTES,
                             TILE_BYTES, fb);
            }
        };
        issue(0); issue(1); issue(2);
        for (int c = 3; c < NCH; c++) {
            int s = c % 3;
            MBARRIER_WAIT_PARITY(sb + 48 + 8u * s, (uint32_t)((c / 3 - 1) & 1));
            issue(c);
        }
    }
    __syncthreads();
    TCGEN05_FENCE_AFTER();

    float* buf = (float*)(smem + HDR) + wid * (32 * 33);
    for (int base = 0; base < nt; base += 32) {
        uint32_t r0[32], r1[32];
        TCGEN05_LD_32X32B_X32(r0, tmem + base);
        if (isOff) { TCGEN05_LD_32X32B_X32(r1, tmem + nt + base); }
        TCGEN05_WAIT_LD();
        if (isOff) {
            #pragma unroll
            for (int q = 0; q < 32; q++)
                buf[lane * 33 + q] = __uint_as_float(r0[q]) + __uint_as_float(r1[q]) * LO_INV;
        } else {
            #pragma unroll
            for (int q = 0; q < 32; q++)
                buf[lane * 33 + q] = __uint_as_float(r0[q]);
        }
        __syncwarp();
        float bv = bias[n0 + base + lane];
        if (seg == 2) {
            #pragma unroll 4
            for (int rr = 0; rr < 32; rr++) {
                int gm = m0 + wid * 32 + rr;
                if (gm < BN) outOff[(size_t)gm * 128 + base + lane] = buf[rr * 33 + lane] + bv;
            }
        } else {
            __half* dst = (seg == 0) ? outQ : outK;
            #pragma unroll 4
            for (int rr = 0; rr < 32; rr++) {
                int gm = m0 + wid * 32 + rr;
                if (gm < BN) dst[(size_t)gm * CC + n0 + base + lane] = __float2half(buf[rr * 33 + lane] + bv);
            }
        }
        __syncwarp();
    }
    TCGEN05_FENCE_BEFORE();
    __syncthreads();
    if (wid == 0) {
        TCGEN05_RELINQUISH_ALLOC_PERMIT();
        TCGEN05_DEALLOC(tmem, 512);
    }
#endif
}

// ===== out-GEMM: NT=256, A single (attention output fp16), B single =====
__global__ void __launch_bounds__(128, 1)
gemm_out(const char* __restrict__ Ah, const char* __restrict__ B,
         const float* __restrict__ bias, float* __restrict__ C)
{
#if HAS_TCGEN05
    constexpr int NT = 256;
    constexpr uint32_t SB = 3 * TILE_BYTES;
    constexpr uint32_t HDR = 1024;
    constexpr uint32_t IDESC = 0x8000010u | ((NT / 8) << 17);

    extern __shared__ char smem[];
    uint32_t sb = smem_to_u32(smem);
    const int tid = threadIdx.x;
    const int wid = tid >> 5;
    const int lane = tid & 31;
    const int m0 = blockIdx.y * 128;
    const int n0 = blockIdx.x * NT;

    if (wid == 0) TCGEN05_ALLOC(sb + 0, 512);
    if (tid == 0) {
        MBARRIER_INIT(sb + 16, 1);
        MBARRIER_INIT(sb + 24, 1);
        MBARRIER_INIT(sb + 32, 1);
        MBARRIER_INIT(sb + 48, 1);
        MBARRIER_INIT(sb + 56, 1);
        MBARRIER_INIT(sb + 64, 1);
    }
    __syncthreads();
    uint32_t tmem;
    asm volatile("ld.shared.b32 %0, [%1];" : "=r"(tmem) : "r"(sb));

    if (tid == 0) {
        for (int c = 0; c < NCH; c++) {
            int s = c % 3;
            MBARRIER_WAIT_PARITY(sb + 16 + 8u * s, (uint32_t)((c / 3) & 1));
            uint32_t st = sb + HDR + (uint32_t)s * SB;
            uint64_t ahd = MAKE_SMEM_DESC(st);
            uint64_t bhd = MAKE_SMEM_DESC(st + TILE_BYTES);
            #pragma unroll
            for (int ks = 0; ks < 4; ks++)
                mma_f16_ss(tmem, ahd + ks * 2, bhd + ks * 2, IDESC, !(c == 0 && ks == 0));
            TCGEN05_COMMIT(sb + 48 + 8u * s);
        }
        for (int c = NCH - 3; c < NCH; c++)
            MBARRIER_WAIT_PARITY(sb + 48 + 8u * (c % 3), (uint32_t)((c / 3) & 1));
    } else if (tid == 32) {
        auto issue = [&](int c) {
            int s = c % 3;
            uint32_t fb = sb + 16 + 8u * s;
            uint32_t st = sb + HDR + (uint32_t)s * SB;
            MBARRIER_EXPECT_TX(fb, SB);
            size_t aoff = ((size_t)blockIdx.y * NCH + c) * TILE_BYTES;
            bulk_g2s(st, Ah + aoff, TILE_BYTES, fb);
            #pragma unroll
            for (int i = 0; i < 2; i++)
                bulk_g2s(st + (1 + i) * TILE_BYTES,
                         B + ((size_t)(blockIdx.x * 2 + i) * NCH + c) * TILE_BYTES,
                         TILE_BYTES, fb);
        };
        issue(0); issue(1); issue(2);
        for (int c = 3; c < NCH; c++) {
            int s = c % 3;
            MBARRIER_WAIT_PARITY(sb + 48 + 8u * s, (uint32_t)((c / 3 - 1) & 1));
            issue(c);
        }
    }
    __syncthreads();
    TCGEN05_FENCE_AFTER();

    float* buf = (float*)(smem + HDR) + wid * (32 * 33);
    #pragma unroll
    for (int base = 0; base < NT; base += 32) {
        uint32_t r0[32];
        TCGEN05_LD_32X32B_X32(r0, tmem + base);
        TCGEN05_WAIT_LD();
        #pragma unroll
        for (int q = 0; q < 32; q++)
            buf[lane * 33 + q] = __uint_as_float(r0[q]);
        __syncwarp();
        float bv = bias[n0 + base + lane];
        #pragma unroll 4
        for (int rr = 0; rr < 32; rr++) {
            int gm = m0 + wid * 32 + rr;
            if (gm < BN)
                C[(size_t)gm * CC + n0 + base + lane] = buf[rr * 33 + lane] + bv;
        }
        __syncwarp();
    }
    TCGEN05_FENCE_BEFORE();
    __syncthreads();
    if (wid == 0) {
        TCGEN05_RELINQUISH_ALLOC_PERMIT();
        TCGEN05_DEALLOC(tmem, 512);
    }
#endif
}

// ============================ Fallback SGEMM ============================
__global__ void sgemm_bias_kernel(const float* __restrict__ A,
                                  const float* __restrict__ Wt,
                                  const float* __restrict__ bias,
                                  float* __restrict__ C,
                                  int M, int Ncols, int K, int ldw)
{
    __shared__ float As[16][64];
    __shared__ float Bs[16][64];
    const int tid = threadIdx.x;
    const int tx = tid & 15;
    const int ty = tid >> 4;
    const int n0 = blockIdx.x * 64;
    const int m0 = blockIdx.y * 64;
    float acc[4][4] = {};
    for (int k0 = 0; k0 < K; k0 += 16) {
        #pragma unroll
        for (int i = 0; i < 4; i++) {
            int idx = tid + i * 256;
            int m  = idx >> 4, kk = idx & 15, gm = m0 + m;
            As[kk][m] = (gm < M) ? A[(size_t)gm * K + (k0 + kk)] : 0.0f;
        }
        #pragma unroll
        for (int i = 0; i < 4; i++) {
            int idx = tid + i * 256;
            int kk = idx >> 6, n = idx & 63, gn = n0 + n;
            Bs[kk][n] = (gn < Ncols) ? Wt[(size_t)(k0 + kk) * ldw + gn] : 0.0f;
        }
        __syncthreads();
        #pragma unroll
        for (int kk = 0; kk < 16; kk++) {
            float4 a = *(const float4*)&As[kk][ty * 4];
            float4 w = *(const float4*)&Bs[kk][tx * 4];
            acc[0][0] += a.x*w.x; acc[0][1] += a.x*w.y; acc[0][2] += a.x*w.z; acc[0][3] += a.x*w.w;
            acc[1][0] += a.y*w.x; acc[1][1] += a.y*w.y; acc[1][2] += a.y*w.z; acc[1][3] += a.y*w.w;
            acc[2][0] += a.z*w.x; acc[2][1] += a.z*w.y; acc[2][2] += a.z*w.z; acc[2][3] += a.z*w.w;
            acc[3][0] += a.w*w.x; acc[3][1] += a.w*w.y; acc[3][2] += a.w*w.z; acc[3][3] += a.w*w.w;
        }
        __syncthreads();
    }
    #pragma unroll
    for (int r = 0; r < 4; r++) {
        int gm = m0 + ty * 4 + r;
        if (gm >= M) continue;
        #pragma unroll
        for (int c = 0; c < 4; c++) {
            int gn = n0 + tx * 4 + c;
            if (gn < Ncols) C[(size_t)gm * Ncols + gn] = acc[r][c] + bias[gn];
        }
    }
}

// ======= Attention: fp16 q + fp16 k gathers, hoisted coords, hi-only out =======
__global__ void attn_warp_kernel()
{
    const int bn = blockIdx.x;
    const int h  = threadIdx.x >> 5;
    const int lane = threadIdx.x & 31;

    const int b = bn / NPIX;
    const int n = bn % NPIX;
    const int row = n / WSP;
    const int col = n % WSP;
    const float step = 2.0f / 36.0f;
    const float ybase = -1.0f + row * step;
    const float xbase = -1.0f + col * step;

    uint2 qu = *(const uint2*)(g_qhf + (size_t)bn * CC + h * HD + lane * 4);
    float2 qa = __half22float2(*(__half2*)&qu.x);
    float2 qb = __half22float2(*(__half2*)&qu.y);
    float4 q4 = make_float4(qa.x, qa.y, qb.x, qb.y);
    const __half* kbase = g_kh + (size_t)b * NPIX * CC + h * HD + lane * 4;

    float offv = 0.0f;
    if (lane < 16) offv = g_off[(size_t)bn * (HEADS * PTS * 2) + h * (PTS * 2) + lane];

    const int pp2 = (lane & 7) * 2;
    float o0 = __shfl_sync(0xffffffffu, offv, pp2);
    float o1 = __shfl_sync(0xffffffffu, offv, pp2 + 1);
    float xn = ybase + o0;
    float yn = xbase + o1;
    float ix = fminf(fmaxf((xn + 1.0f) * 0.5f * (WSP - 1), 0.0f), (float)(WSP - 1));
    float iy = fminf(fmaxf((yn + 1.0f) * 0.5f * (HSP - 1), 0.0f), (float)(HSP - 1));
    float x0f = floorf(ix), y0f = floorf(iy);
    float wxl = ix - x0f, wyl = iy - y0f;
    int x0 = (int)x0f, y0 = (int)y0f;
    int x1 = min(x0 + 1, WSP - 1);
    int y1 = min(y0 + 1, HSP - 1);
    int c00l = (y0 * WSP + x0) * CC;
    int c01l = (y0 * WSP + x1) * CC;
    int c10l = (y1 * WSP + x0) * CC;
    int c11l = (y1 * WSP + x1) * CC;

    float4 sv[PTS];
    float sc[PTS];
    #pragma unroll
    for (int p = 0; p < PTS; p++) {
        int i00 = __shfl_sync(0xffffffffu, c00l, p);
        int i01 = __shfl_sync(0xffffffffu, c01l, p);
        int i10 = __shfl_sync(0xffffffffu, c10l, p);
        int i11 = __shfl_sync(0xffffffffu, c11l, p);
        float wx = __shfl_sync(0xffffffffu, wxl, p);
        float wy = __shfl_sync(0xffffffffu, wyl, p);

        uint2 u00 = *(const uint2*)(kbase + i00);
        uint2 u01 = *(const uint2*)(kbase + i01);
        uint2 u10 = *(const uint2*)(kbase + i10);
        uint2 u11 = *(const uint2*)(kbase + i11);
        float2 a00 = __half22float2(*(__half2*)&u00.x), b00 = __half22float2(*(__half2*)&u00.y);
        float2 a01 = __half22float2(*(__half2*)&u01.x), b01 = __half22float2(*(__half2*)&u01.y);
        float2 a10 = __half22float2(*(__half2*)&u10.x), b10 = __half22float2(*(__half2*)&u10.y);
        float2 a11 = __half22float2(*(__half2*)&u11.x), b11 = __half22float2(*(__half2*)&u11.y);

        float w00 = (1.0f - wy) * (1.0f - wx), w01 = (1.0f - wy) * wx;
        float w10 = wy * (1.0f - wx), w11 = wy * wx;
        float4 s;
        s.x = w00*a00.x + w01*a01.x + w10*a10.x + w11*a11.x;
        s.y = w00*a00.y + w01*a01.y + w10*a10.y + w11*a11.y;
        s.z = w00*b00.x + w01*b01.x + w10*b10.x + w11*b11.x;
        s.w = w00*b00.y + w01*b01.y + w10*b10.y + w11*b11.y;
        sv[p] = s;

        float d = q4.x*s.x + q4.y*s.y + q4.z*s.z + q4.w*s.w;
        #pragma unroll
        for (int o = 16; o; o >>= 1) d += __shfl_xor_sync(0xffffffffu, d, o);
        sc[p] = d * 0.088388347648318447f;
    }

    float m = sc[0];
    #pragma unroll
    for (int p = 1; p < PTS; p++) m = fmaxf(m, sc[p]);
    float e[PTS], denom = 0.0f;
    #pragma unroll
    for (int p = 0; p < PTS; p++) { e[p] = expf(sc[p] - m); denom += e[p]; }
    float inv = 1.0f / denom;

    float4 o = make_float4(0, 0, 0, 0);
    #pragma unroll
    for (int p = 0; p < PTS; p++) {
        float w = e[p] * inv;
        o.x += w * sv[p].x; o.y += w * sv[p].y; o.z += w * sv[p].z; o.w += w * sv[p].w;
    }

    int k = h * HD + lane * 4;
    int mb = bn >> 7, ml = bn & 127;
    int c = k >> 6, kl = k & 63;
    size_t tbase = ((size_t)(mb * NCH + c)) * TILE_BYTES;
    uint32_t off = SMEM_SWIZZLE_128B((uint32_t)(ml * 128 + kl * 2));

    __half h4[4];
    h4[0] = __float2half(o.x); h4[1] = __float2half(o.y);
    h4[2] = __float2half(o.z); h4[3] = __float2half(o.w);
    *(uint2*)((char*)g_ah + tbase + off) = *(uint2*)h4;
}

// Fallback attention (fp32 k, fp32 output to g_attn)
__global__ void attn_kernel(float* __restrict__ out)
{
    const int bn = blockIdx.x;
    const int h  = blockIdx.y;
    const int t  = threadIdx.x;
    const int lane = t & 31;
    const int wid  = t >> 5;
    const int b = bn / NPIX;
    const int n = bn % NPIX;
    const int row = n / WSP;
    const int col = n % WSP;
    const float step = 2.0f / 36.0f;
    const float ybase = -1.0f + row * step;
    const float xbase = -1.0f + col * step;
    const float qv = g_q[(size_t)bn * CC + h * HD + t];
    const float* kbase = g_k + (size_t)b * NPIX * CC + h * HD + t;
    const float* offp  = g_off + (size_t)bn * (HEADS * PTS * 2) + h * (PTS * 2);
    float sv[PTS];
    __shared__ float red[PTS][4];
    __shared__ float sc[PTS];
    #pragma unroll
    for (int p = 0; p < PTS; p++) {
        float o0 = offp[p * 2 + 0], o1 = offp[p * 2 + 1];
        float xn = ybase + o0, yn = xbase + o1;
        float ix = fminf(fmaxf((xn + 1.0f) * 0.5f * (WSP - 1), 0.0f), (float)(WSP - 1));
        float iy = fminf(fmaxf((yn + 1.0f) * 0.5f * (HSP - 1), 0.0f), (float)(HSP - 1));
        float x0f = floorf(ix), y0f = floorf(iy);
        float wx = ix - x0f, wy = iy - y0f;
        int x0 = (int)x0f, y0 = (int)y0f;
        int x1 = min(x0 + 1, WSP - 1), y1 = min(y0 + 1, HSP - 1);
        float v00 = kbase[(size_t)(y0 * WSP + x0) * CC];
        float v01 = kbase[(size_t)(y0 * WSP + x1) * CC];
        float v10 = kbase[(size_t)(y1 * WSP + x0) * CC];
        float v11 = kbase[(size_t)(y1 * WSP + x1) * CC];
        float s = (1.0f - wy) * ((1.0f - wx) * v00 + wx * v01)
                +          wy * ((1.0f - wx) * v10 + wx * v11);
        sv[p] = s;
        float d = qv * s;
        #pragma unroll
        for (int o = 16; o; o >>= 1) d += __shfl_down_sync(0xffffffffu, d, o);
        if (lane == 0) red[p][wid] = d;
    }
    __syncthreads();
    if (t < PTS) sc[t] = (red[t][0] + red[t][1] + red[t][2] + red[t][3]) * 0.088388347648318447f;
    __syncthreads();
    float m = sc[0];
    #pragma unroll
    for (int p = 1; p < PTS; p++) m = fmaxf(m, sc[p]);
    float e[PTS], denom = 0.0f;
    #pragma unroll
    for (int p = 0; p < PTS; p++) { e[p] = expf(sc[p] - m); denom += e[p]; }
    float inv = 1.0f / denom;
    float o = 0.0f;
    #pragma unroll
    for (int p = 0; p < PTS; p++) o += e[p] * inv * sv[p];
    out[(size_t)bn * CC + h * HD + t] = o;
}

// ============================ Launch ============================
extern "C" void kernel_launch(void* const* d_in, const int* in_sizes, int n_in,
                              void* d_out, int out_size)
{
    const float* query = (const float*)d_in[0];
    const float* ref   = (const float*)d_in[1];
    const float* Wq    = (const float*)d_in[2];
    const float* bq    = (const float*)d_in[3];
    const float* Wkv   = (const float*)d_in[4];
    const float* bkv   = (const float*)d_in[5];
    const float* Woff  = (const float*)d_in[6];
    const float* boff  = (const float*)d_in[7];
    const float* Wout  = (const float*)d_in[8];
    const float* bout  = (const float*)d_in[9];
    float* out = (float*)d_out;

    float *q_ptr, *k_ptr, *off_ptr, *attn_ptr;
    __half *kh_ptr, *qhf_ptr;
    cudaGetSymbolAddress((void**)&q_ptr,    g_q);
    cudaGetSymbolAddress((void**)&k_ptr,    g_k);
    cudaGetSymbolAddress((void**)&qhf_ptr,  g_qhf);
    cudaGetSymbolAddress((void**)&kh_ptr,   g_kh);
    cudaGetSymbolAddress((void**)&off_ptr,  g_off);
    cudaGetSymbolAddress((void**)&attn_ptr, g_attn);

    cudaFuncAttributes fa;
    cudaFuncGetAttributes(&fa, gemm_fused);
    bool use_tc = (fa.numRegs > 32);

    if (use_tc) {
        char *qh, *ql, *rh, *ah;
        char *wq, *wk, *wo, *wfh, *wfl;
        cudaGetSymbolAddress((void**)&qh, g_qh);   cudaGetSymbolAddress((void**)&ql, g_ql);
        cudaGetSymbolAddress((void**)&rh, g_rh);
        cudaGetSymbolAddress((void**)&ah, g_ah);
        cudaGetSymbolAddress((void**)&wq, g_Wq);
        cudaGetSymbolAddress((void**)&wk, g_Wk);
        cudaGetSymbolAddress((void**)&wo, g_Wo);
        cudaGetSymbolAddress((void**)&wfh, g_Wf_h); cudaGetSymbolAddress((void**)&wfl, g_Wf_l);

        static bool attr_set = false;
        if (!attr_set) {
            cudaFuncSetAttribute(gemm_fused, cudaFuncAttributeMaxDynamicSharedMemorySize, 197632);
            cudaFuncSetAttribute(gemm_out,   cudaFuncAttributeMaxDynamicSharedMemorySize, 197632);
            attr_set = true;
        }

        split_act2_kernel<<<dim3(NCH, MBLK, 2), 128>>>(
            query, (__half*)qh, (__half*)ql,
            ref,   (__half*)rh, BN);
        pack_weights_all<<<dim3(NCH, 25), 512>>>(
            Wq, Wkv, Woff, Wout,
            (__half*)wq, (__half*)wk, (__half*)wfh, (__half*)wfl, (__half*)wo);

        gemm_fused<<<774, 128, 197632>>>(
            qh, ql, rh, wq, wk, wfh, wfl, bq, bkv, boff,
            qhf_ptr, kh_ptr, off_ptr);

        attn_warp_kernel<<<BN, 256>>>();

        gemm_out<<<dim3(4, MBLK), 128, 197632>>>(ah, wo, bout, out);
    } else {
        dim3 blk(256);
        dim3 gBig((CC + 63) / 64, (BN + 63) / 64);
        dim3 gOff((128 + 63) / 64, (BN + 63) / 64);
        sgemm_bias_kernel<<<gBig, blk>>>(query, Wq, bq, q_ptr, BN, CC, CC, CC);
        sgemm_bias_kernel<<<gBig, blk>>>(ref, Wkv, bkv, k_ptr, BN, CC, CC, 2 * CC);
        sgemm_bias_kernel<<<gOff, blk>>>(query, Woff, boff, off_ptr, BN, HEADS * PTS * 2, CC, HEADS * PTS * 2);
        attn_kernel<<<dim3(BN, HEADS), 128>>>(attn_ptr);
        sgemm_bias_kernel<<<gBig, blk>>>(attn_ptr, Wout, bout, out, BN, CC, CC, CC);
    }
}